// round 1
// baseline (speedup 1.0000x reference)
#include <cuda_runtime.h>
#include <math.h>

#define NB 2
#define NE 512
#define NH 8
#define ND 64
#define NT 2048
#define EPSV 1e-5f
#define INV_SCALE (1.0f/181.0f)

// ---------------- scratch (device globals: allocation-free) ----------------
__device__ float g_Wn[4*NE*NE];     // standardized weights
__device__ float g_q[NB*NE*NT];
__device__ float g_k[NB*NE*NT];
__device__ float g_v[NB*NE*NT];
__device__ float g_att[NB*NE*NT];

// ---------------- 1) weight standardization ----------------
// grid (512 rows, 4 matrices), 128 threads. Row of 512: mean/var (ddof=0) + eps.
__global__ void std_weights_kernel(const float* __restrict__ W0, const float* __restrict__ W1,
                                   const float* __restrict__ W2, const float* __restrict__ W3) {
    const float* Ws[4] = {W0, W1, W2, W3};
    const float* W = Ws[blockIdx.y];
    float* out = g_Wn + blockIdx.y * NE * NE;
    const int row = blockIdx.x;
    const int tid = threadIdx.x;

    float w[4];
    #pragma unroll
    for (int j = 0; j < 4; j++) w[j] = W[row*NE + tid + 128*j];

    __shared__ float red[4];
    float s = w[0]+w[1]+w[2]+w[3];
    #pragma unroll
    for (int o = 16; o > 0; o >>= 1) s += __shfl_down_sync(0xffffffffu, s, o);
    if ((tid & 31) == 0) red[tid >> 5] = s;
    __syncthreads();
    const float mu = (red[0]+red[1]+red[2]+red[3]) * (1.0f/NE);
    __syncthreads();

    float s2 = 0.f;
    #pragma unroll
    for (int j = 0; j < 4; j++) { float d = w[j]-mu; s2 += d*d; }
    #pragma unroll
    for (int o = 16; o > 0; o >>= 1) s2 += __shfl_down_sync(0xffffffffu, s2, o);
    if ((tid & 31) == 0) red[tid >> 5] = s2;
    __syncthreads();
    const float var = (red[0]+red[1]+red[2]+red[3]) * (1.0f/NE);
    const float rstd = rsqrtf(var + EPSV);
    #pragma unroll
    for (int j = 0; j < 4; j++) out[row*NE + tid + 128*j] = (w[j]-mu)*rstd;
}

// ---------------- 2/4) projection GEMM (+bias, optional per-head LN) ----------------
struct ProjSet {
    const float* x; const int* mask; const float* wn; const float* bias;
    const float* lng; const float* lnb; float* out;
};
struct ProjArgs { ProjSet s[3]; };

// grid (T/128, H, nsets*B). Block 256 = 16x16, each thread 4 rows x 8 cols.
// Tile: BM=64 (one head), BN=128, BK=32.
template<bool DO_LN>
__global__ void __launch_bounds__(256) proj_kernel(ProjArgs A) {
    const int which = blockIdx.z >> 1;
    const int b = blockIdx.z & 1;
    const float* __restrict__ Xp = A.s[which].x;
    const int*   __restrict__ Mp = A.s[which].mask;
    const float* __restrict__ Wp = A.s[which].wn;
    const float* __restrict__ Bp = A.s[which].bias;
    const float* __restrict__ Gp = A.s[which].lng;
    const float* __restrict__ Lp = A.s[which].lnb;
    float*       __restrict__ Op = A.s[which].out;

    const int h  = blockIdx.y;
    const int t0 = blockIdx.x * 128;
    const int tid = threadIdx.x;
    const int tx = tid & 15, ty = tid >> 4;

    __shared__ float smem[8192];      // GEMM tiles, then reused as 64x128 LN tile
    __shared__ float km_s[128];
    __shared__ float lng_s[ND];
    __shared__ float lnb_s[ND];
    float* wt = smem;                 // [64][33]
    float* xt = smem + 64*33;         // [32][128]

    if (tid < 128) km_s[tid] = (float)Mp[b*NT + t0 + tid];
    if (DO_LN && tid >= 128 && tid < 192) {
        lng_s[tid-128] = Gp[tid-128];
        lnb_s[tid-128] = Lp[tid-128];
    }
    __syncthreads();

    float acc[4][8];
    #pragma unroll
    for (int i = 0; i < 4; i++)
        #pragma unroll
        for (int j = 0; j < 8; j++) acc[i][j] = 0.f;

    const float* Wr = Wp + (h*ND)*NE;
    const float* Xb = Xp + b*NE*NT;

    for (int k0 = 0; k0 < NE; k0 += 32) {
        #pragma unroll
        for (int l = 0; l < 8; l++) {
            int e = tid + 256*l; int r = e >> 5, c = e & 31;
            wt[r*33 + c] = Wr[r*NE + k0 + c];
        }
        #pragma unroll
        for (int l = 0; l < 16; l++) {
            int e = tid + 256*l; int r = e >> 7, c = e & 127;
            xt[e] = Xb[(k0 + r)*NT + t0 + c] * km_s[c];
        }
        __syncthreads();
        #pragma unroll 8
        for (int kk = 0; kk < 32; kk++) {
            float a[4], xx[8];
            #pragma unroll
            for (int i = 0; i < 4; i++) a[i] = wt[(ty*4+i)*33 + kk];
            #pragma unroll
            for (int j = 0; j < 8; j++) xx[j] = xt[kk*128 + tx + 16*j];
            #pragma unroll
            for (int i = 0; i < 4; i++)
                #pragma unroll
                for (int j = 0; j < 8; j++) acc[i][j] += a[i]*xx[j];
        }
        __syncthreads();
    }

    float bv[4];
    #pragma unroll
    for (int i = 0; i < 4; i++) bv[i] = Bp[h*ND + ty*4 + i];

    if (!DO_LN) {
        #pragma unroll
        for (int i = 0; i < 4; i++)
            #pragma unroll
            for (int j = 0; j < 8; j++)
                Op[b*NE*NT + (h*ND + ty*4+i)*NT + t0 + tx + 16*j] = acc[i][j] + bv[i];
    } else {
        // stage tile in smem, LN per column over the 64 head rows
        #pragma unroll
        for (int i = 0; i < 4; i++)
            #pragma unroll
            for (int j = 0; j < 8; j++)
                smem[(ty*4+i)*128 + tx + 16*j] = acc[i][j] + bv[i];
        __syncthreads();
        if (tid < 128) {
            const int c = tid;
            float s = 0.f;
            #pragma unroll 16
            for (int d = 0; d < 64; d++) s += smem[d*128 + c];
            const float mu = s * (1.0f/64.0f);
            float s2 = 0.f;
            #pragma unroll 16
            for (int d = 0; d < 64; d++) { float dd = smem[d*128 + c] - mu; s2 += dd*dd; }
            const float rstd = rsqrtf(s2*(1.0f/64.0f) + EPSV);
            float* o = Op + b*NE*NT + (h*ND)*NT + t0 + c;
            #pragma unroll 8
            for (int d = 0; d < 64; d++)
                o[d*NT] = (smem[d*128 + c] - mu)*rstd*lng_s[d] + lnb_s[d];
        }
    }
}

// ---------------- 3) flash attention (fp32, online softmax) ----------------
// grid (T/64, H, B). Block 256 = 16x16. BQ=BK=64, DH=64.
// Thread owns tq rows ty*4+i (S/P/O rows) ; S cols tx+16*j ; O d-cols tx+16*kk.
__global__ void __launch_bounds__(256) attn_kernel(
        const float* __restrict__ q, const float* __restrict__ k, const float* __restrict__ v,
        const int* __restrict__ qmask, const int* __restrict__ kmask,
        float* __restrict__ out) {
    extern __shared__ float sm[];
    float* qs = sm;                        // [64][64]
    float* ks = sm + 4096;                 // [64][65]  (K tile, then V tile)
    float* ps = sm + 4096 + 4160;          // [64][65]
    float* km = sm + 4096 + 4160 + 4160;   // [64]

    const int t0 = blockIdx.x * 64;
    const int h = blockIdx.y, b = blockIdx.z;
    const int tid = threadIdx.x, tx = tid & 15, ty = tid >> 4;
    const int base = (b*NE + h*ND)*NT;

    #pragma unroll
    for (int l = 0; l < 16; l++) {
        int e = tid + 256*l;
        qs[e] = q[base + (e >> 6)*NT + t0 + (e & 63)];
    }

    float m_i[4], l_i[4], acc[4][4];
    #pragma unroll
    for (int i = 0; i < 4; i++) {
        m_i[i] = -1e30f; l_i[i] = 0.f;
        #pragma unroll
        for (int j = 0; j < 4; j++) acc[i][j] = 0.f;
    }

    for (int kt = 0; kt < NT/64; kt++) {
        const int tk0 = kt*64;
        __syncthreads();                       // protect ks/ps from previous iter
        #pragma unroll
        for (int l = 0; l < 16; l++) {
            int e = tid + 256*l;
            ks[(e >> 6)*65 + (e & 63)] = k[base + (e >> 6)*NT + tk0 + (e & 63)];
        }
        if (tid < 64) km[tid] = (float)kmask[b*NT + tk0 + tid];
        __syncthreads();

        // S = Q^T K  (64x64 tile)
        float s[4][4];
        #pragma unroll
        for (int i = 0; i < 4; i++)
            #pragma unroll
            for (int j = 0; j < 4; j++) s[i][j] = 0.f;
        #pragma unroll 16
        for (int d = 0; d < 64; d++) {
            float a[4], bb[4];
            #pragma unroll
            for (int i = 0; i < 4; i++) a[i] = qs[d*64 + ty*4 + i];
            #pragma unroll
            for (int j = 0; j < 4; j++) bb[j] = ks[d*65 + tx + 16*j];
            #pragma unroll
            for (int i = 0; i < 4; i++)
                #pragma unroll
                for (int j = 0; j < 4; j++) s[i][j] += a[i]*bb[j];
        }
        float kmr[4];
        #pragma unroll
        for (int j = 0; j < 4; j++) kmr[j] = km[tx + 16*j];
        #pragma unroll
        for (int i = 0; i < 4; i++)
            #pragma unroll
            for (int j = 0; j < 4; j++)
                s[i][j] = (kmr[j] != 0.f) ? s[i][j]*INV_SCALE : -1e9f;

        // online softmax over this key tile (row reductions across 16-lane groups)
        #pragma unroll
        for (int i = 0; i < 4; i++) {
            float mm = fmaxf(fmaxf(s[i][0], s[i][1]), fmaxf(s[i][2], s[i][3]));
            mm = fmaxf(mm, __shfl_xor_sync(0xffffffffu, mm, 1));
            mm = fmaxf(mm, __shfl_xor_sync(0xffffffffu, mm, 2));
            mm = fmaxf(mm, __shfl_xor_sync(0xffffffffu, mm, 4));
            mm = fmaxf(mm, __shfl_xor_sync(0xffffffffu, mm, 8));
            const float mn = fmaxf(m_i[i], mm);
            const float c = __expf(m_i[i] - mn);
            m_i[i] = mn;
            float p[4], rs = 0.f;
            #pragma unroll
            for (int j = 0; j < 4; j++) { p[j] = __expf(s[i][j] - mn); rs += p[j]; }
            rs += __shfl_xor_sync(0xffffffffu, rs, 1);
            rs += __shfl_xor_sync(0xffffffffu, rs, 2);
            rs += __shfl_xor_sync(0xffffffffu, rs, 4);
            rs += __shfl_xor_sync(0xffffffffu, rs, 8);
            l_i[i] = l_i[i]*c + rs;
            #pragma unroll
            for (int j = 0; j < 4; j++) acc[i][j] *= c;
            #pragma unroll
            for (int j = 0; j < 4; j++) ps[(ty*4+i)*65 + tx + 16*j] = p[j];
        }
        __syncthreads();                        // ps done; ks (K) reads done
        #pragma unroll
        for (int l = 0; l < 16; l++) {          // overwrite ks with V tile
            int e = tid + 256*l;
            ks[(e >> 6)*65 + (e & 63)] = v[base + (e >> 6)*NT + tk0 + (e & 63)];
        }
        __syncthreads();

        // O += P @ V^T
        #pragma unroll 16
        for (int j = 0; j < 64; j++) {
            float pv[4], vv[4];
            #pragma unroll
            for (int i = 0; i < 4; i++) pv[i] = ps[(ty*4+i)*65 + j];
            #pragma unroll
            for (int kk = 0; kk < 4; kk++) vv[kk] = ks[(tx + 16*kk)*65 + j];
            #pragma unroll
            for (int i = 0; i < 4; i++)
                #pragma unroll
                for (int kk = 0; kk < 4; kk++) acc[i][kk] += pv[i]*vv[kk];
        }
    }

    #pragma unroll
    for (int i = 0; i < 4; i++) {
        const int tq = t0 + ty*4 + i;
        const float sel = (qmask[b*NT + tq] != 0) ? (1.0f / l_i[i]) : 0.f;
        #pragma unroll
        for (int kk = 0; kk < 4; kk++)
            out[base + (tx + 16*kk)*NT + tq] = acc[i][kk] * sel;
    }
}

// ---------------- launch ----------------
extern "C" void kernel_launch(void* const* d_in, const int* in_sizes, int n_in,
                              void* d_out, int out_size) {
    (void)in_sizes; (void)n_in; (void)out_size;
    const float* q   = (const float*)d_in[0];
    const float* k   = (const float*)d_in[1];
    const float* v   = (const float*)d_in[2];
    const int*   qm  = (const int*)d_in[3];
    const int*   km  = (const int*)d_in[4];
    const int*   vm  = (const int*)d_in[5];
    const float* Wq  = (const float*)d_in[6];
    const float* bq  = (const float*)d_in[7];
    const float* Wk  = (const float*)d_in[8];
    const float* bk  = (const float*)d_in[9];
    const float* Wv  = (const float*)d_in[10];
    const float* bv  = (const float*)d_in[11];
    const float* Wo  = (const float*)d_in[12];
    const float* bo  = (const float*)d_in[13];
    const float* gq  = (const float*)d_in[14];
    const float* bgq = (const float*)d_in[15];
    const float* gk  = (const float*)d_in[16];
    const float* bgk = (const float*)d_in[17];
    const float* gv  = (const float*)d_in[18];
    const float* bgv = (const float*)d_in[19];

    float *wn, *pq, *pk, *pv, *pa;
    cudaGetSymbolAddress((void**)&wn, g_Wn);
    cudaGetSymbolAddress((void**)&pq, g_q);
    cudaGetSymbolAddress((void**)&pk, g_k);
    cudaGetSymbolAddress((void**)&pv, g_v);
    cudaGetSymbolAddress((void**)&pa, g_att);

    std_weights_kernel<<<dim3(NE, 4), 128>>>(Wq, Wk, Wv, Wo);

    ProjArgs A;
    A.s[0] = { q, qm, wn + 0*NE*NE, bq, gq, bgq, pq };
    A.s[1] = { k, km, wn + 1*NE*NE, bk, gk, bgk, pk };
    A.s[2] = { v, vm, wn + 2*NE*NE, bv, gv, bgv, pv };
    proj_kernel<true><<<dim3(NT/128, NH, 6), 256>>>(A);

    const int attn_smem = (4096 + 4160 + 4160 + 64) * 4;   // 49,920 B
    cudaFuncSetAttribute(attn_kernel, cudaFuncAttributeMaxDynamicSharedMemorySize, 51200);
    attn_kernel<<<dim3(NT/64, NH, NB), 256, attn_smem>>>(pq, pk, pv, qm, km, pa);

    ProjArgs Ao;
    Ao.s[0] = { pa, qm, wn + 3*NE*NE, bo, nullptr, nullptr, (float*)d_out };
    Ao.s[1] = Ao.s[0];
    Ao.s[2] = Ao.s[0];
    proj_kernel<false><<<dim3(NT/128, NH, 2), 256>>>(Ao);
}

// round 2
// speedup vs baseline: 1.0071x; 1.0071x over previous
#include <cuda_runtime.h>
#include <math.h>

#define NB 2
#define NE 512
#define NH 8
#define ND 64
#define NT 2048
#define EPSV 1e-5f
#define INV_SCALE (1.0f/181.0f)

// ---------------- scratch (device globals: allocation-free) ----------------
__device__ float g_Wn[4*NE*NE];     // standardized weights
__device__ float g_q[NB*NE*NT];
__device__ float g_k[NB*NE*NT];
__device__ float g_v[NB*NE*NT];
__device__ float g_att[NB*NE*NT];

__device__ __forceinline__ float to_tf32(float x) {
    unsigned u;
    asm("cvt.rna.tf32.f32 %0, %1;" : "=r"(u) : "f"(x));
    return __uint_as_float(u);
}

__device__ __forceinline__ void mma_tf32(float* d,
        unsigned a0, unsigned a1, unsigned a2, unsigned a3,
        unsigned b0, unsigned b1) {
    asm volatile("mma.sync.aligned.m16n8k8.row.col.f32.tf32.tf32.f32 "
        "{%0,%1,%2,%3}, {%4,%5,%6,%7}, {%8,%9}, {%0,%1,%2,%3};\n"
        : "+f"(d[0]), "+f"(d[1]), "+f"(d[2]), "+f"(d[3])
        : "r"(a0), "r"(a1), "r"(a2), "r"(a3), "r"(b0), "r"(b1));
}

// ---------------- 1) weight standardization ----------------
__global__ void std_weights_kernel(const float* __restrict__ W0, const float* __restrict__ W1,
                                   const float* __restrict__ W2, const float* __restrict__ W3) {
    const float* Ws[4] = {W0, W1, W2, W3};
    const float* W = Ws[blockIdx.y];
    float* out = g_Wn + blockIdx.y * NE * NE;
    const int row = blockIdx.x;
    const int tid = threadIdx.x;

    float w[4];
    #pragma unroll
    for (int j = 0; j < 4; j++) w[j] = W[row*NE + tid + 128*j];

    __shared__ float red[4];
    float s = w[0]+w[1]+w[2]+w[3];
    #pragma unroll
    for (int o = 16; o > 0; o >>= 1) s += __shfl_down_sync(0xffffffffu, s, o);
    if ((tid & 31) == 0) red[tid >> 5] = s;
    __syncthreads();
    const float mu = (red[0]+red[1]+red[2]+red[3]) * (1.0f/NE);
    __syncthreads();

    float s2 = 0.f;
    #pragma unroll
    for (int j = 0; j < 4; j++) { float d = w[j]-mu; s2 += d*d; }
    #pragma unroll
    for (int o = 16; o > 0; o >>= 1) s2 += __shfl_down_sync(0xffffffffu, s2, o);
    if ((tid & 31) == 0) red[tid >> 5] = s2;
    __syncthreads();
    const float var = (red[0]+red[1]+red[2]+red[3]) * (1.0f/NE);
    const float rstd = rsqrtf(var + EPSV);
    #pragma unroll
    for (int j = 0; j < 4; j++) out[row*NE + tid + 128*j] = (w[j]-mu)*rstd;
}

// ---------------- 2/4) projection GEMM (+bias, optional per-head LN) ----------------
struct ProjSet {
    const float* x; const int* mask; const float* wn; const float* bias;
    const float* lng; const float* lnb; float* out;
};
struct ProjArgs { ProjSet s[3]; };

template<bool DO_LN>
__global__ void __launch_bounds__(256) proj_kernel(ProjArgs A) {
    const int which = blockIdx.z >> 1;
    const int b = blockIdx.z & 1;
    const float* __restrict__ Xp = A.s[which].x;
    const int*   __restrict__ Mp = A.s[which].mask;
    const float* __restrict__ Wp = A.s[which].wn;
    const float* __restrict__ Bp = A.s[which].bias;
    const float* __restrict__ Gp = A.s[which].lng;
    const float* __restrict__ Lp = A.s[which].lnb;
    float*       __restrict__ Op = A.s[which].out;

    const int h  = blockIdx.y;
    const int t0 = blockIdx.x * 128;
    const int tid = threadIdx.x;
    const int tx = tid & 15, ty = tid >> 4;

    __shared__ float smem[8192];
    __shared__ float km_s[128];
    __shared__ float lng_s[ND];
    __shared__ float lnb_s[ND];
    float* wt = smem;                 // [64][33]
    float* xt = smem + 64*33;         // [32][128]

    if (tid < 128) km_s[tid] = (float)Mp[b*NT + t0 + tid];
    if (DO_LN && tid >= 128 && tid < 192) {
        lng_s[tid-128] = Gp[tid-128];
        lnb_s[tid-128] = Lp[tid-128];
    }
    __syncthreads();

    float acc[4][8];
    #pragma unroll
    for (int i = 0; i < 4; i++)
        #pragma unroll
        for (int j = 0; j < 8; j++) acc[i][j] = 0.f;

    const float* Wr = Wp + (h*ND)*NE;
    const float* Xb = Xp + b*NE*NT;

    for (int k0 = 0; k0 < NE; k0 += 32) {
        #pragma unroll
        for (int l = 0; l < 8; l++) {
            int e = tid + 256*l; int r = e >> 5, c = e & 31;
            wt[r*33 + c] = Wr[r*NE + k0 + c];
        }
        #pragma unroll
        for (int l = 0; l < 16; l++) {
            int e = tid + 256*l; int r = e >> 7, c = e & 127;
            xt[e] = Xb[(k0 + r)*NT + t0 + c] * km_s[c];
        }
        __syncthreads();
        #pragma unroll 8
        for (int kk = 0; kk < 32; kk++) {
            float a[4], xx[8];
            #pragma unroll
            for (int i = 0; i < 4; i++) a[i] = wt[(ty*4+i)*33 + kk];
            #pragma unroll
            for (int j = 0; j < 8; j++) xx[j] = xt[kk*128 + tx + 16*j];
            #pragma unroll
            for (int i = 0; i < 4; i++)
                #pragma unroll
                for (int j = 0; j < 8; j++) acc[i][j] += a[i]*xx[j];
        }
        __syncthreads();
    }

    float bv[4];
    #pragma unroll
    for (int i = 0; i < 4; i++) bv[i] = Bp[h*ND + ty*4 + i];

    if (!DO_LN) {
        #pragma unroll
        for (int i = 0; i < 4; i++)
            #pragma unroll
            for (int j = 0; j < 8; j++)
                Op[b*NE*NT + (h*ND + ty*4+i)*NT + t0 + tx + 16*j] = acc[i][j] + bv[i];
    } else {
        #pragma unroll
        for (int i = 0; i < 4; i++)
            #pragma unroll
            for (int j = 0; j < 8; j++)
                smem[(ty*4+i)*128 + tx + 16*j] = acc[i][j] + bv[i];
        __syncthreads();
        if (tid < 128) {
            const int c = tid;
            float s = 0.f;
            #pragma unroll 16
            for (int d = 0; d < 64; d++) s += smem[d*128 + c];
            const float mu = s * (1.0f/64.0f);
            float s2 = 0.f;
            #pragma unroll 16
            for (int d = 0; d < 64; d++) { float dd = smem[d*128 + c] - mu; s2 += dd*dd; }
            const float rstd = rsqrtf(s2*(1.0f/64.0f) + EPSV);
            float* o = Op + b*NE*NT + (h*ND)*NT + t0 + c;
            #pragma unroll 8
            for (int d = 0; d < 64; d++)
                o[d*NT] = (smem[d*128 + c] - mu)*rstd*lng_s[d] + lnb_s[d];
        }
    }
}

// ---------------- 3) flash attention: tf32 tensor cores ----------------
// grid (T/64, H, B), 128 threads = 4 warps. Warp w owns q-rows [w*16, w*16+16).
// smem tiles (tf32-rounded fp32):
//   qs[d][q]  stride 72  (A-fragments of S read B-style: conflict-free)
//   ks[d][k]  stride 72
//   vs[d][k]  stride 68
//   ps[q][k]  stride 72  (warp-private rows)
#define QS_S 72
#define KS_S 72
#define VS_S 68
#define PS_S 72
#define ATTN_SMEM_FLOATS (64*QS_S + 64*KS_S + 64*VS_S + 64*PS_S + 64)

__global__ void __launch_bounds__(128) attn_mma_kernel(
        const float* __restrict__ q, const float* __restrict__ k, const float* __restrict__ v,
        const int* __restrict__ qmask, const int* __restrict__ kmask,
        float* __restrict__ out) {
    extern __shared__ float sm[];
    float* qs = sm;
    float* ks = qs + 64*QS_S;
    float* vs = ks + 64*KS_S;
    float* ps = vs + 64*VS_S;
    float* km = ps + 64*PS_S;

    const int t0 = blockIdx.x * 64;
    const int h = blockIdx.y, b = blockIdx.z;
    const int tid = threadIdx.x;
    const int lane = tid & 31;
    const int w = tid >> 5;             // warp 0..3
    const int g = lane >> 2;            // group 0..7
    const int t4 = lane & 3;            // thread in group
    const int w16 = w * 16;
    const int base = (b*NE + h*ND)*NT;

    // ---- load Q tile: qs[d][t], float4, tf32-rounded ----
    {
        const int r0 = tid >> 4;        // 0..7
        const int c4 = tid & 15;        // 0..15 (x4 floats)
        #pragma unroll
        for (int l = 0; l < 8; l++) {
            const int d = r0 + 8*l;
            float4 val = *(const float4*)(q + base + d*NT + t0 + c4*4);
            float4 o4 = make_float4(to_tf32(val.x), to_tf32(val.y), to_tf32(val.z), to_tf32(val.w));
            *(float4*)(qs + d*QS_S + c4*4) = o4;
        }
    }

    float m0 = -1e30f, m1 = -1e30f, l0 = 0.f, l1 = 0.f;
    float oacc[8][4];
    #pragma unroll
    for (int n = 0; n < 8; n++)
        #pragma unroll
        for (int j = 0; j < 4; j++) oacc[n][j] = 0.f;

    for (int kt = 0; kt < NT/64; kt++) {
        const int tk0 = kt*64;
        __syncthreads();   // previous iteration's ks/vs reads complete
        {
            const int r0 = tid >> 4;
            const int c4 = tid & 15;
            #pragma unroll
            for (int l = 0; l < 8; l++) {
                const int d = r0 + 8*l;
                float4 kv = *(const float4*)(k + base + d*NT + tk0 + c4*4);
                *(float4*)(ks + d*KS_S + c4*4) =
                    make_float4(to_tf32(kv.x), to_tf32(kv.y), to_tf32(kv.z), to_tf32(kv.w));
                float4 vv = *(const float4*)(v + base + d*NT + tk0 + c4*4);
                *(float4*)(vs + d*VS_S + c4*4) =
                    make_float4(to_tf32(vv.x), to_tf32(vv.y), to_tf32(vv.z), to_tf32(vv.w));
            }
            if (tid < 64) km[tid] = (float)kmask[b*NT + tk0 + tid];
        }
        __syncthreads();

        // ---- S = Q^T K : 8 n-tiles of m16n8, k-dim = d (8 chunks of 8) ----
        float sf[8][4];
        #pragma unroll
        for (int n = 0; n < 8; n++)
            #pragma unroll
            for (int j = 0; j < 4; j++) sf[n][j] = 0.f;
        #pragma unroll
        for (int dc = 0; dc < 8; dc++) {
            const int d0 = dc*8;
            unsigned a0 = __float_as_uint(qs[(d0+t4  )*QS_S + w16 + g]);
            unsigned a1 = __float_as_uint(qs[(d0+t4  )*QS_S + w16 + g + 8]);
            unsigned a2 = __float_as_uint(qs[(d0+t4+4)*QS_S + w16 + g]);
            unsigned a3 = __float_as_uint(qs[(d0+t4+4)*QS_S + w16 + g + 8]);
            #pragma unroll
            for (int n = 0; n < 8; n++) {
                unsigned b0 = __float_as_uint(ks[(d0+t4  )*KS_S + n*8 + g]);
                unsigned b1 = __float_as_uint(ks[(d0+t4+4)*KS_S + n*8 + g]);
                mma_tf32(sf[n], a0, a1, a2, a3, b0, b1);
            }
        }

        // ---- mask + scale ----
        #pragma unroll
        for (int n = 0; n < 8; n++) {
            const float km0 = km[n*8 + 2*t4];
            const float km1 = km[n*8 + 2*t4 + 1];
            sf[n][0] = (km0 != 0.f) ? sf[n][0]*INV_SCALE : -1e9f;
            sf[n][1] = (km1 != 0.f) ? sf[n][1]*INV_SCALE : -1e9f;
            sf[n][2] = (km0 != 0.f) ? sf[n][2]*INV_SCALE : -1e9f;
            sf[n][3] = (km1 != 0.f) ? sf[n][3]*INV_SCALE : -1e9f;
        }

        // ---- online softmax (rows g and g+8; row-mates = 4-lane quad) ----
        float mx0 = -1e30f, mx1 = -1e30f;
        #pragma unroll
        for (int n = 0; n < 8; n++) {
            mx0 = fmaxf(mx0, fmaxf(sf[n][0], sf[n][1]));
            mx1 = fmaxf(mx1, fmaxf(sf[n][2], sf[n][3]));
        }
        mx0 = fmaxf(mx0, __shfl_xor_sync(0xffffffffu, mx0, 1));
        mx0 = fmaxf(mx0, __shfl_xor_sync(0xffffffffu, mx0, 2));
        mx1 = fmaxf(mx1, __shfl_xor_sync(0xffffffffu, mx1, 1));
        mx1 = fmaxf(mx1, __shfl_xor_sync(0xffffffffu, mx1, 2));

        const float mn0 = fmaxf(m0, mx0);
        const float mn1 = fmaxf(m1, mx1);
        const float c0 = __expf(m0 - mn0);
        const float c1 = __expf(m1 - mn1);
        m0 = mn0; m1 = mn1;

        float rs0 = 0.f, rs1 = 0.f;
        #pragma unroll
        for (int n = 0; n < 8; n++) {
            float p0 = __expf(sf[n][0] - mn0);
            float p1 = __expf(sf[n][1] - mn0);
            float p2 = __expf(sf[n][2] - mn1);
            float p3 = __expf(sf[n][3] - mn1);
            rs0 += p0 + p1; rs1 += p2 + p3;
            *(float2*)(ps + (w16+g  )*PS_S + n*8 + 2*t4) = make_float2(to_tf32(p0), to_tf32(p1));
            *(float2*)(ps + (w16+g+8)*PS_S + n*8 + 2*t4) = make_float2(to_tf32(p2), to_tf32(p3));
        }
        rs0 += __shfl_xor_sync(0xffffffffu, rs0, 1);
        rs0 += __shfl_xor_sync(0xffffffffu, rs0, 2);
        rs1 += __shfl_xor_sync(0xffffffffu, rs1, 1);
        rs1 += __shfl_xor_sync(0xffffffffu, rs1, 2);
        l0 = l0*c0 + rs0;
        l1 = l1*c1 + rs1;
        #pragma unroll
        for (int n = 0; n < 8; n++) {
            oacc[n][0] *= c0; oacc[n][1] *= c0;
            oacc[n][2] *= c1; oacc[n][3] *= c1;
        }
        __syncwarp();   // ps rows are warp-private

        // ---- O += P @ V^T : n = d (8 tiles), k-dim = key (8 chunks) ----
        #pragma unroll
        for (int kc = 0; kc < 8; kc++) {
            const int k0c = kc*8;
            unsigned a0 = __float_as_uint(ps[(w16+g  )*PS_S + k0c + t4]);
            unsigned a1 = __float_as_uint(ps[(w16+g+8)*PS_S + k0c + t4]);
            unsigned a2 = __float_as_uint(ps[(w16+g  )*PS_S + k0c + t4 + 4]);
            unsigned a3 = __float_as_uint(ps[(w16+g+8)*PS_S + k0c + t4 + 4]);
            #pragma unroll
            for (int n = 0; n < 8; n++) {
                unsigned b0 = __float_as_uint(vs[(n*8+g)*VS_S + k0c + t4]);
                unsigned b1 = __float_as_uint(vs[(n*8+g)*VS_S + k0c + t4 + 4]);
                mma_tf32(oacc[n], a0, a1, a2, a3, b0, b1);
            }
        }
        __syncwarp();
    }

    // ---- epilogue: normalize + query mask, write out[d][t] ----
    const int qrow0 = t0 + w16 + g;
    const int qrow1 = qrow0 + 8;
    const float sel0 = (qmask[b*NT + qrow0] != 0) ? (1.0f / l0) : 0.f;
    const float sel1 = (qmask[b*NT + qrow1] != 0) ? (1.0f / l1) : 0.f;
    #pragma unroll
    for (int n = 0; n < 8; n++) {
        const int d0 = n*8 + 2*t4;
        out[base + (d0  )*NT + qrow0] = oacc[n][0] * sel0;
        out[base + (d0+1)*NT + qrow0] = oacc[n][1] * sel0;
        out[base + (d0  )*NT + qrow1] = oacc[n][2] * sel1;
        out[base + (d0+1)*NT + qrow1] = oacc[n][3] * sel1;
    }
}

// ---------------- launch ----------------
extern "C" void kernel_launch(void* const* d_in, const int* in_sizes, int n_in,
                              void* d_out, int out_size) {
    (void)in_sizes; (void)n_in; (void)out_size;
    const float* q   = (const float*)d_in[0];
    const float* k   = (const float*)d_in[1];
    const float* v   = (const float*)d_in[2];
    const int*   qm  = (const int*)d_in[3];
    const int*   km  = (const int*)d_in[4];
    const int*   vm  = (const int*)d_in[5];
    const float* Wq  = (const float*)d_in[6];
    const float* bq  = (const float*)d_in[7];
    const float* Wk  = (const float*)d_in[8];
    const float* bk  = (const float*)d_in[9];
    const float* Wv  = (const float*)d_in[10];
    const float* bv  = (const float*)d_in[11];
    const float* Wo  = (const float*)d_in[12];
    const float* bo  = (const float*)d_in[13];
    const float* gq  = (const float*)d_in[14];
    const float* bgq = (const float*)d_in[15];
    const float* gk  = (const float*)d_in[16];
    const float* bgk = (const float*)d_in[17];
    const float* gv  = (const float*)d_in[18];
    const float* bgv = (const float*)d_in[19];

    float *wn, *pq, *pk, *pv, *pa;
    cudaGetSymbolAddress((void**)&wn, g_Wn);
    cudaGetSymbolAddress((void**)&pq, g_q);
    cudaGetSymbolAddress((void**)&pk, g_k);
    cudaGetSymbolAddress((void**)&pv, g_v);
    cudaGetSymbolAddress((void**)&pa, g_att);

    std_weights_kernel<<<dim3(NE, 4), 128>>>(Wq, Wk, Wv, Wo);

    ProjArgs A;
    A.s[0] = { q, qm, wn + 0*NE*NE, bq, gq, bgq, pq };
    A.s[1] = { k, km, wn + 1*NE*NE, bk, gk, bgk, pk };
    A.s[2] = { v, vm, wn + 2*NE*NE, bv, gv, bgv, pv };
    proj_kernel<true><<<dim3(NT/128, NH, 6), 256>>>(A);

    const int attn_smem = ATTN_SMEM_FLOATS * 4;
    static int attn_cfg = 0;
    if (!attn_cfg) {
        cudaFuncSetAttribute(attn_mma_kernel, cudaFuncAttributeMaxDynamicSharedMemorySize, attn_smem);
        attn_cfg = 1;
    }
    attn_mma_kernel<<<dim3(NT/64, NH, NB), 128, attn_smem>>>(pq, pk, pv, qm, km, pa);

    ProjArgs Ao;
    Ao.s[0] = { pa, qm, wn + 3*NE*NE, bo, nullptr, nullptr, (float*)d_out };
    Ao.s[1] = Ao.s[0];
    Ao.s[2] = Ao.s[0];
    proj_kernel<false><<<dim3(NT/128, NH, 2), 256>>>(Ao);
}

// round 4
// speedup vs baseline: 2.6786x; 2.6599x over previous
#include <cuda_runtime.h>
#include <math.h>

#define NB 2
#define NE 512
#define NH 8
#define ND 64
#define NT 2048
#define EPSV 1e-5f
#define INV_SCALE (1.0f/181.0f)

// ---------------- scratch (device globals: allocation-free) ----------------
__device__ float g_Wn[4*NE*NE];     // standardized weights
__device__ float g_q[NB*NE*NT];
__device__ float g_k[NB*NE*NT];
__device__ float g_v[NB*NE*NT];
__device__ float g_att[NB*NE*NT];

__device__ __forceinline__ float to_tf32(float x) {
    unsigned u;
    asm("cvt.rna.tf32.f32 %0, %1;" : "=r"(u) : "f"(x));
    return __uint_as_float(u);
}

__device__ __forceinline__ void mma_tf32(float* d,
        unsigned a0, unsigned a1, unsigned a2, unsigned a3,
        unsigned b0, unsigned b1) {
    asm volatile("mma.sync.aligned.m16n8k8.row.col.f32.tf32.tf32.f32 "
        "{%0,%1,%2,%3}, {%4,%5,%6,%7}, {%8,%9}, {%0,%1,%2,%3};\n"
        : "+f"(d[0]), "+f"(d[1]), "+f"(d[2]), "+f"(d[3])
        : "r"(a0), "r"(a1), "r"(a2), "r"(a3), "r"(b0), "r"(b1));
}

// ---------------- 1) weight standardization ----------------
__global__ void std_weights_kernel(const float* __restrict__ W0, const float* __restrict__ W1,
                                   const float* __restrict__ W2, const float* __restrict__ W3) {
    const float* Ws[4] = {W0, W1, W2, W3};
    const float* W = Ws[blockIdx.y];
    float* out = g_Wn + blockIdx.y * NE * NE;
    const int row = blockIdx.x;
    const int tid = threadIdx.x;

    float w[4];
    #pragma unroll
    for (int j = 0; j < 4; j++) w[j] = W[row*NE + tid + 128*j];

    __shared__ float red[4];
    float s = w[0]+w[1]+w[2]+w[3];
    #pragma unroll
    for (int o = 16; o > 0; o >>= 1) s += __shfl_down_sync(0xffffffffu, s, o);
    if ((tid & 31) == 0) red[tid >> 5] = s;
    __syncthreads();
    const float mu = (red[0]+red[1]+red[2]+red[3]) * (1.0f/NE);
    __syncthreads();

    float s2 = 0.f;
    #pragma unroll
    for (int j = 0; j < 4; j++) { float d = w[j]-mu; s2 += d*d; }
    #pragma unroll
    for (int o = 16; o > 0; o >>= 1) s2 += __shfl_down_sync(0xffffffffu, s2, o);
    if ((tid & 31) == 0) red[tid >> 5] = s2;
    __syncthreads();
    const float var = (red[0]+red[1]+red[2]+red[3]) * (1.0f/NE);
    const float rstd = rsqrtf(var + EPSV);
    #pragma unroll
    for (int j = 0; j < 4; j++) out[row*NE + tid + 128*j] = (w[j]-mu)*rstd;
}

// ---------------- 2/4) projection GEMM via tf32 mma (+bias, optional LN) ----------------
struct ProjSet {
    const float* x; const int* mask; const float* wn; const float* bias;
    const float* lng; const float* lnb; float* out;
};
struct ProjArgs { ProjSet s[3]; };

// Block: 256 thr = 8 warps (wm 0..3 picks 16 rows, wn 0..1 picks 64 cols).
// Tile M=64 (one head), N=128, K-chunks of 32.
#define WT_S 36
#define XT_S 136
template<bool DO_LN>
__global__ void __launch_bounds__(256) proj_mma_kernel(ProjArgs A) {
    const int which = blockIdx.z >> 1;
    const int b = blockIdx.z & 1;
    const float* __restrict__ Xp = A.s[which].x;
    const int*   __restrict__ Mp = A.s[which].mask;
    const float* __restrict__ Wp = A.s[which].wn;
    const float* __restrict__ Bp = A.s[which].bias;
    const float* __restrict__ Gp = A.s[which].lng;
    const float* __restrict__ Lp = A.s[which].lnb;
    float*       __restrict__ Op = A.s[which].out;

    const int h  = blockIdx.y;
    const int t0 = blockIdx.x * 128;
    const int tid = threadIdx.x;
    const int lane = tid & 31;
    const int wid = tid >> 5;
    const int wm = wid & 3, wn = wid >> 2;
    const int g = lane >> 2, t4 = lane & 3;

    __shared__ float smem[64*XT_S];           // wt(64*36=2304) + xt(32*136=4352) <= 8704; reused as ts[64][136]
    __shared__ float km_s[128];
    __shared__ float lng_s[ND];
    __shared__ float lnb_s[ND];
    float* wt = smem;                         // [64][36]
    float* xt = smem + 64*WT_S;               // [32][136]

    if (tid < 128) km_s[tid] = (float)Mp[b*NT + t0 + tid];
    if (DO_LN && tid >= 128 && tid < 192) {
        lng_s[tid-128] = Gp[tid-128];
        lnb_s[tid-128] = Lp[tid-128];
    }
    __syncthreads();

    float acc[8][4];
    #pragma unroll
    for (int n = 0; n < 8; n++)
        #pragma unroll
        for (int j = 0; j < 4; j++) acc[n][j] = 0.f;

    const float* Wr = Wp + (h*ND)*NE;
    const float* Xb = Xp + b*NE*NT;

    for (int k0 = 0; k0 < NE; k0 += 32) {
        // fill wt [64 rows][32 k] tf32
        #pragma unroll
        for (int l = 0; l < 2; l++) {
            int f = tid + 256*l; int r = f >> 3, c4 = f & 7;
            float4 wv = *(const float4*)(Wr + r*NE + k0 + c4*4);
            *(float4*)(wt + r*WT_S + c4*4) =
                make_float4(to_tf32(wv.x), to_tf32(wv.y), to_tf32(wv.z), to_tf32(wv.w));
        }
        // fill xt [32 k][128 t] masked tf32
        #pragma unroll
        for (int l = 0; l < 4; l++) {
            int f = tid + 256*l; int r = f >> 5, c4 = f & 31;
            float4 xv = *(const float4*)(Xb + (k0+r)*NT + t0 + c4*4);
            float4 mv = *(const float4*)(km_s + c4*4);
            *(float4*)(xt + r*XT_S + c4*4) =
                make_float4(to_tf32(xv.x*mv.x), to_tf32(xv.y*mv.y),
                            to_tf32(xv.z*mv.z), to_tf32(xv.w*mv.w));
        }
        __syncthreads();
        #pragma unroll
        for (int dc = 0; dc < 4; dc++) {
            const int kk = dc*8;
            unsigned a0 = __float_as_uint(wt[(wm*16+g   )*WT_S + kk + t4]);
            unsigned a1 = __float_as_uint(wt[(wm*16+g+8 )*WT_S + kk + t4]);
            unsigned a2 = __float_as_uint(wt[(wm*16+g   )*WT_S + kk + t4 + 4]);
            unsigned a3 = __float_as_uint(wt[(wm*16+g+8 )*WT_S + kk + t4 + 4]);
            #pragma unroll
            for (int n = 0; n < 8; n++) {
                unsigned b0 = __float_as_uint(xt[(kk+t4  )*XT_S + wn*64 + n*8 + g]);
                unsigned b1 = __float_as_uint(xt[(kk+t4+4)*XT_S + wn*64 + n*8 + g]);
                mma_tf32(acc[n], a0, a1, a2, a3, b0, b1);
            }
        }
        __syncthreads();
    }

    const float bv0 = Bp[h*ND + wm*16 + g];
    const float bv1 = Bp[h*ND + wm*16 + g + 8];

    if (!DO_LN) {
        float* o = Op + b*NE*NT + (h*ND)*NT + t0;
        #pragma unroll
        for (int n = 0; n < 8; n++) {
            const int c = wn*64 + n*8 + 2*t4;
            *(float2*)(o + (wm*16+g  )*NT + c) = make_float2(acc[n][0]+bv0, acc[n][1]+bv0);
            *(float2*)(o + (wm*16+g+8)*NT + c) = make_float2(acc[n][2]+bv1, acc[n][3]+bv1);
        }
    } else {
        // stage tile into smem [64][136], then per-column LN over the 64 head rows
        #pragma unroll
        for (int n = 0; n < 8; n++) {
            const int c = wn*64 + n*8 + 2*t4;
            *(float2*)(smem + (wm*16+g  )*XT_S + c) = make_float2(acc[n][0]+bv0, acc[n][1]+bv0);
            *(float2*)(smem + (wm*16+g+8)*XT_S + c) = make_float2(acc[n][2]+bv1, acc[n][3]+bv1);
        }
        __syncthreads();
        if (tid < 128) {
            const int c = tid;
            float s = 0.f;
            #pragma unroll 16
            for (int d = 0; d < 64; d++) s += smem[d*XT_S + c];
            const float mu = s * (1.0f/64.0f);
            float s2 = 0.f;
            #pragma unroll 16
            for (int d = 0; d < 64; d++) { float dd = smem[d*XT_S + c] - mu; s2 += dd*dd; }
            const float rstd = rsqrtf(s2*(1.0f/64.0f) + EPSV);
            float* o = Op + b*NE*NT + (h*ND)*NT + t0 + c;
            #pragma unroll 8
            for (int d = 0; d < 64; d++)
                o[d*NT] = (smem[d*XT_S + c] - mu)*rstd*lng_s[d] + lnb_s[d];
        }
    }
}

// ---------------- 3) flash attention: tf32 mma, Q-frags in regs, P via shuffle ----------------
// grid (T/64, H, B), 128 threads = 4 warps; warp w owns q-rows [w*16, w*16+16).
#define KS_S 72
#define VS_S 72
__global__ void __launch_bounds__(128) attn_mma_kernel(
        const float* __restrict__ q, const float* __restrict__ k, const float* __restrict__ v,
        const int* __restrict__ qmask, const int* __restrict__ kmask,
        float* __restrict__ out) {
    __shared__ float ks[64*KS_S];
    __shared__ float vs[64*VS_S];
    __shared__ float km[64];

    const int t0 = blockIdx.x * 64;
    const int h = blockIdx.y, b = blockIdx.z;
    const int tid = threadIdx.x;
    const int lane = tid & 31;
    const int w = tid >> 5;
    const int g = lane >> 2;
    const int t4 = lane & 3;
    const int w16 = w * 16;
    const int base = (b*NE + h*ND)*NT;
    const int r0 = tid >> 4;        // 0..7
    const int c4 = tid & 15;        // 0..15

    // ---- prologue: stage Q through ks, extract fragments to registers ----
    #pragma unroll
    for (int l = 0; l < 8; l++) {
        const int d = r0 + 8*l;
        float4 val = *(const float4*)(q + base + d*NT + t0 + c4*4);
        *(float4*)(ks + d*KS_S + c4*4) =
            make_float4(to_tf32(val.x), to_tf32(val.y), to_tf32(val.z), to_tf32(val.w));
    }
    __syncthreads();
    unsigned qa[8][4];
    #pragma unroll
    for (int dc = 0; dc < 8; dc++) {
        const int d0 = dc*8;
        qa[dc][0] = __float_as_uint(ks[(d0+t4  )*KS_S + w16 + g]);
        qa[dc][1] = __float_as_uint(ks[(d0+t4  )*KS_S + w16 + g + 8]);
        qa[dc][2] = __float_as_uint(ks[(d0+t4+4)*KS_S + w16 + g]);
        qa[dc][3] = __float_as_uint(ks[(d0+t4+4)*KS_S + w16 + g + 8]);
    }

    float m0 = -1e30f, m1 = -1e30f, l0 = 0.f, l1 = 0.f;
    float oacc[8][4];
    #pragma unroll
    for (int n = 0; n < 8; n++)
        #pragma unroll
        for (int j = 0; j < 4; j++) oacc[n][j] = 0.f;

    const int srcA = (lane & ~3) | (t4 >> 1);
    const int srcB = srcA + 2;
    const bool odd = (t4 & 1);

    for (int kt = 0; kt < NT/64; kt++) {
        const int tk0 = kt*64;
        __syncthreads();   // previous tile's smem reads complete (also guards Q extract)
        #pragma unroll
        for (int l = 0; l < 8; l++) {
            const int d = r0 + 8*l;
            float4 kv = *(const float4*)(k + base + d*NT + tk0 + c4*4);
            *(float4*)(ks + d*KS_S + c4*4) =
                make_float4(to_tf32(kv.x), to_tf32(kv.y), to_tf32(kv.z), to_tf32(kv.w));
            float4 vv = *(const float4*)(v + base + d*NT + tk0 + c4*4);
            *(float4*)(vs + d*VS_S + c4*4) =
                make_float4(to_tf32(vv.x), to_tf32(vv.y), to_tf32(vv.z), to_tf32(vv.w));
        }
        if (tid < 64) km[tid] = (float)kmask[b*NT + tk0 + tid];
        __syncthreads();

        // ---- S = Q^T K ----
        float sf[8][4];
        #pragma unroll
        for (int n = 0; n < 8; n++)
            #pragma unroll
            for (int j = 0; j < 4; j++) sf[n][j] = 0.f;
        #pragma unroll
        for (int dc = 0; dc < 8; dc++) {
            const int d0 = dc*8;
            #pragma unroll
            for (int n = 0; n < 8; n++) {
                unsigned b0 = __float_as_uint(ks[(d0+t4  )*KS_S + n*8 + g]);
                unsigned b1 = __float_as_uint(ks[(d0+t4+4)*KS_S + n*8 + g]);
                mma_tf32(sf[n], qa[dc][0], qa[dc][1], qa[dc][2], qa[dc][3], b0, b1);
            }
        }

        // ---- mask + scale ----
        #pragma unroll
        for (int n = 0; n < 8; n++) {
            const float km0 = km[n*8 + 2*t4];
            const float km1 = km[n*8 + 2*t4 + 1];
            sf[n][0] = (km0 != 0.f) ? sf[n][0]*INV_SCALE : -1e9f;
            sf[n][1] = (km1 != 0.f) ? sf[n][1]*INV_SCALE : -1e9f;
            sf[n][2] = (km0 != 0.f) ? sf[n][2]*INV_SCALE : -1e9f;
            sf[n][3] = (km1 != 0.f) ? sf[n][3]*INV_SCALE : -1e9f;
        }

        // ---- online softmax (rows g, g+8; row-mates share the 4-lane quad) ----
        float mx0 = -1e30f, mx1 = -1e30f;
        #pragma unroll
        for (int n = 0; n < 8; n++) {
            mx0 = fmaxf(mx0, fmaxf(sf[n][0], sf[n][1]));
            mx1 = fmaxf(mx1, fmaxf(sf[n][2], sf[n][3]));
        }
        mx0 = fmaxf(mx0, __shfl_xor_sync(0xffffffffu, mx0, 1));
        mx0 = fmaxf(mx0, __shfl_xor_sync(0xffffffffu, mx0, 2));
        mx1 = fmaxf(mx1, __shfl_xor_sync(0xffffffffu, mx1, 1));
        mx1 = fmaxf(mx1, __shfl_xor_sync(0xffffffffu, mx1, 2));

        const float mn0 = fmaxf(m0, mx0);
        const float mn1 = fmaxf(m1, mx1);
        const float c0 = __expf(m0 - mn0);
        const float c1 = __expf(m1 - mn1);
        m0 = mn0; m1 = mn1;

        unsigned pu0[8], pu1[8], pu2[8], pu3[8];
        float rs0 = 0.f, rs1 = 0.f;
        #pragma unroll
        for (int n = 0; n < 8; n++) {
            float p0 = __expf(sf[n][0] - mn0);
            float p1 = __expf(sf[n][1] - mn0);
            float p2 = __expf(sf[n][2] - mn1);
            float p3 = __expf(sf[n][3] - mn1);
            rs0 += p0 + p1; rs1 += p2 + p3;
            pu0[n] = __float_as_uint(to_tf32(p0));
            pu1[n] = __float_as_uint(to_tf32(p1));
            pu2[n] = __float_as_uint(to_tf32(p2));
            pu3[n] = __float_as_uint(to_tf32(p3));
        }
        rs0 += __shfl_xor_sync(0xffffffffu, rs0, 1);
        rs0 += __shfl_xor_sync(0xffffffffu, rs0, 2);
        rs1 += __shfl_xor_sync(0xffffffffu, rs1, 1);
        rs1 += __shfl_xor_sync(0xffffffffu, rs1, 2);
        l0 = l0*c0 + rs0;
        l1 = l1*c1 + rs1;
        #pragma unroll
        for (int n = 0; n < 8; n++) {
            oacc[n][0] *= c0; oacc[n][1] *= c0;
            oacc[n][2] *= c1; oacc[n][3] *= c1;
        }

        // ---- O += P @ V^T ; A fragment built by quad shuffles (no smem) ----
        #pragma unroll
        for (int kc = 0; kc < 8; kc++) {
            unsigned e0 = __shfl_sync(0xffffffffu, pu0[kc], srcA);
            unsigned e1 = __shfl_sync(0xffffffffu, pu1[kc], srcA);
            unsigned a0 = odd ? e1 : e0;
            unsigned f0 = __shfl_sync(0xffffffffu, pu2[kc], srcA);
            unsigned f1 = __shfl_sync(0xffffffffu, pu3[kc], srcA);
            unsigned a1 = odd ? f1 : f0;
            e0 = __shfl_sync(0xffffffffu, pu0[kc], srcB);
            e1 = __shfl_sync(0xffffffffu, pu1[kc], srcB);
            unsigned a2 = odd ? e1 : e0;
            f0 = __shfl_sync(0xffffffffu, pu2[kc], srcB);
            f1 = __shfl_sync(0xffffffffu, pu3[kc], srcB);
            unsigned a3 = odd ? f1 : f0;
            const int k0c = kc*8;
            #pragma unroll
            for (int n = 0; n < 8; n++) {
                unsigned b0 = __float_as_uint(vs[(n*8+g)*VS_S + k0c + t4]);
                unsigned b1 = __float_as_uint(vs[(n*8+g)*VS_S + k0c + t4 + 4]);
                mma_tf32(oacc[n], a0, a1, a2, a3, b0, b1);
            }
        }
    }

    // ---- epilogue: normalize + query mask, write out[d][t] ----
    const int qrow0 = t0 + w16 + g;
    const int qrow1 = qrow0 + 8;
    const float sel0 = (qmask[b*NT + qrow0] != 0) ? (1.0f / l0) : 0.f;
    const float sel1 = (qmask[b*NT + qrow1] != 0) ? (1.0f / l1) : 0.f;
    #pragma unroll
    for (int n = 0; n < 8; n++) {
        const int d0 = n*8 + 2*t4;
        out[base + (d0  )*NT + qrow0] = oacc[n][0] * sel0;
        out[base + (d0+1)*NT + qrow0] = oacc[n][1] * sel0;
        out[base + (d0  )*NT + qrow1] = oacc[n][2] * sel1;
        out[base + (d0+1)*NT + qrow1] = oacc[n][3] * sel1;
    }
}

// ---------------- launch ----------------
extern "C" void kernel_launch(void* const* d_in, const int* in_sizes, int n_in,
                              void* d_out, int out_size) {
    (void)in_sizes; (void)n_in; (void)out_size;
    const float* q   = (const float*)d_in[0];
    const float* k   = (const float*)d_in[1];
    const float* v   = (const float*)d_in[2];
    const int*   qm  = (const int*)d_in[3];
    const int*   km  = (const int*)d_in[4];
    const int*   vm  = (const int*)d_in[5];
    const float* Wq  = (const float*)d_in[6];
    const float* bq  = (const float*)d_in[7];
    const float* Wk  = (const float*)d_in[8];
    const float* bk  = (const float*)d_in[9];
    const float* Wv  = (const float*)d_in[10];
    const float* bv  = (const float*)d_in[11];
    const float* Wo  = (const float*)d_in[12];
    const float* bo  = (const float*)d_in[13];
    const float* gq  = (const float*)d_in[14];
    const float* bgq = (const float*)d_in[15];
    const float* gk  = (const float*)d_in[16];
    const float* bgk = (const float*)d_in[17];
    const float* gv  = (const float*)d_in[18];
    const float* bgv = (const float*)d_in[19];

    float *wn, *pq, *pk, *pv, *pa;
    cudaGetSymbolAddress((void**)&wn, g_Wn);
    cudaGetSymbolAddress((void**)&pq, g_q);
    cudaGetSymbolAddress((void**)&pk, g_k);
    cudaGetSymbolAddress((void**)&pv, g_v);
    cudaGetSymbolAddress((void**)&pa, g_att);

    std_weights_kernel<<<dim3(NE, 4), 128>>>(Wq, Wk, Wv, Wo);

    ProjArgs A;
    A.s[0] = { q, qm, wn + 0*NE*NE, bq, gq, bgq, pq };
    A.s[1] = { k, km, wn + 1*NE*NE, bk, gk, bgk, pk };
    A.s[2] = { v, vm, wn + 2*NE*NE, bv, gv, bgv, pv };
    proj_mma_kernel<true><<<dim3(NT/128, NH, 6), 256>>>(A);

    attn_mma_kernel<<<dim3(NT/64, NH, NB), 128>>>(pq, pk, pv, qm, km, pa);

    ProjArgs Ao;
    Ao.s[0] = { pa, qm, wn + 3*NE*NE, bo, nullptr, nullptr, (float*)d_out };
    Ao.s[1] = Ao.s[0];
    Ao.s[2] = Ao.s[0];
    proj_mma_kernel<false><<<dim3(NT/128, NH, 2), 256>>>(Ao);
}

// round 5
// speedup vs baseline: 2.9059x; 1.0849x over previous
#include <cuda_runtime.h>
#include <math.h>

#define NB 2
#define NE 512
#define NH 8
#define ND 64
#define NT 2048
#define EPSV 1e-5f
#define INV_SCALE (1.0f/181.0f)

// ---------------- scratch (device globals: allocation-free) ----------------
__device__ float g_Wn[4*NE*NE];
__device__ float g_q[NB*NE*NT];
__device__ float g_k[NB*NE*NT];
__device__ float g_v[NB*NE*NT];
__device__ float g_att[NB*NE*NT];

__device__ __forceinline__ float to_tf32(float x) {
    unsigned u;
    asm("cvt.rna.tf32.f32 %0, %1;" : "=r"(u) : "f"(x));
    return __uint_as_float(u);
}
__device__ __forceinline__ unsigned tf32u(float x) {
    unsigned u;
    asm("cvt.rna.tf32.f32 %0, %1;" : "=r"(u) : "f"(x));
    return u;
}

__device__ __forceinline__ void mma_tf32(float* d,
        unsigned a0, unsigned a1, unsigned a2, unsigned a3,
        unsigned b0, unsigned b1) {
    asm volatile("mma.sync.aligned.m16n8k8.row.col.f32.tf32.tf32.f32 "
        "{%0,%1,%2,%3}, {%4,%5,%6,%7}, {%8,%9}, {%0,%1,%2,%3};\n"
        : "+f"(d[0]), "+f"(d[1]), "+f"(d[2]), "+f"(d[3])
        : "r"(a0), "r"(a1), "r"(a2), "r"(a3), "r"(b0), "r"(b1));
}

__device__ __forceinline__ void cp16(void* dst, const void* src) {
    unsigned d = (unsigned)__cvta_generic_to_shared(dst);
    asm volatile("cp.async.ca.shared.global [%0], [%1], 16;" :: "r"(d), "l"(src));
}
__device__ __forceinline__ void cp_commit() { asm volatile("cp.async.commit_group;"); }
__device__ __forceinline__ void cp_wait0()  { asm volatile("cp.async.wait_group 0;"); }

// ---------------- 1) weight standardization ----------------
__global__ void std_weights_kernel(const float* __restrict__ W0, const float* __restrict__ W1,
                                   const float* __restrict__ W2, const float* __restrict__ W3) {
    const float* Ws[4] = {W0, W1, W2, W3};
    const float* W = Ws[blockIdx.y];
    float* out = g_Wn + blockIdx.y * NE * NE;
    const int row = blockIdx.x;
    const int tid = threadIdx.x;

    float w[4];
    #pragma unroll
    for (int j = 0; j < 4; j++) w[j] = W[row*NE + tid + 128*j];

    __shared__ float red[4];
    float s = w[0]+w[1]+w[2]+w[3];
    #pragma unroll
    for (int o = 16; o > 0; o >>= 1) s += __shfl_down_sync(0xffffffffu, s, o);
    if ((tid & 31) == 0) red[tid >> 5] = s;
    __syncthreads();
    const float mu = (red[0]+red[1]+red[2]+red[3]) * (1.0f/NE);
    __syncthreads();

    float s2 = 0.f;
    #pragma unroll
    for (int j = 0; j < 4; j++) { float d = w[j]-mu; s2 += d*d; }
    #pragma unroll
    for (int o = 16; o > 0; o >>= 1) s2 += __shfl_down_sync(0xffffffffu, s2, o);
    if ((tid & 31) == 0) red[tid >> 5] = s2;
    __syncthreads();
    const float var = (red[0]+red[1]+red[2]+red[3]) * (1.0f/NE);
    const float rstd = rsqrtf(var + EPSV);
    #pragma unroll
    for (int j = 0; j < 4; j++) out[row*NE + tid + 128*j] = (w[j]-mu)*rstd;
}

// ---------------- 2/4) projection GEMM: tf32 mma + cp.async 2-stage ----------------
struct ProjSet {
    const float* x; const int* mask; const float* wn; const float* bias;
    const float* lng; const float* lnb; float* out;
};
struct ProjArgs { ProjSet s[3]; };

#define WT_S 36
#define XT_S 136
#define WCH (64*WT_S)
#define XCH (32*XT_S)
#define PROJ_SMEM ((2*WCH + 2*XCH)*4)

template<bool DO_LN>
__global__ void __launch_bounds__(256) proj_mma_kernel(ProjArgs A) {
    const int which = blockIdx.z >> 1;
    const int b = blockIdx.z & 1;
    const float* __restrict__ Xp = A.s[which].x;
    const int*   __restrict__ Mp = A.s[which].mask;
    const float* __restrict__ Wp = A.s[which].wn;
    const float* __restrict__ Bp = A.s[which].bias;
    const float* __restrict__ Gp = A.s[which].lng;
    const float* __restrict__ Lp = A.s[which].lnb;
    float*       __restrict__ Op = A.s[which].out;

    const int h  = blockIdx.y;
    const int t0 = blockIdx.x * 128;
    const int tid = threadIdx.x;
    const int lane = tid & 31;
    const int wid = tid >> 5;
    const int wm = wid & 3, wn = wid >> 2;
    const int g = lane >> 2, t4 = lane & 3;

    extern __shared__ float psm[];
    float* wtb = psm;             // [2][64*36]
    float* xtb = psm + 2*WCH;     // [2][32*136]
    __shared__ float km_s[128];
    __shared__ float lng_s[ND];
    __shared__ float lnb_s[ND];

    if (tid < 128) km_s[tid] = (float)Mp[b*NT + t0 + tid];
    if (DO_LN && tid >= 128 && tid < 192) {
        lng_s[tid-128] = Gp[tid-128];
        lnb_s[tid-128] = Lp[tid-128];
    }

    const float* Wr = Wp + (h*ND)*NE;
    const float* Xb = Xp + b*NE*NT;

    auto prefetch = [&](int c, int s) {
        const int k0 = c*32;
        #pragma unroll
        for (int l = 0; l < 2; l++) {
            int idx = tid + 256*l; int r = idx >> 3, c4 = idx & 7;
            cp16(wtb + s*WCH + r*WT_S + c4*4, Wr + r*NE + k0 + c4*4);
        }
        #pragma unroll
        for (int l = 0; l < 4; l++) {
            int idx = tid + 256*l; int r = idx >> 5, c4 = idx & 31;
            cp16(xtb + s*XCH + r*XT_S + c4*4, Xb + (k0+r)*NT + t0 + c4*4);
        }
    };

    prefetch(0, 0);
    cp_commit();

    float acc[8][4];
    #pragma unroll
    for (int n = 0; n < 8; n++)
        #pragma unroll
        for (int j = 0; j < 4; j++) acc[n][j] = 0.f;

    for (int c = 0; c < 16; c++) {
        const int cur = c & 1;
        cp_wait0();
        __syncthreads();
        if (c + 1 < 16) { prefetch(c+1, cur^1); cp_commit(); }

        const float* wt = wtb + cur*WCH;
        const float* xt = xtb + cur*XCH;
        #pragma unroll
        for (int dc = 0; dc < 4; dc++) {
            const int kk = dc*8;
            unsigned a0 = tf32u(wt[(wm*16+g  )*WT_S + kk + t4]);
            unsigned a1 = tf32u(wt[(wm*16+g+8)*WT_S + kk + t4]);
            unsigned a2 = tf32u(wt[(wm*16+g  )*WT_S + kk + t4 + 4]);
            unsigned a3 = tf32u(wt[(wm*16+g+8)*WT_S + kk + t4 + 4]);
            #pragma unroll
            for (int n = 0; n < 8; n++) {
                unsigned b0 = tf32u(xt[(kk+t4  )*XT_S + wn*64 + n*8 + g]);
                unsigned b1 = tf32u(xt[(kk+t4+4)*XT_S + wn*64 + n*8 + g]);
                mma_tf32(acc[n], a0, a1, a2, a3, b0, b1);
            }
        }
    }

    const float bv0 = Bp[h*ND + wm*16 + g];
    const float bv1 = Bp[h*ND + wm*16 + g + 8];

    if (!DO_LN) {
        float* o = Op + b*NE*NT + (h*ND)*NT + t0;
        #pragma unroll
        for (int n = 0; n < 8; n++) {
            const int cc = wn*64 + n*8 + 2*t4;
            const float m0 = km_s[cc], m1 = km_s[cc+1];
            *(float2*)(o + (wm*16+g  )*NT + cc) = make_float2(acc[n][0]*m0+bv0, acc[n][1]*m1+bv0);
            *(float2*)(o + (wm*16+g+8)*NT + cc) = make_float2(acc[n][2]*m0+bv1, acc[n][3]*m1+bv1);
        }
    } else {
        __syncthreads();   // done reading pipeline buffers; reuse psm as [64][136] tile
        #pragma unroll
        for (int n = 0; n < 8; n++) {
            const int cc = wn*64 + n*8 + 2*t4;
            const float m0 = km_s[cc], m1 = km_s[cc+1];
            *(float2*)(psm + (wm*16+g  )*XT_S + cc) = make_float2(acc[n][0]*m0+bv0, acc[n][1]*m1+bv0);
            *(float2*)(psm + (wm*16+g+8)*XT_S + cc) = make_float2(acc[n][2]*m0+bv1, acc[n][3]*m1+bv1);
        }
        __syncthreads();
        if (tid < 128) {
            const int cc = tid;
            float s = 0.f;
            #pragma unroll 16
            for (int d = 0; d < 64; d++) s += psm[d*XT_S + cc];
            const float mu = s * (1.0f/64.0f);
            float s2 = 0.f;
            #pragma unroll 16
            for (int d = 0; d < 64; d++) { float dd = psm[d*XT_S + cc] - mu; s2 += dd*dd; }
            const float rstd = rsqrtf(s2*(1.0f/64.0f) + EPSV);
            float* o = Op + b*NE*NT + (h*ND)*NT + t0 + cc;
            #pragma unroll 8
            for (int d = 0; d < 64; d++)
                o[d*NT] = (psm[d*XT_S + cc] - mu)*rstd*lng_s[d] + lnb_s[d];
        }
    }
}

// ---------------- 3) flash attention: tf32 mma + cp.async 2-stage, BQ=128 ----------------
// grid (T/128, H, B), 256 thr = 8 warps; warp w owns q-rows [w*16, w*16+16).
#define KS_S 68
#define ATILE (64*KS_S)
#define ATTN_SMEM ((4*ATILE)*4 + 2*64*4)

__global__ void __launch_bounds__(256, 2) attn_mma_kernel(
        const float* __restrict__ q, const float* __restrict__ k, const float* __restrict__ v,
        const int* __restrict__ qmask, const int* __restrict__ kmask,
        float* __restrict__ out) {
    extern __shared__ float sm[];
    float* ksb = sm;                       // [2][64*68]
    float* vsb = sm + 2*ATILE;             // [2][64*68]
    int*   kmb = (int*)(sm + 4*ATILE);     // [2][64]

    const int t0 = blockIdx.x * 128;
    const int h = blockIdx.y, b = blockIdx.z;
    const int tid = threadIdx.x;
    const int lane = tid & 31;
    const int w = tid >> 5;
    const int g = lane >> 2;
    const int t4 = lane & 3;
    const int w16 = w * 16;
    const int base = (b*NE + h*ND)*NT;

    // ---- stage Q (tf32) through ksb region, stride 136, extract fragments ----
    #pragma unroll
    for (int l = 0; l < 8; l++) {
        int idx = tid + 256*l; int d = idx >> 5; int c4 = idx & 31;
        float4 val = *(const float4*)(q + base + d*NT + t0 + c4*4);
        *(float4*)(ksb + d*136 + c4*4) =
            make_float4(to_tf32(val.x), to_tf32(val.y), to_tf32(val.z), to_tf32(val.w));
    }
    __syncthreads();
    unsigned qa[8][4];
    #pragma unroll
    for (int dc = 0; dc < 8; dc++) {
        const int d0 = dc*8;
        qa[dc][0] = __float_as_uint(ksb[(d0+t4  )*136 + w16 + g]);
        qa[dc][1] = __float_as_uint(ksb[(d0+t4  )*136 + w16 + g + 8]);
        qa[dc][2] = __float_as_uint(ksb[(d0+t4+4)*136 + w16 + g]);
        qa[dc][3] = __float_as_uint(ksb[(d0+t4+4)*136 + w16 + g + 8]);
    }
    __syncthreads();

    auto prefetch = [&](int kt, int s) {
        const int tk0 = kt*64;
        #pragma unroll
        for (int l = 0; l < 4; l++) {
            int idx = tid + 256*l; int d = idx >> 4; int c4 = idx & 15;
            cp16(ksb + s*ATILE + d*KS_S + c4*4, k + base + d*NT + tk0 + c4*4);
            cp16(vsb + s*ATILE + d*KS_S + c4*4, v + base + d*NT + tk0 + c4*4);
        }
        if (tid < 16) cp16(kmb + s*64 + tid*4, kmask + b*NT + tk0 + tid*4);
    };

    prefetch(0, 0);
    cp_commit();

    float m0 = -1e30f, m1 = -1e30f, l0 = 0.f, l1 = 0.f;
    float oacc[8][4];
    #pragma unroll
    for (int n = 0; n < 8; n++)
        #pragma unroll
        for (int j = 0; j < 4; j++) oacc[n][j] = 0.f;

    const int srcA = (lane & ~3) | (t4 >> 1);
    const int srcB = srcA + 2;
    const bool odd = (t4 & 1);

    for (int kt = 0; kt < NT/64; kt++) {
        const int cur = kt & 1;
        cp_wait0();
        __syncthreads();
        if (kt + 1 < NT/64) { prefetch(kt+1, cur^1); cp_commit(); }

        const float* ks = ksb + cur*ATILE;
        const float* vs = vsb + cur*ATILE;
        const int*   km = kmb + cur*64;

        // ---- S = Q^T K ----
        float sf[8][4];
        #pragma unroll
        for (int n = 0; n < 8; n++)
            #pragma unroll
            for (int j = 0; j < 4; j++) sf[n][j] = 0.f;
        #pragma unroll
        for (int dc = 0; dc < 8; dc++) {
            const int d0 = dc*8;
            #pragma unroll
            for (int n = 0; n < 8; n++) {
                unsigned b0 = tf32u(ks[(d0+t4  )*KS_S + n*8 + g]);
                unsigned b1 = tf32u(ks[(d0+t4+4)*KS_S + n*8 + g]);
                mma_tf32(sf[n], qa[dc][0], qa[dc][1], qa[dc][2], qa[dc][3], b0, b1);
            }
        }

        // ---- mask + scale ----
        #pragma unroll
        for (int n = 0; n < 8; n++) {
            const int km0 = km[n*8 + 2*t4];
            const int km1 = km[n*8 + 2*t4 + 1];
            sf[n][0] = km0 ? sf[n][0]*INV_SCALE : -1e9f;
            sf[n][1] = km1 ? sf[n][1]*INV_SCALE : -1e9f;
            sf[n][2] = km0 ? sf[n][2]*INV_SCALE : -1e9f;
            sf[n][3] = km1 ? sf[n][3]*INV_SCALE : -1e9f;
        }

        // ---- online softmax ----
        float mx0 = -1e30f, mx1 = -1e30f;
        #pragma unroll
        for (int n = 0; n < 8; n++) {
            mx0 = fmaxf(mx0, fmaxf(sf[n][0], sf[n][1]));
            mx1 = fmaxf(mx1, fmaxf(sf[n][2], sf[n][3]));
        }
        mx0 = fmaxf(mx0, __shfl_xor_sync(0xffffffffu, mx0, 1));
        mx0 = fmaxf(mx0, __shfl_xor_sync(0xffffffffu, mx0, 2));
        mx1 = fmaxf(mx1, __shfl_xor_sync(0xffffffffu, mx1, 1));
        mx1 = fmaxf(mx1, __shfl_xor_sync(0xffffffffu, mx1, 2));

        const float mn0 = fmaxf(m0, mx0);
        const float mn1 = fmaxf(m1, mx1);
        const float c0 = __expf(m0 - mn0);
        const float c1 = __expf(m1 - mn1);
        m0 = mn0; m1 = mn1;

        unsigned pu0[8], pu1[8], pu2[8], pu3[8];
        float rs0 = 0.f, rs1 = 0.f;
        #pragma unroll
        for (int n = 0; n < 8; n++) {
            float p0 = __expf(sf[n][0] - mn0);
            float p1 = __expf(sf[n][1] - mn0);
            float p2 = __expf(sf[n][2] - mn1);
            float p3 = __expf(sf[n][3] - mn1);
            rs0 += p0 + p1; rs1 += p2 + p3;
            pu0[n] = tf32u(p0);
            pu1[n] = tf32u(p1);
            pu2[n] = tf32u(p2);
            pu3[n] = tf32u(p3);
        }
        rs0 += __shfl_xor_sync(0xffffffffu, rs0, 1);
        rs0 += __shfl_xor_sync(0xffffffffu, rs0, 2);
        rs1 += __shfl_xor_sync(0xffffffffu, rs1, 1);
        rs1 += __shfl_xor_sync(0xffffffffu, rs1, 2);
        l0 = l0*c0 + rs0;
        l1 = l1*c1 + rs1;
        #pragma unroll
        for (int n = 0; n < 8; n++) {
            oacc[n][0] *= c0; oacc[n][1] *= c0;
            oacc[n][2] *= c1; oacc[n][3] *= c1;
        }

        // ---- O += P @ V^T ; A fragment via quad shuffles ----
        #pragma unroll
        for (int kc = 0; kc < 8; kc++) {
            unsigned e0 = __shfl_sync(0xffffffffu, pu0[kc], srcA);
            unsigned e1 = __shfl_sync(0xffffffffu, pu1[kc], srcA);
            unsigned a0 = odd ? e1 : e0;
            unsigned f0 = __shfl_sync(0xffffffffu, pu2[kc], srcA);
            unsigned f1 = __shfl_sync(0xffffffffu, pu3[kc], srcA);
            unsigned a1 = odd ? f1 : f0;
            e0 = __shfl_sync(0xffffffffu, pu0[kc], srcB);
            e1 = __shfl_sync(0xffffffffu, pu1[kc], srcB);
            unsigned a2 = odd ? e1 : e0;
            f0 = __shfl_sync(0xffffffffu, pu2[kc], srcB);
            f1 = __shfl_sync(0xffffffffu, pu3[kc], srcB);
            unsigned a3 = odd ? f1 : f0;
            const int k0c = kc*8;
            #pragma unroll
            for (int n = 0; n < 8; n++) {
                unsigned b0 = tf32u(vs[(n*8+g)*KS_S + k0c + t4]);
                unsigned b1 = tf32u(vs[(n*8+g)*KS_S + k0c + t4 + 4]);
                mma_tf32(oacc[n], a0, a1, a2, a3, b0, b1);
            }
        }
    }

    // ---- epilogue ----
    const int qrow0 = t0 + w16 + g;
    const int qrow1 = qrow0 + 8;
    const float sel0 = (qmask[b*NT + qrow0] != 0) ? (1.0f / l0) : 0.f;
    const float sel1 = (qmask[b*NT + qrow1] != 0) ? (1.0f / l1) : 0.f;
    #pragma unroll
    for (int n = 0; n < 8; n++) {
        const int d0 = n*8 + 2*t4;
        out[base + (d0  )*NT + qrow0] = oacc[n][0] * sel0;
        out[base + (d0+1)*NT + qrow0] = oacc[n][1] * sel0;
        out[base + (d0  )*NT + qrow1] = oacc[n][2] * sel1;
        out[base + (d0+1)*NT + qrow1] = oacc[n][3] * sel1;
    }
}

// ---------------- launch ----------------
extern "C" void kernel_launch(void* const* d_in, const int* in_sizes, int n_in,
                              void* d_out, int out_size) {
    (void)in_sizes; (void)n_in; (void)out_size;
    const float* q   = (const float*)d_in[0];
    const float* k   = (const float*)d_in[1];
    const float* v   = (const float*)d_in[2];
    const int*   qm  = (const int*)d_in[3];
    const int*   km  = (const int*)d_in[4];
    const int*   vm  = (const int*)d_in[5];
    const float* Wq  = (const float*)d_in[6];
    const float* bq  = (const float*)d_in[7];
    const float* Wk  = (const float*)d_in[8];
    const float* bk  = (const float*)d_in[9];
    const float* Wv  = (const float*)d_in[10];
    const float* bv  = (const float*)d_in[11];
    const float* Wo  = (const float*)d_in[12];
    const float* bo  = (const float*)d_in[13];
    const float* gq  = (const float*)d_in[14];
    const float* bgq = (const float*)d_in[15];
    const float* gk  = (const float*)d_in[16];
    const float* bgk = (const float*)d_in[17];
    const float* gv  = (const float*)d_in[18];
    const float* bgv = (const float*)d_in[19];

    float *wn, *pq, *pk, *pv, *pa;
    cudaGetSymbolAddress((void**)&wn, g_Wn);
    cudaGetSymbolAddress((void**)&pq, g_q);
    cudaGetSymbolAddress((void**)&pk, g_k);
    cudaGetSymbolAddress((void**)&pv, g_v);
    cudaGetSymbolAddress((void**)&pa, g_att);

    cudaFuncSetAttribute(proj_mma_kernel<true>,  cudaFuncAttributeMaxDynamicSharedMemorySize, PROJ_SMEM);
    cudaFuncSetAttribute(proj_mma_kernel<false>, cudaFuncAttributeMaxDynamicSharedMemorySize, PROJ_SMEM);
    cudaFuncSetAttribute(attn_mma_kernel,        cudaFuncAttributeMaxDynamicSharedMemorySize, ATTN_SMEM);

    std_weights_kernel<<<dim3(NE, 4), 128>>>(Wq, Wk, Wv, Wo);

    ProjArgs A;
    A.s[0] = { q, qm, wn + 0*NE*NE, bq, gq, bgq, pq };
    A.s[1] = { k, km, wn + 1*NE*NE, bk, gk, bgk, pk };
    A.s[2] = { v, vm, wn + 2*NE*NE, bv, gv, bgv, pv };
    proj_mma_kernel<true><<<dim3(NT/128, NH, 6), 256, PROJ_SMEM>>>(A);

    attn_mma_kernel<<<dim3(NT/128, NH, NB), 256, ATTN_SMEM>>>(pq, pk, pv, qm, km, pa);

    ProjArgs Ao;
    Ao.s[0] = { pa, qm, wn + 3*NE*NE, bo, nullptr, nullptr, (float*)d_out };
    Ao.s[1] = Ao.s[0];
    Ao.s[2] = Ao.s[0];
    proj_mma_kernel<false><<<dim3(NT/128, NH, 2), 256, PROJ_SMEM>>>(Ao);
}

// round 6
// speedup vs baseline: 3.2017x; 1.1018x over previous
#include <cuda_runtime.h>
#include <math.h>

#define NB 2
#define NE 512
#define NH 8
#define ND 64
#define NT 2048
#define EPSV 1e-5f
// exp(s/181) = ex2(s * log2(e)/181)
#define EXP_C (1.44269504088896341f/181.0f)

// ---------------- scratch (device globals: allocation-free) ----------------
__device__ float g_Wn[4*NE*NE];   // tf32-rounded standardized weights
__device__ float g_q[NB*NE*NT];   // tf32-rounded
__device__ float g_k[NB*NE*NT];   // tf32-rounded
__device__ float g_v[NB*NE*NT];   // tf32-rounded
__device__ float g_att[NB*NE*NT]; // tf32-rounded

__device__ __forceinline__ float to_tf32(float x) {
    unsigned u;
    asm("cvt.rna.tf32.f32 %0, %1;" : "=r"(u) : "f"(x));
    return __uint_as_float(u);
}
__device__ __forceinline__ unsigned tf32u(float x) {
    unsigned u;
    asm("cvt.rna.tf32.f32 %0, %1;" : "=r"(u) : "f"(x));
    return u;
}
__device__ __forceinline__ float ex2a(float x) {
    float y;
    asm("ex2.approx.f32 %0, %1;" : "=f"(y) : "f"(x));
    return y;
}

__device__ __forceinline__ void mma_tf32(float* d,
        unsigned a0, unsigned a1, unsigned a2, unsigned a3,
        unsigned b0, unsigned b1) {
    asm volatile("mma.sync.aligned.m16n8k8.row.col.f32.tf32.tf32.f32 "
        "{%0,%1,%2,%3}, {%4,%5,%6,%7}, {%8,%9}, {%0,%1,%2,%3};\n"
        : "+f"(d[0]), "+f"(d[1]), "+f"(d[2]), "+f"(d[3])
        : "r"(a0), "r"(a1), "r"(a2), "r"(a3), "r"(b0), "r"(b1));
}

__device__ __forceinline__ void cp16(void* dst, const void* src) {
    unsigned d = (unsigned)__cvta_generic_to_shared(dst);
    asm volatile("cp.async.ca.shared.global [%0], [%1], 16;" :: "r"(d), "l"(src));
}
__device__ __forceinline__ void cp_commit() { asm volatile("cp.async.commit_group;"); }
__device__ __forceinline__ void cp_wait0()  { asm volatile("cp.async.wait_group 0;"); }

// ---------------- 1) weight standardization (writes tf32-rounded) ----------------
__global__ void std_weights_kernel(const float* __restrict__ W0, const float* __restrict__ W1,
                                   const float* __restrict__ W2, const float* __restrict__ W3) {
    const float* Ws[4] = {W0, W1, W2, W3};
    const float* W = Ws[blockIdx.y];
    float* out = g_Wn + blockIdx.y * NE * NE;
    const int row = blockIdx.x;
    const int tid = threadIdx.x;

    float w[4];
    #pragma unroll
    for (int j = 0; j < 4; j++) w[j] = W[row*NE + tid + 128*j];

    __shared__ float red[4];
    float s = w[0]+w[1]+w[2]+w[3];
    #pragma unroll
    for (int o = 16; o > 0; o >>= 1) s += __shfl_down_sync(0xffffffffu, s, o);
    if ((tid & 31) == 0) red[tid >> 5] = s;
    __syncthreads();
    const float mu = (red[0]+red[1]+red[2]+red[3]) * (1.0f/NE);
    __syncthreads();

    float s2 = 0.f;
    #pragma unroll
    for (int j = 0; j < 4; j++) { float d = w[j]-mu; s2 += d*d; }
    #pragma unroll
    for (int o = 16; o > 0; o >>= 1) s2 += __shfl_down_sync(0xffffffffu, s2, o);
    if ((tid & 31) == 0) red[tid >> 5] = s2;
    __syncthreads();
    const float var = (red[0]+red[1]+red[2]+red[3]) * (1.0f/NE);
    const float rstd = rsqrtf(var + EPSV);
    #pragma unroll
    for (int j = 0; j < 4; j++) out[row*NE + tid + 128*j] = to_tf32((w[j]-mu)*rstd);
}

// ---------------- 2/4) projection GEMM: tf32 mma + cp.async 2-stage ----------------
struct ProjSet {
    const float* x; const int* mask; const float* wn; const float* bias;
    const float* lng; const float* lnb; float* out;
};
struct ProjArgs { ProjSet s[3]; };

#define WT_S 36
#define XT_S 136
#define WCH (64*WT_S)
#define XCH (32*XT_S)
#define PROJ_SMEM ((2*WCH + 2*XCH)*4)

// Block 256 thr = 8 warps: wm = wid&1 (m32 half), wn = wid>>1 (n32 quarter).
// CVT_B: x operand is raw fp32 (first projection); otherwise pre-rounded tf32.
template<bool DO_LN, bool CVT_B>
__global__ void __launch_bounds__(256) proj_mma_kernel(ProjArgs A) {
    const int which = blockIdx.z >> 1;
    const int b = blockIdx.z & 1;
    const float* __restrict__ Xp = A.s[which].x;
    const int*   __restrict__ Mp = A.s[which].mask;
    const float* __restrict__ Wp = A.s[which].wn;
    const float* __restrict__ Bp = A.s[which].bias;
    const float* __restrict__ Gp = A.s[which].lng;
    const float* __restrict__ Lp = A.s[which].lnb;
    float*       __restrict__ Op = A.s[which].out;

    const int h  = blockIdx.y;
    const int t0 = blockIdx.x * 128;
    const int tid = threadIdx.x;
    const int lane = tid & 31;
    const int wid = tid >> 5;
    const int wm = wid & 1, wn = wid >> 1;
    const int g = lane >> 2, t4 = lane & 3;

    extern __shared__ float psm[];
    float* wtb = psm;             // [2][64*36]
    float* xtb = psm + 2*WCH;     // [2][32*136]
    __shared__ float km_s[128];
    __shared__ float lng_s[ND];
    __shared__ float lnb_s[ND];

    if (tid < 128) km_s[tid] = (float)Mp[b*NT + t0 + tid];
    if (DO_LN && tid >= 128 && tid < 192) {
        lng_s[tid-128] = Gp[tid-128];
        lnb_s[tid-128] = Lp[tid-128];
    }

    const float* Wr = Wp + (h*ND)*NE;
    const float* Xb = Xp + b*NE*NT;

    auto prefetch = [&](int c, int s) {
        const int k0 = c*32;
        #pragma unroll
        for (int l = 0; l < 2; l++) {
            int idx = tid + 256*l; int r = idx >> 3, c4 = idx & 7;
            cp16(wtb + s*WCH + r*WT_S + c4*4, Wr + r*NE + k0 + c4*4);
        }
        #pragma unroll
        for (int l = 0; l < 4; l++) {
            int idx = tid + 256*l; int r = idx >> 5, c4 = idx & 31;
            cp16(xtb + s*XCH + r*XT_S + c4*4, Xb + (k0+r)*NT + t0 + c4*4);
        }
    };

    prefetch(0, 0);
    cp_commit();

    float acc[2][4][4];
    #pragma unroll
    for (int mt = 0; mt < 2; mt++)
        #pragma unroll
        for (int n = 0; n < 4; n++)
            #pragma unroll
            for (int j = 0; j < 4; j++) acc[mt][n][j] = 0.f;

    for (int c = 0; c < 16; c++) {
        const int cur = c & 1;
        cp_wait0();
        __syncthreads();
        if (c + 1 < 16) { prefetch(c+1, cur^1); cp_commit(); }

        const float* wt = wtb + cur*WCH;
        const float* xt = xtb + cur*XCH;
        #pragma unroll
        for (int dc = 0; dc < 4; dc++) {
            const int kk = dc*8;
            unsigned a[2][4];
            #pragma unroll
            for (int mt = 0; mt < 2; mt++) {
                const int r0 = wm*32 + mt*16;
                a[mt][0] = __float_as_uint(wt[(r0+g  )*WT_S + kk + t4]);
                a[mt][1] = __float_as_uint(wt[(r0+g+8)*WT_S + kk + t4]);
                a[mt][2] = __float_as_uint(wt[(r0+g  )*WT_S + kk + t4 + 4]);
                a[mt][3] = __float_as_uint(wt[(r0+g+8)*WT_S + kk + t4 + 4]);
            }
            #pragma unroll
            for (int n = 0; n < 4; n++) {
                const int col = wn*32 + n*8 + g;
                float x0 = xt[(kk+t4  )*XT_S + col];
                float x1 = xt[(kk+t4+4)*XT_S + col];
                unsigned b0 = CVT_B ? tf32u(x0) : __float_as_uint(x0);
                unsigned b1 = CVT_B ? tf32u(x1) : __float_as_uint(x1);
                #pragma unroll
                for (int mt = 0; mt < 2; mt++)
                    mma_tf32(acc[mt][n], a[mt][0], a[mt][1], a[mt][2], a[mt][3], b0, b1);
            }
        }
    }

    float bv[2][2];
    #pragma unroll
    for (int mt = 0; mt < 2; mt++) {
        bv[mt][0] = Bp[h*ND + wm*32 + mt*16 + g];
        bv[mt][1] = Bp[h*ND + wm*32 + mt*16 + g + 8];
    }

    if (!DO_LN) {
        float* o = Op + b*NE*NT + (h*ND)*NT + t0;
        #pragma unroll
        for (int mt = 0; mt < 2; mt++) {
            const int r0 = wm*32 + mt*16 + g;
            #pragma unroll
            for (int n = 0; n < 4; n++) {
                const int cc = wn*32 + n*8 + 2*t4;
                const float m0 = km_s[cc], m1 = km_s[cc+1];
                *(float2*)(o + (r0  )*NT + cc) =
                    make_float2(acc[mt][n][0]*m0 + bv[mt][0], acc[mt][n][1]*m1 + bv[mt][0]);
                *(float2*)(o + (r0+8)*NT + cc) =
                    make_float2(acc[mt][n][2]*m0 + bv[mt][1], acc[mt][n][3]*m1 + bv[mt][1]);
            }
        }
    } else {
        __syncthreads();   // done with pipeline buffers; reuse psm as [64][136] tile
        #pragma unroll
        for (int mt = 0; mt < 2; mt++) {
            const int r0 = wm*32 + mt*16 + g;
            #pragma unroll
            for (int n = 0; n < 4; n++) {
                const int cc = wn*32 + n*8 + 2*t4;
                const float m0 = km_s[cc], m1 = km_s[cc+1];
                *(float2*)(psm + (r0  )*XT_S + cc) =
                    make_float2(acc[mt][n][0]*m0 + bv[mt][0], acc[mt][n][1]*m1 + bv[mt][0]);
                *(float2*)(psm + (r0+8)*XT_S + cc) =
                    make_float2(acc[mt][n][2]*m0 + bv[mt][1], acc[mt][n][3]*m1 + bv[mt][1]);
            }
        }
        __syncthreads();
        if (tid < 128) {
            const int cc = tid;
            float s = 0.f;
            #pragma unroll 16
            for (int d = 0; d < 64; d++) s += psm[d*XT_S + cc];
            const float mu = s * (1.0f/64.0f);
            float s2 = 0.f;
            #pragma unroll 16
            for (int d = 0; d < 64; d++) { float dd = psm[d*XT_S + cc] - mu; s2 += dd*dd; }
            const float rstd = rsqrtf(s2*(1.0f/64.0f) + EPSV);
            float* o = Op + b*NE*NT + (h*ND)*NT + t0 + cc;
            #pragma unroll 8
            for (int d = 0; d < 64; d++)
                o[d*NT] = to_tf32((psm[d*XT_S + cc] - mu)*rstd*lng_s[d] + lnb_s[d]);
        }
    }
}

// ---------------- 3) flash attention: tf32 mma, no-max softmax, raw tf32 loads ----------------
// grid (T/128, H, B), 256 thr = 8 warps; warp w owns q-rows [w*16, w*16+16).
// Scores bounded: per-head LN => |q|,|k| <= 8 => |q.k|/181 <= 0.354. exp never overflows.
#define KS_S 72
#define ATILE (64*KS_S)
#define ATTN_SMEM ((4*ATILE)*4 + 2*64*4)

__global__ void __launch_bounds__(256, 2) attn_mma_kernel(
        const float* __restrict__ q, const float* __restrict__ k, const float* __restrict__ v,
        const int* __restrict__ qmask, const int* __restrict__ kmask,
        float* __restrict__ out) {
    extern __shared__ float sm[];
    float* ksb = sm;                       // [2][64*72]
    float* vsb = sm + 2*ATILE;             // [2][64*72]
    int*   kmb = (int*)(sm + 4*ATILE);     // [2][64]

    const int t0 = blockIdx.x * 128;
    const int h = blockIdx.y, b = blockIdx.z;
    const int tid = threadIdx.x;
    const int lane = tid & 31;
    const int w = tid >> 5;
    const int g = lane >> 2;
    const int t4 = lane & 3;
    const int w16 = w * 16;
    const int base = (b*NE + h*ND)*NT;

    // ---- stage Q (already tf32) through ksb, stride 136, extract fragments ----
    #pragma unroll
    for (int l = 0; l < 8; l++) {
        int idx = tid + 256*l; int d = idx >> 5; int c4 = idx & 31;
        *(float4*)(ksb + d*136 + c4*4) = *(const float4*)(q + base + d*NT + t0 + c4*4);
    }
    __syncthreads();
    unsigned qa[8][4];
    #pragma unroll
    for (int dc = 0; dc < 8; dc++) {
        const int d0 = dc*8;
        qa[dc][0] = __float_as_uint(ksb[(d0+t4  )*136 + w16 + g]);
        qa[dc][1] = __float_as_uint(ksb[(d0+t4  )*136 + w16 + g + 8]);
        qa[dc][2] = __float_as_uint(ksb[(d0+t4+4)*136 + w16 + g]);
        qa[dc][3] = __float_as_uint(ksb[(d0+t4+4)*136 + w16 + g + 8]);
    }
    __syncthreads();

    auto prefetch = [&](int kt, int s) {
        const int tk0 = kt*64;
        #pragma unroll
        for (int l = 0; l < 4; l++) {
            int idx = tid + 256*l; int d = idx >> 4; int c4 = idx & 15;
            cp16(ksb + s*ATILE + d*KS_S + c4*4, k + base + d*NT + tk0 + c4*4);
            cp16(vsb + s*ATILE + d*KS_S + c4*4, v + base + d*NT + tk0 + c4*4);
        }
        if (tid < 16) cp16(kmb + s*64 + tid*4, kmask + b*NT + tk0 + tid*4);
    };

    prefetch(0, 0);
    cp_commit();

    float rs0 = 0.f, rs1 = 0.f;
    float oacc[8][4];
    #pragma unroll
    for (int n = 0; n < 8; n++)
        #pragma unroll
        for (int j = 0; j < 4; j++) oacc[n][j] = 0.f;

    const int srcA = (lane & ~3) | (t4 >> 1);
    const int srcB = srcA + 2;
    const bool odd = (t4 & 1);

    for (int kt = 0; kt < NT/64; kt++) {
        const int cur = kt & 1;
        cp_wait0();
        __syncthreads();
        if (kt + 1 < NT/64) { prefetch(kt+1, cur^1); cp_commit(); }

        const float* ks = ksb + cur*ATILE;
        const float* vs = vsb + cur*ATILE;
        const int*   km = kmb + cur*64;

        // ---- S = Q^T K (raw tf32 operands) ----
        float sf[8][4];
        #pragma unroll
        for (int n = 0; n < 8; n++)
            #pragma unroll
            for (int j = 0; j < 4; j++) sf[n][j] = 0.f;
        #pragma unroll
        for (int dc = 0; dc < 8; dc++) {
            const int d0 = dc*8;
            #pragma unroll
            for (int n = 0; n < 8; n++) {
                unsigned b0 = __float_as_uint(ks[(d0+t4  )*KS_S + n*8 + g]);
                unsigned b1 = __float_as_uint(ks[(d0+t4+4)*KS_S + n*8 + g]);
                mma_tf32(sf[n], qa[dc][0], qa[dc][1], qa[dc][2], qa[dc][3], b0, b1);
            }
        }

        // ---- p = mask ? exp(s/181) : 0 ; no max tracking (scores bounded) ----
        unsigned pu0[8], pu1[8], pu2[8], pu3[8];
        #pragma unroll
        for (int n = 0; n < 8; n++) {
            const int km0 = km[n*8 + 2*t4];
            const int km1 = km[n*8 + 2*t4 + 1];
            float p0 = km0 ? ex2a(sf[n][0]*EXP_C) : 0.f;
            float p1 = km1 ? ex2a(sf[n][1]*EXP_C) : 0.f;
            float p2 = km0 ? ex2a(sf[n][2]*EXP_C) : 0.f;
            float p3 = km1 ? ex2a(sf[n][3]*EXP_C) : 0.f;
            rs0 += p0 + p1; rs1 += p2 + p3;
            pu0[n] = tf32u(p0);
            pu1[n] = tf32u(p1);
            pu2[n] = tf32u(p2);
            pu3[n] = tf32u(p3);
        }

        // ---- O += P @ V^T ; A fragment via quad shuffles ----
        #pragma unroll
        for (int kc = 0; kc < 8; kc++) {
            unsigned e0 = __shfl_sync(0xffffffffu, pu0[kc], srcA);
            unsigned e1 = __shfl_sync(0xffffffffu, pu1[kc], srcA);
            unsigned a0 = odd ? e1 : e0;
            unsigned f0 = __shfl_sync(0xffffffffu, pu2[kc], srcA);
            unsigned f1 = __shfl_sync(0xffffffffu, pu3[kc], srcA);
            unsigned a1 = odd ? f1 : f0;
            e0 = __shfl_sync(0xffffffffu, pu0[kc], srcB);
            e1 = __shfl_sync(0xffffffffu, pu1[kc], srcB);
            unsigned a2 = odd ? e1 : e0;
            f0 = __shfl_sync(0xffffffffu, pu2[kc], srcB);
            f1 = __shfl_sync(0xffffffffu, pu3[kc], srcB);
            unsigned a3 = odd ? f1 : f0;
            const int k0c = kc*8;
            #pragma unroll
            for (int n = 0; n < 8; n++) {
                unsigned b0 = __float_as_uint(vs[(n*8+g)*KS_S + k0c + t4]);
                unsigned b1 = __float_as_uint(vs[(n*8+g)*KS_S + k0c + t4 + 4]);
                mma_tf32(oacc[n], a0, a1, a2, a3, b0, b1);
            }
        }
    }

    // ---- final row-sum reduction (within quad) and epilogue ----
    rs0 += __shfl_xor_sync(0xffffffffu, rs0, 1);
    rs0 += __shfl_xor_sync(0xffffffffu, rs0, 2);
    rs1 += __shfl_xor_sync(0xffffffffu, rs1, 1);
    rs1 += __shfl_xor_sync(0xffffffffu, rs1, 2);

    const int qrow0 = t0 + w16 + g;
    const int qrow1 = qrow0 + 8;
    const float sel0 = (qmask[b*NT + qrow0] != 0) ? (1.0f / rs0) : 0.f;
    const float sel1 = (qmask[b*NT + qrow1] != 0) ? (1.0f / rs1) : 0.f;
    #pragma unroll
    for (int n = 0; n < 8; n++) {
        const int d0 = n*8 + 2*t4;
        out[base + (d0  )*NT + qrow0] = to_tf32(oacc[n][0] * sel0);
        out[base + (d0+1)*NT + qrow0] = to_tf32(oacc[n][1] * sel0);
        out[base + (d0  )*NT + qrow1] = to_tf32(oacc[n][2] * sel1);
        out[base + (d0+1)*NT + qrow1] = to_tf32(oacc[n][3] * sel1);
    }
}

// ---------------- launch ----------------
extern "C" void kernel_launch(void* const* d_in, const int* in_sizes, int n_in,
                              void* d_out, int out_size) {
    (void)in_sizes; (void)n_in; (void)out_size;
    const float* q   = (const float*)d_in[0];
    const float* k   = (const float*)d_in[1];
    const float* v   = (const float*)d_in[2];
    const int*   qm  = (const int*)d_in[3];
    const int*   km  = (const int*)d_in[4];
    const int*   vm  = (const int*)d_in[5];
    const float* Wq  = (const float*)d_in[6];
    const float* bq  = (const float*)d_in[7];
    const float* Wk  = (const float*)d_in[8];
    const float* bk  = (const float*)d_in[9];
    const float* Wv  = (const float*)d_in[10];
    const float* bv  = (const float*)d_in[11];
    const float* Wo  = (const float*)d_in[12];
    const float* bo  = (const float*)d_in[13];
    const float* gq  = (const float*)d_in[14];
    const float* bgq = (const float*)d_in[15];
    const float* gk  = (const float*)d_in[16];
    const float* bgk = (const float*)d_in[17];
    const float* gv  = (const float*)d_in[18];
    const float* bgv = (const float*)d_in[19];

    float *wn, *pq, *pk, *pv, *pa;
    cudaGetSymbolAddress((void**)&wn, g_Wn);
    cudaGetSymbolAddress((void**)&pq, g_q);
    cudaGetSymbolAddress((void**)&pk, g_k);
    cudaGetSymbolAddress((void**)&pv, g_v);
    cudaGetSymbolAddress((void**)&pa, g_att);

    cudaFuncSetAttribute((const void*)proj_mma_kernel<true, true>,
                         cudaFuncAttributeMaxDynamicSharedMemorySize, PROJ_SMEM);
    cudaFuncSetAttribute((const void*)proj_mma_kernel<false, false>,
                         cudaFuncAttributeMaxDynamicSharedMemorySize, PROJ_SMEM);
    cudaFuncSetAttribute((const void*)attn_mma_kernel,
                         cudaFuncAttributeMaxDynamicSharedMemorySize, ATTN_SMEM);

    std_weights_kernel<<<dim3(NE, 4), 128>>>(Wq, Wk, Wv, Wo);

    ProjArgs A;
    A.s[0] = { q, qm, wn + 0*NE*NE, bq, gq, bgq, pq };
    A.s[1] = { k, km, wn + 1*NE*NE, bk, gk, bgk, pk };
    A.s[2] = { v, vm, wn + 2*NE*NE, bv, gv, bgv, pv };
    proj_mma_kernel<true, true><<<dim3(NT/128, NH, 6), 256, PROJ_SMEM>>>(A);

    attn_mma_kernel<<<dim3(NT/128, NH, NB), 256, ATTN_SMEM>>>(pq, pk, pv, qm, km, pa);

    ProjArgs Ao;
    Ao.s[0] = { pa, qm, wn + 3*NE*NE, bo, nullptr, nullptr, (float*)d_out };
    Ao.s[1] = Ao.s[0];
    Ao.s[2] = Ao.s[0];
    proj_mma_kernel<false, false><<<dim3(NT/128, NH, 2), 256, PROJ_SMEM>>>(Ao);
}

// round 7
// speedup vs baseline: 4.9834x; 1.5565x over previous
#include <cuda_runtime.h>
#include <cuda_fp16.h>
#include <math.h>

#define NB 2
#define NE 512
#define NH 8
#define ND 64
#define NT 2048
#define EPSV 1e-5f
// exp(s/181) = ex2(s * log2(e)/181)
#define EXP_C (1.44269504088896341f/181.0f)

// ---------------- scratch (device globals: allocation-free) ----------------
__device__ float  g_Wn[4*NE*NE];        // tf32-rounded standardized weights
__device__ __half g_qh[NB*NH*NT*ND];    // Q transposed: [b][h][t][d] half
__device__ __half g_kh[NB*NH*NT*ND];    // K transposed: [b][h][t][d] half
__device__ __half g_vh[NB*NE*NT];       // V: [b][e][t] half
__device__ float  g_att[NB*NE*NT];      // attention out, tf32-rounded fp32

__device__ __forceinline__ float to_tf32(float x) {
    unsigned u;
    asm("cvt.rna.tf32.f32 %0, %1;" : "=r"(u) : "f"(x));
    return __uint_as_float(u);
}
__device__ __forceinline__ float ex2a(float x) {
    float y;
    asm("ex2.approx.f32 %0, %1;" : "=f"(y) : "f"(x));
    return y;
}
// pack two fp32 -> half2 (lo = first arg)
__device__ __forceinline__ unsigned packh2(float lo, float hi) {
    unsigned r;
    asm("cvt.rn.f16x2.f32 %0, %1, %2;" : "=r"(r) : "f"(hi), "f"(lo));
    return r;
}

__device__ __forceinline__ void mma_tf32(float* d,
        unsigned a0, unsigned a1, unsigned a2, unsigned a3,
        unsigned b0, unsigned b1) {
    asm volatile("mma.sync.aligned.m16n8k8.row.col.f32.tf32.tf32.f32 "
        "{%0,%1,%2,%3}, {%4,%5,%6,%7}, {%8,%9}, {%0,%1,%2,%3};\n"
        : "+f"(d[0]), "+f"(d[1]), "+f"(d[2]), "+f"(d[3])
        : "r"(a0), "r"(a1), "r"(a2), "r"(a3), "r"(b0), "r"(b1));
}
__device__ __forceinline__ void mma_f16(float* d,
        unsigned a0, unsigned a1, unsigned a2, unsigned a3,
        unsigned b0, unsigned b1) {
    asm volatile("mma.sync.aligned.m16n8k16.row.col.f32.f16.f16.f32 "
        "{%0,%1,%2,%3}, {%4,%5,%6,%7}, {%8,%9}, {%0,%1,%2,%3};\n"
        : "+f"(d[0]), "+f"(d[1]), "+f"(d[2]), "+f"(d[3])
        : "r"(a0), "r"(a1), "r"(a2), "r"(a3), "r"(b0), "r"(b1));
}

__device__ __forceinline__ void cp16(void* dst, const void* src) {
    unsigned d = (unsigned)__cvta_generic_to_shared(dst);
    asm volatile("cp.async.ca.shared.global [%0], [%1], 16;" :: "r"(d), "l"(src));
}
__device__ __forceinline__ void cp_commit() { asm volatile("cp.async.commit_group;"); }
__device__ __forceinline__ void cp_wait0()  { asm volatile("cp.async.wait_group 0;"); }

// ---------------- 1) weight standardization (writes tf32-rounded) ----------------
__global__ void std_weights_kernel(const float* __restrict__ W0, const float* __restrict__ W1,
                                   const float* __restrict__ W2, const float* __restrict__ W3) {
    const float* Ws[4] = {W0, W1, W2, W3};
    const float* W = Ws[blockIdx.y];
    float* out = g_Wn + blockIdx.y * NE * NE;
    const int row = blockIdx.x;
    const int tid = threadIdx.x;

    float w[4];
    #pragma unroll
    for (int j = 0; j < 4; j++) w[j] = W[row*NE + tid + 128*j];

    __shared__ float red[4];
    float s = w[0]+w[1]+w[2]+w[3];
    #pragma unroll
    for (int o = 16; o > 0; o >>= 1) s += __shfl_down_sync(0xffffffffu, s, o);
    if ((tid & 31) == 0) red[tid >> 5] = s;
    __syncthreads();
    const float mu = (red[0]+red[1]+red[2]+red[3]) * (1.0f/NE);
    __syncthreads();

    float s2 = 0.f;
    #pragma unroll
    for (int j = 0; j < 4; j++) { float d = w[j]-mu; s2 += d*d; }
    #pragma unroll
    for (int o = 16; o > 0; o >>= 1) s2 += __shfl_down_sync(0xffffffffu, s2, o);
    if ((tid & 31) == 0) red[tid >> 5] = s2;
    __syncthreads();
    const float var = (red[0]+red[1]+red[2]+red[3]) * (1.0f/NE);
    const float rstd = rsqrtf(var + EPSV);
    #pragma unroll
    for (int j = 0; j < 4; j++) out[row*NE + tid + 128*j] = to_tf32((w[j]-mu)*rstd);
}

// ---------------- 2/4) projection GEMM: tf32 mma + cp.async 2-stage ----------------
// mode 1: LN + transposed half out [b][h][t][64]  (Q, K)
// mode 2: LN + half out [b][e][t]                 (V)
// mode 0 (!DO_LN): fp32 out [b][e][t]             (final output)
struct ProjSet {
    const float* x; const int* mask; const float* wn; const float* bias;
    const float* lng; const float* lnb; void* out; int mode;
};
struct ProjArgs { ProjSet s[3]; };

#define WT_S 36
#define XT_S 136
#define WCH (64*WT_S)
#define XCH (32*XT_S)
#define PROJ_SMEM ((2*WCH + 2*XCH)*4)

template<bool DO_LN, bool CVT_B>
__global__ void __launch_bounds__(256) proj_mma_kernel(ProjArgs A) {
    const int which = blockIdx.z >> 1;
    const int b = blockIdx.z & 1;
    const float* __restrict__ Xp = A.s[which].x;
    const int*   __restrict__ Mp = A.s[which].mask;
    const float* __restrict__ Wp = A.s[which].wn;
    const float* __restrict__ Bp = A.s[which].bias;
    const float* __restrict__ Gp = A.s[which].lng;
    const float* __restrict__ Lp = A.s[which].lnb;
    void*        __restrict__ Op = A.s[which].out;

    const int h  = blockIdx.y;
    const int t0 = blockIdx.x * 128;
    const int tid = threadIdx.x;
    const int lane = tid & 31;
    const int wid = tid >> 5;
    const int wm = wid & 1, wn = wid >> 1;
    const int g = lane >> 2, t4 = lane & 3;

    extern __shared__ float psm[];
    float* wtb = psm;             // [2][64*36]
    float* xtb = psm + 2*WCH;     // [2][32*136]
    __shared__ float km_s[128];
    __shared__ float lng_s[ND];
    __shared__ float lnb_s[ND];

    if (tid < 128) km_s[tid] = (float)Mp[b*NT + t0 + tid];
    if (DO_LN && tid >= 128 && tid < 192) {
        lng_s[tid-128] = Gp[tid-128];
        lnb_s[tid-128] = Lp[tid-128];
    }

    const float* Wr = Wp + (h*ND)*NE;
    const float* Xb = Xp + b*NE*NT;

    auto prefetch = [&](int c, int s) {
        const int k0 = c*32;
        #pragma unroll
        for (int l = 0; l < 2; l++) {
            int idx = tid + 256*l; int r = idx >> 3, c4 = idx & 7;
            cp16(wtb + s*WCH + r*WT_S + c4*4, Wr + r*NE + k0 + c4*4);
        }
        #pragma unroll
        for (int l = 0; l < 4; l++) {
            int idx = tid + 256*l; int r = idx >> 5, c4 = idx & 31;
            cp16(xtb + s*XCH + r*XT_S + c4*4, Xb + (k0+r)*NT + t0 + c4*4);
        }
    };

    prefetch(0, 0);
    cp_commit();

    float acc[2][4][4];
    #pragma unroll
    for (int mt = 0; mt < 2; mt++)
        #pragma unroll
        for (int n = 0; n < 4; n++)
            #pragma unroll
            for (int j = 0; j < 4; j++) acc[mt][n][j] = 0.f;

    for (int c = 0; c < 16; c++) {
        const int cur = c & 1;
        cp_wait0();
        __syncthreads();
        if (c + 1 < 16) { prefetch(c+1, cur^1); cp_commit(); }

        const float* wt = wtb + cur*WCH;
        const float* xt = xtb + cur*XCH;
        #pragma unroll
        for (int dc = 0; dc < 4; dc++) {
            const int kk = dc*8;
            unsigned a[2][4];
            #pragma unroll
            for (int mt = 0; mt < 2; mt++) {
                const int r0 = wm*32 + mt*16;
                a[mt][0] = __float_as_uint(wt[(r0+g  )*WT_S + kk + t4]);
                a[mt][1] = __float_as_uint(wt[(r0+g+8)*WT_S + kk + t4]);
                a[mt][2] = __float_as_uint(wt[(r0+g  )*WT_S + kk + t4 + 4]);
                a[mt][3] = __float_as_uint(wt[(r0+g+8)*WT_S + kk + t4 + 4]);
            }
            #pragma unroll
            for (int n = 0; n < 4; n++) {
                const int col = wn*32 + n*8 + g;
                float x0 = xt[(kk+t4  )*XT_S + col];
                float x1 = xt[(kk+t4+4)*XT_S + col];
                unsigned b0, b1;
                if (CVT_B) {
                    asm("cvt.rna.tf32.f32 %0, %1;" : "=r"(b0) : "f"(x0));
                    asm("cvt.rna.tf32.f32 %0, %1;" : "=r"(b1) : "f"(x1));
                } else {
                    b0 = __float_as_uint(x0);
                    b1 = __float_as_uint(x1);
                }
                #pragma unroll
                for (int mt = 0; mt < 2; mt++)
                    mma_tf32(acc[mt][n], a[mt][0], a[mt][1], a[mt][2], a[mt][3], b0, b1);
            }
        }
    }

    float bv[2][2];
    #pragma unroll
    for (int mt = 0; mt < 2; mt++) {
        bv[mt][0] = Bp[h*ND + wm*32 + mt*16 + g];
        bv[mt][1] = Bp[h*ND + wm*32 + mt*16 + g + 8];
    }

    if (!DO_LN) {
        float* o = (float*)Op + b*NE*NT + (h*ND)*NT + t0;
        #pragma unroll
        for (int mt = 0; mt < 2; mt++) {
            const int r0 = wm*32 + mt*16 + g;
            #pragma unroll
            for (int n = 0; n < 4; n++) {
                const int cc = wn*32 + n*8 + 2*t4;
                const float m0 = km_s[cc], m1 = km_s[cc+1];
                *(float2*)(o + (r0  )*NT + cc) =
                    make_float2(acc[mt][n][0]*m0 + bv[mt][0], acc[mt][n][1]*m1 + bv[mt][0]);
                *(float2*)(o + (r0+8)*NT + cc) =
                    make_float2(acc[mt][n][2]*m0 + bv[mt][1], acc[mt][n][3]*m1 + bv[mt][1]);
            }
        }
    } else {
        __syncthreads();   // done with pipeline buffers; reuse psm as [64][136] tile
        #pragma unroll
        for (int mt = 0; mt < 2; mt++) {
            const int r0 = wm*32 + mt*16 + g;
            #pragma unroll
            for (int n = 0; n < 4; n++) {
                const int cc = wn*32 + n*8 + 2*t4;
                const float m0 = km_s[cc], m1 = km_s[cc+1];
                *(float2*)(psm + (r0  )*XT_S + cc) =
                    make_float2(acc[mt][n][0]*m0 + bv[mt][0], acc[mt][n][1]*m1 + bv[mt][0]);
                *(float2*)(psm + (r0+8)*XT_S + cc) =
                    make_float2(acc[mt][n][2]*m0 + bv[mt][1], acc[mt][n][3]*m1 + bv[mt][1]);
            }
        }
        __syncthreads();
        if (tid < 128) {
            const int cc = tid;
            float s = 0.f;
            #pragma unroll 16
            for (int d = 0; d < 64; d++) s += psm[d*XT_S + cc];
            const float mu = s * (1.0f/64.0f);
            float s2 = 0.f;
            #pragma unroll 16
            for (int d = 0; d < 64; d++) { float dd = psm[d*XT_S + cc] - mu; s2 += dd*dd; }
            const float rstd = rsqrtf(s2*(1.0f/64.0f) + EPSV);
            const int mode = A.s[which].mode;
            if (mode == 1) {
                // transposed half: [b][h][t][64]
                __half2* dst = (__half2*)((__half*)Op + ((size_t)((b*NH + h)*NT) + t0 + cc)*64);
                #pragma unroll 8
                for (int d2 = 0; d2 < 32; d2++) {
                    float x0 = (psm[(2*d2  )*XT_S + cc] - mu)*rstd*lng_s[2*d2  ] + lnb_s[2*d2  ];
                    float x1 = (psm[(2*d2+1)*XT_S + cc] - mu)*rstd*lng_s[2*d2+1] + lnb_s[2*d2+1];
                    dst[d2] = __floats2half2_rn(x0, x1);
                }
            } else {
                // d-major half: [b][e][t]
                __half* dst = (__half*)Op + ((size_t)(b*NE + h*ND))*NT + t0 + cc;
                #pragma unroll 8
                for (int d = 0; d < 64; d++)
                    dst[d*NT] = __float2half_rn((psm[d*XT_S + cc] - mu)*rstd*lng_s[d] + lnb_s[d]);
            }
        }
    }
}

// ---------------- 3) flash attention: fp16 m16n8k16, no-max softmax ----------------
// grid (T/128, H, B), 256 thr = 8 warps; warp w owns q-rows [w*16, w*16+16).
// K tile: [key][72 halves] (transposed gmem [t][d]); V tile: [d][72 halves] (native [d][t]).
// Scores bounded (per-head LN): |q.k|/181 <= 0.354 — exp never overflows, no max tracking.
#define KV_S2 36                 // stride in half2 units (72 halves = 144B)
#define KVT (64*KV_S2)           // tile size in half2 units

__global__ void __launch_bounds__(256, 2) attn_mma_kernel(
        const __half* __restrict__ qh, const __half* __restrict__ kh, const __half* __restrict__ vh,
        const int* __restrict__ qmask, const int* __restrict__ kmask,
        float* __restrict__ out) {
    __shared__ unsigned kh2[2*KVT];
    __shared__ unsigned vh2[2*KVT];
    __shared__ int kmb[2*64];

    const int t0 = blockIdx.x * 128;
    const int h = blockIdx.y, b = blockIdx.z;
    const int tid = threadIdx.x;
    const int lane = tid & 31;
    const int w = tid >> 5;
    const int g = lane >> 2;
    const int t4 = lane & 3;
    const int w16 = w * 16;
    const int base  = (b*NE + h*ND)*NT;          // fp32 out / V gmem base rows
    const int baseq = ((b*NH + h)*NT);           // transposed Q/K token base

    // ---- Q fragments straight from gmem (transposed layout [t][64]) ----
    const __half* q0 = qh + (size_t)(baseq + t0 + w16 + g)*64;
    const __half* q1 = q0 + 8*64;
    unsigned qa[4][4];
    #pragma unroll
    for (int kc = 0; kc < 4; kc++) {
        qa[kc][0] = *(const unsigned*)(q0 + 16*kc + 2*t4);
        qa[kc][1] = *(const unsigned*)(q1 + 16*kc + 2*t4);
        qa[kc][2] = *(const unsigned*)(q0 + 16*kc + 2*t4 + 8);
        qa[kc][3] = *(const unsigned*)(q1 + 16*kc + 2*t4 + 8);
    }

    auto prefetch = [&](int kt, int s) {
        const int tk0 = kt*64;
        #pragma unroll
        for (int l = 0; l < 2; l++) {
            int idx = tid + 256*l;          // 0..511
            int row = idx >> 3, c16 = idx & 7;
            cp16((char*)(kh2 + s*KVT + row*KV_S2) + c16*16,
                 kh + (size_t)(baseq + tk0 + row)*64 + c16*8);
            cp16((char*)(vh2 + s*KVT + row*KV_S2) + c16*16,
                 vh + (size_t)(base + row*NT) + tk0 + c16*8);
        }
        if (tid < 16) cp16(kmb + s*64 + tid*4, kmask + b*NT + tk0 + tid*4);
    };

    prefetch(0, 0);
    cp_commit();

    float rs0 = 0.f, rs1 = 0.f;
    float oacc[8][4];
    #pragma unroll
    for (int n = 0; n < 8; n++)
        #pragma unroll
        for (int j = 0; j < 4; j++) oacc[n][j] = 0.f;

    for (int kt = 0; kt < NT/64; kt++) {
        const int cur = kt & 1;
        cp_wait0();
        __syncthreads();
        if (kt + 1 < NT/64) { prefetch(kt+1, cur^1); cp_commit(); }

        const unsigned* ks = kh2 + cur*KVT;
        const unsigned* vs = vh2 + cur*KVT;
        const int*      km = kmb + cur*64;

        // ---- S = Q K^T : m16n8k16, k-dim = d (4 chunks of 16) ----
        float sf[8][4];
        #pragma unroll
        for (int n = 0; n < 8; n++)
            #pragma unroll
            for (int j = 0; j < 4; j++) sf[n][j] = 0.f;
        #pragma unroll
        for (int kc = 0; kc < 4; kc++) {
            #pragma unroll
            for (int n = 0; n < 8; n++) {
                unsigned b0 = ks[(n*8+g)*KV_S2 + 8*kc + t4];
                unsigned b1 = ks[(n*8+g)*KV_S2 + 8*kc + t4 + 4];
                mma_f16(sf[n], qa[kc][0], qa[kc][1], qa[kc][2], qa[kc][3], b0, b1);
            }
        }

        // ---- p = mask ? exp(s/181) : 0 ; no max tracking ----
        #pragma unroll
        for (int n = 0; n < 8; n++) {
            const int km0 = km[n*8 + 2*t4];
            const int km1 = km[n*8 + 2*t4 + 1];
            float p0 = km0 ? ex2a(sf[n][0]*EXP_C) : 0.f;
            float p1 = km1 ? ex2a(sf[n][1]*EXP_C) : 0.f;
            float p2 = km0 ? ex2a(sf[n][2]*EXP_C) : 0.f;
            float p3 = km1 ? ex2a(sf[n][3]*EXP_C) : 0.f;
            rs0 += p0 + p1; rs1 += p2 + p3;
            sf[n][0] = p0; sf[n][1] = p1; sf[n][2] = p2; sf[n][3] = p3;
        }

        // ---- O += P V^T : P packs straight into A fragments (no shuffles) ----
        #pragma unroll
        for (int kc = 0; kc < 4; kc++) {
            unsigned a0 = packh2(sf[2*kc  ][0], sf[2*kc  ][1]);
            unsigned a1 = packh2(sf[2*kc  ][2], sf[2*kc  ][3]);
            unsigned a2 = packh2(sf[2*kc+1][0], sf[2*kc+1][1]);
            unsigned a3 = packh2(sf[2*kc+1][2], sf[2*kc+1][3]);
            #pragma unroll
            for (int n = 0; n < 8; n++) {
                unsigned b0 = vs[(n*8+g)*KV_S2 + 8*kc + t4];
                unsigned b1 = vs[(n*8+g)*KV_S2 + 8*kc + t4 + 4];
                mma_f16(oacc[n], a0, a1, a2, a3, b0, b1);
            }
        }
    }

    // ---- final row-sum reduction (within quad) and epilogue ----
    rs0 += __shfl_xor_sync(0xffffffffu, rs0, 1);
    rs0 += __shfl_xor_sync(0xffffffffu, rs0, 2);
    rs1 += __shfl_xor_sync(0xffffffffu, rs1, 1);
    rs1 += __shfl_xor_sync(0xffffffffu, rs1, 2);

    const int qrow0 = t0 + w16 + g;
    const int qrow1 = qrow0 + 8;
    const float sel0 = (qmask[b*NT + qrow0] != 0) ? (1.0f / rs0) : 0.f;
    const float sel1 = (qmask[b*NT + qrow1] != 0) ? (1.0f / rs1) : 0.f;
    #pragma unroll
    for (int n = 0; n < 8; n++) {
        const int d0 = n*8 + 2*t4;
        out[base + (d0  )*NT + qrow0] = to_tf32(oacc[n][0] * sel0);
        out[base + (d0+1)*NT + qrow0] = to_tf32(oacc[n][1] * sel0);
        out[base + (d0  )*NT + qrow1] = to_tf32(oacc[n][2] * sel1);
        out[base + (d0+1)*NT + qrow1] = to_tf32(oacc[n][3] * sel1);
    }
}

// ---------------- launch ----------------
extern "C" void kernel_launch(void* const* d_in, const int* in_sizes, int n_in,
                              void* d_out, int out_size) {
    (void)in_sizes; (void)n_in; (void)out_size;
    const float* q   = (const float*)d_in[0];
    const float* k   = (const float*)d_in[1];
    const float* v   = (const float*)d_in[2];
    const int*   qm  = (const int*)d_in[3];
    const int*   km  = (const int*)d_in[4];
    const int*   vm  = (const int*)d_in[5];
    const float* Wq  = (const float*)d_in[6];
    const float* bq  = (const float*)d_in[7];
    const float* Wk  = (const float*)d_in[8];
    const float* bk  = (const float*)d_in[9];
    const float* Wv  = (const float*)d_in[10];
    const float* bv  = (const float*)d_in[11];
    const float* Wo  = (const float*)d_in[12];
    const float* bo  = (const float*)d_in[13];
    const float* gq  = (const float*)d_in[14];
    const float* bgq = (const float*)d_in[15];
    const float* gk  = (const float*)d_in[16];
    const float* bgk = (const float*)d_in[17];
    const float* gv  = (const float*)d_in[18];
    const float* bgv = (const float*)d_in[19];

    float *wn, *pa;
    __half *qh, *kh, *vh;
    cudaGetSymbolAddress((void**)&wn, g_Wn);
    cudaGetSymbolAddress((void**)&qh, g_qh);
    cudaGetSymbolAddress((void**)&kh, g_kh);
    cudaGetSymbolAddress((void**)&vh, g_vh);
    cudaGetSymbolAddress((void**)&pa, g_att);

    cudaFuncSetAttribute((const void*)proj_mma_kernel<true, true>,
                         cudaFuncAttributeMaxDynamicSharedMemorySize, PROJ_SMEM);
    cudaFuncSetAttribute((const void*)proj_mma_kernel<false, false>,
                         cudaFuncAttributeMaxDynamicSharedMemorySize, PROJ_SMEM);

    std_weights_kernel<<<dim3(NE, 4), 128>>>(Wq, Wk, Wv, Wo);

    ProjArgs A;
    A.s[0] = { q, qm, wn + 0*NE*NE, bq, gq, bgq, (void*)qh, 1 };
    A.s[1] = { k, km, wn + 1*NE*NE, bk, gk, bgk, (void*)kh, 1 };
    A.s[2] = { v, vm, wn + 2*NE*NE, bv, gv, bgv, (void*)vh, 2 };
    proj_mma_kernel<true, true><<<dim3(NT/128, NH, 6), 256, PROJ_SMEM>>>(A);

    attn_mma_kernel<<<dim3(NT/128, NH, NB), 256>>>(qh, kh, vh, qm, km, pa);

    ProjArgs Ao;
    Ao.s[0] = { pa, qm, wn + 3*NE*NE, bo, nullptr, nullptr, d_out, 0 };
    Ao.s[1] = Ao.s[0];
    Ao.s[2] = Ao.s[0];
    proj_mma_kernel<false, false><<<dim3(NT/128, NH, 2), 256, PROJ_SMEM>>>(Ao);
}

// round 8
// speedup vs baseline: 5.6082x; 1.1254x over previous
#include <cuda_runtime.h>
#include <cuda_fp16.h>
#include <math.h>

#define NB 2
#define NE 512
#define NH 8
#define ND 64
#define NT 2048
#define EPSV 1e-5f
// exp(s/181) = ex2(s * log2(e)/181)
#define EXP_C (1.44269504088896341f/181.0f)

// ---------------- scratch (device globals: allocation-free) ----------------
__device__ __half g_Wh[4*NE*NE];        // standardized weights, half, [mat][m][e]
__device__ __half g_xT[3*NB*NT*NE];     // masked transposed inputs [which][b][t][e]
__device__ __half g_qh[NB*NH*NT*ND];    // Q transposed: [b][h][t][d]
__device__ __half g_kh[NB*NH*NT*ND];    // K transposed: [b][h][t][d]
__device__ __half g_vh[NB*NE*NT];       // V: [b][e][t]
__device__ __half g_aT[NB*NT*NE];       // attention out transposed [b][t][e]

__device__ __forceinline__ float ex2a(float x) {
    float y;
    asm("ex2.approx.f32 %0, %1;" : "=f"(y) : "f"(x));
    return y;
}
// pack two fp32 -> half2 (lo = first arg)
__device__ __forceinline__ unsigned packh2(float lo, float hi) {
    unsigned r;
    asm("cvt.rn.f16x2.f32 %0, %1, %2;" : "=r"(r) : "f"(hi), "f"(lo));
    return r;
}
__device__ __forceinline__ void mma_f16(float* d,
        unsigned a0, unsigned a1, unsigned a2, unsigned a3,
        unsigned b0, unsigned b1) {
    asm volatile("mma.sync.aligned.m16n8k16.row.col.f32.f16.f16.f32 "
        "{%0,%1,%2,%3}, {%4,%5,%6,%7}, {%8,%9}, {%0,%1,%2,%3};\n"
        : "+f"(d[0]), "+f"(d[1]), "+f"(d[2]), "+f"(d[3])
        : "r"(a0), "r"(a1), "r"(a2), "r"(a3), "r"(b0), "r"(b1));
}
__device__ __forceinline__ void cp16(void* dst, const void* src) {
    unsigned d = (unsigned)__cvta_generic_to_shared(dst);
    asm volatile("cp.async.ca.shared.global [%0], [%1], 16;" :: "r"(d), "l"(src));
}
__device__ __forceinline__ void cp_commit() { asm volatile("cp.async.commit_group;"); }
__device__ __forceinline__ void cp_wait0()  { asm volatile("cp.async.wait_group 0;"); }

// ---------------- 1) weight standardization (writes half) ----------------
__global__ void std_weights_kernel(const float* __restrict__ W0, const float* __restrict__ W1,
                                   const float* __restrict__ W2, const float* __restrict__ W3) {
    const float* Ws[4] = {W0, W1, W2, W3};
    const float* W = Ws[blockIdx.y];
    __half* out = g_Wh + blockIdx.y * NE * NE;
    const int row = blockIdx.x;
    const int tid = threadIdx.x;

    float w[4];
    #pragma unroll
    for (int j = 0; j < 4; j++) w[j] = W[row*NE + tid + 128*j];

    __shared__ float red[4];
    float s = w[0]+w[1]+w[2]+w[3];
    #pragma unroll
    for (int o = 16; o > 0; o >>= 1) s += __shfl_down_sync(0xffffffffu, s, o);
    if ((tid & 31) == 0) red[tid >> 5] = s;
    __syncthreads();
    const float mu = (red[0]+red[1]+red[2]+red[3]) * (1.0f/NE);
    __syncthreads();

    float s2 = 0.f;
    #pragma unroll
    for (int j = 0; j < 4; j++) { float d = w[j]-mu; s2 += d*d; }
    #pragma unroll
    for (int o = 16; o > 0; o >>= 1) s2 += __shfl_down_sync(0xffffffffu, s2, o);
    if ((tid & 31) == 0) red[tid >> 5] = s2;
    __syncthreads();
    const float var = (red[0]+red[1]+red[2]+red[3]) * (1.0f/NE);
    const float rstd = rsqrtf(var + EPSV);
    #pragma unroll
    for (int j = 0; j < 4; j++)
        out[row*NE + tid + 128*j] = __float2half_rn((w[j]-mu)*rstd);
}

// ---------------- 1b) masked transpose: x [b][e][t] fp32 -> xT [which][b][t][e] half ----------------
__global__ void transpose_mask_kernel(const float* __restrict__ x0, const float* __restrict__ x1,
                                      const float* __restrict__ x2,
                                      const int* __restrict__ m0, const int* __restrict__ m1,
                                      const int* __restrict__ m2) {
    const int which = blockIdx.z >> 1;
    const int b = blockIdx.z & 1;
    const float* X = (which == 0) ? x0 : (which == 1) ? x1 : x2;
    const int*   M = (which == 0) ? m0 : (which == 1) ? m1 : m2;
    __half* O = g_xT + ((size_t)which*NB + b)*NT*NE;

    __shared__ float tile[32][33];
    const int t0 = blockIdx.x*32, e0 = blockIdx.y*32;
    const int tx = threadIdx.x, ty = threadIdx.y;
    #pragma unroll
    for (int i = 0; i < 4; i++)
        tile[ty+8*i][tx] = X[(size_t)(b*NE + e0 + ty + 8*i)*NT + t0 + tx];
    __syncthreads();
    #pragma unroll
    for (int i = 0; i < 4; i++) {
        const int t = t0 + ty + 8*i;
        const float mk = (float)M[b*NT + t];
        O[(size_t)t*NE + e0 + tx] = __float2half_rn(tile[tx][ty+8*i]*mk);
    }
}

// ---------------- 2/4) projection GEMM: fp16 m16n8k16 + cp.async 2-stage ----------------
// out[m 64][t 128] = Wh[m][e] @ xT[t][e]^T ; both fragments natural half2 loads.
// mode 1: LN + transposed half out [b][h][t][64]  (Q, K)
// mode 2: LN + half out [b][e][t]                 (V)
// mode 0: fp32 out [b][e][t] + bias               (final output; input pre-masked)
struct ProjSet {
    const __half* bT; const __half* wh; const float* bias;
    const float* lng; const float* lnb; void* out; int mode;
};
struct ProjArgs { ProjSet s[3]; };

#define WT_U 20                  // u32 stride per row (40 halves, conflict-free)
#define WCHU (64*WT_U)           // 1280 u32 per W stage
#define XCHU (128*WT_U)          // 2560 u32 per x stage
#define XT_S 136
#define PROJ_SMEM (64*XT_S*4)    // 34816 B >= pipeline 2*(WCHU+XCHU)*4 = 30720 B

template<bool DO_LN>
__global__ void __launch_bounds__(256) proj_h_kernel(ProjArgs A) {
    const int which = blockIdx.z >> 1;
    const int b = blockIdx.z & 1;
    const __half* __restrict__ Bt = A.s[which].bT + (size_t)b*NT*NE;   // [t][e]
    const __half* __restrict__ Wh = A.s[which].wh;
    const float*  __restrict__ Bp = A.s[which].bias;
    const float*  __restrict__ Gp = A.s[which].lng;
    const float*  __restrict__ Lp = A.s[which].lnb;
    void*         __restrict__ Op = A.s[which].out;

    const int h  = blockIdx.y;
    const int t0 = blockIdx.x * 128;
    const int tid = threadIdx.x;
    const int lane = tid & 31;
    const int wid = tid >> 5;
    const int wm = wid & 1, wn = wid >> 1;
    const int g = lane >> 2, t4 = lane & 3;

    extern __shared__ float psm[];
    unsigned* wtb = (unsigned*)psm;        // [2][1280] u32 (64 rows x 40 halves)
    unsigned* xtb = wtb + 2*WCHU;          // [2][2560] u32 (128 rows x 40 halves)
    __shared__ float lng_s[ND];
    __shared__ float lnb_s[ND];

    if (DO_LN && tid < 64) {
        lng_s[tid] = Gp[tid];
        lnb_s[tid] = Lp[tid];
    }

    const __half* Wr = Wh + (size_t)(h*ND)*NE;

    auto prefetch = [&](int c, int s) {
        const int k0 = c*32;    // halves
        {   // W: 64 rows x 64B -> 256 cp16 (1/thread)
            int r = tid >> 2, c16 = tid & 3;
            cp16((char*)(wtb + s*WCHU + r*WT_U) + c16*16, Wr + (size_t)r*NE + k0 + c16*8);
        }
        #pragma unroll
        for (int l = 0; l < 2; l++) {   // xT: 128 rows x 64B -> 512 cp16 (2/thread)
            int idx = tid + 256*l; int r = idx >> 2, c16 = idx & 3;
            cp16((char*)(xtb + s*XCHU + r*WT_U) + c16*16, Bt + (size_t)(t0 + r)*NE + k0 + c16*8);
        }
    };

    prefetch(0, 0);
    cp_commit();

    float acc[2][4][4];
    #pragma unroll
    for (int mt = 0; mt < 2; mt++)
        #pragma unroll
        for (int n = 0; n < 4; n++)
            #pragma unroll
            for (int j = 0; j < 4; j++) acc[mt][n][j] = 0.f;

    for (int c = 0; c < 16; c++) {
        const int cur = c & 1;
        cp_wait0();
        __syncthreads();
        if (c + 1 < 16) { prefetch(c+1, cur^1); cp_commit(); }

        const unsigned* wt = wtb + cur*WCHU;
        const unsigned* xt = xtb + cur*XCHU;
        #pragma unroll
        for (int sub = 0; sub < 2; sub++) {
            unsigned a[2][4];
            #pragma unroll
            for (int mt = 0; mt < 2; mt++) {
                const int r0 = wm*32 + mt*16;
                a[mt][0] = wt[(r0+g  )*WT_U + 8*sub + t4];
                a[mt][1] = wt[(r0+g+8)*WT_U + 8*sub + t4];
                a[mt][2] = wt[(r0+g  )*WT_U + 8*sub + t4 + 4];
                a[mt][3] = wt[(r0+g+8)*WT_U + 8*sub + t4 + 4];
            }
            #pragma unroll
            for (int n = 0; n < 4; n++) {
                const int col = wn*32 + n*8 + g;
                unsigned b0 = xt[col*WT_U + 8*sub + t4];
                unsigned b1 = xt[col*WT_U + 8*sub + t4 + 4];
                #pragma unroll
                for (int mt = 0; mt < 2; mt++)
                    mma_f16(acc[mt][n], a[mt][0], a[mt][1], a[mt][2], a[mt][3], b0, b1);
            }
        }
    }

    float bv[2][2];
    #pragma unroll
    for (int mt = 0; mt < 2; mt++) {
        bv[mt][0] = Bp[h*ND + wm*32 + mt*16 + g];
        bv[mt][1] = Bp[h*ND + wm*32 + mt*16 + g + 8];
    }

    if (!DO_LN) {
        float* o = (float*)Op + (size_t)(b*NE + h*ND)*NT + t0;
        #pragma unroll
        for (int mt = 0; mt < 2; mt++) {
            const int r0 = wm*32 + mt*16 + g;
            #pragma unroll
            for (int n = 0; n < 4; n++) {
                const int cc = wn*32 + n*8 + 2*t4;
                *(float2*)(o + (size_t)(r0  )*NT + cc) =
                    make_float2(acc[mt][n][0] + bv[mt][0], acc[mt][n][1] + bv[mt][0]);
                *(float2*)(o + (size_t)(r0+8)*NT + cc) =
                    make_float2(acc[mt][n][2] + bv[mt][1], acc[mt][n][3] + bv[mt][1]);
            }
        }
    } else {
        __syncthreads();   // done with pipeline buffers; reuse psm as [64][136] fp32 tile
        #pragma unroll
        for (int mt = 0; mt < 2; mt++) {
            const int r0 = wm*32 + mt*16 + g;
            #pragma unroll
            for (int n = 0; n < 4; n++) {
                const int cc = wn*32 + n*8 + 2*t4;
                *(float2*)(psm + (r0  )*XT_S + cc) =
                    make_float2(acc[mt][n][0] + bv[mt][0], acc[mt][n][1] + bv[mt][0]);
                *(float2*)(psm + (r0+8)*XT_S + cc) =
                    make_float2(acc[mt][n][2] + bv[mt][1], acc[mt][n][3] + bv[mt][1]);
            }
        }
        __syncthreads();
        if (tid < 128) {
            const int cc = tid;
            float s = 0.f;
            #pragma unroll 16
            for (int d = 0; d < 64; d++) s += psm[d*XT_S + cc];
            const float mu = s * (1.0f/64.0f);
            float s2 = 0.f;
            #pragma unroll 16
            for (int d = 0; d < 64; d++) { float dd = psm[d*XT_S + cc] - mu; s2 += dd*dd; }
            const float rstd = rsqrtf(s2*(1.0f/64.0f) + EPSV);
            const int mode = A.s[which].mode;
            if (mode == 1) {
                // transposed half: [b][h][t][64]
                __half2* dst = (__half2*)((__half*)Op + ((size_t)((b*NH + h)*NT) + t0 + cc)*64);
                #pragma unroll 8
                for (int d2 = 0; d2 < 32; d2++) {
                    float x0 = (psm[(2*d2  )*XT_S + cc] - mu)*rstd*lng_s[2*d2  ] + lnb_s[2*d2  ];
                    float x1 = (psm[(2*d2+1)*XT_S + cc] - mu)*rstd*lng_s[2*d2+1] + lnb_s[2*d2+1];
                    dst[d2] = __floats2half2_rn(x0, x1);
                }
            } else {
                // d-major half: [b][e][t]
                __half* dst = (__half*)Op + (size_t)(b*NE + h*ND)*NT + t0 + cc;
                #pragma unroll 8
                for (int d = 0; d < 64; d++)
                    dst[(size_t)d*NT] = __float2half_rn((psm[d*XT_S + cc] - mu)*rstd*lng_s[d] + lnb_s[d]);
            }
        }
    }
}

// ---------------- 3) flash attention: fp16 m16n8k16, no-max softmax ----------------
// grid (T/128, H, B), 256 thr = 8 warps; warp w owns q-rows [w*16, w*16+16).
// K tile: [key][72 halves]; V tile: [d][72 halves]. Output transposed half -> g_aT [b][t][e].
// Scores bounded (per-head LN): |q.k|/181 <= 0.354 — exp never overflows, no max tracking.
#define KV_S2 36                 // stride in half2 units (72 halves)
#define KVT (64*KV_S2)

__global__ void __launch_bounds__(256, 2) attn_mma_kernel(
        const __half* __restrict__ qh, const __half* __restrict__ kh, const __half* __restrict__ vh,
        const int* __restrict__ qmask, const int* __restrict__ kmask,
        __half* __restrict__ aT) {
    __shared__ unsigned kh2[2*KVT];
    __shared__ unsigned vh2[2*KVT];
    __shared__ int kmb[2*64];

    const int t0 = blockIdx.x * 128;
    const int h = blockIdx.y, b = blockIdx.z;
    const int tid = threadIdx.x;
    const int lane = tid & 31;
    const int w = tid >> 5;
    const int g = lane >> 2;
    const int t4 = lane & 3;
    const int w16 = w * 16;
    const int base  = (b*NE + h*ND)*NT;          // V gmem base rows
    const int baseq = ((b*NH + h)*NT);           // transposed Q/K token base

    // ---- Q fragments straight from gmem (transposed layout [t][64]) ----
    const __half* q0 = qh + (size_t)(baseq + t0 + w16 + g)*64;
    const __half* q1 = q0 + 8*64;
    unsigned qa[4][4];
    #pragma unroll
    for (int kc = 0; kc < 4; kc++) {
        qa[kc][0] = *(const unsigned*)(q0 + 16*kc + 2*t4);
        qa[kc][1] = *(const unsigned*)(q1 + 16*kc + 2*t4);
        qa[kc][2] = *(const unsigned*)(q0 + 16*kc + 2*t4 + 8);
        qa[kc][3] = *(const unsigned*)(q1 + 16*kc + 2*t4 + 8);
    }

    auto prefetch = [&](int kt, int s) {
        const int tk0 = kt*64;
        #pragma unroll
        for (int l = 0; l < 2; l++) {
            int idx = tid + 256*l;
            int row = idx >> 3, c16 = idx & 7;
            cp16((char*)(kh2 + s*KVT + row*KV_S2) + c16*16,
                 kh + (size_t)(baseq + tk0 + row)*64 + c16*8);
            cp16((char*)(vh2 + s*KVT + row*KV_S2) + c16*16,
                 vh + (size_t)(base + row*NT) + tk0 + c16*8);
        }
        if (tid < 16) cp16(kmb + s*64 + tid*4, kmask + b*NT + tk0 + tid*4);
    };

    prefetch(0, 0);
    cp_commit();

    float rs0 = 0.f, rs1 = 0.f;
    float oacc[8][4];
    #pragma unroll
    for (int n = 0; n < 8; n++)
        #pragma unroll
        for (int j = 0; j < 4; j++) oacc[n][j] = 0.f;

    for (int kt = 0; kt < NT/64; kt++) {
        const int cur = kt & 1;
        cp_wait0();
        __syncthreads();
        if (kt + 1 < NT/64) { prefetch(kt+1, cur^1); cp_commit(); }

        const unsigned* ks = kh2 + cur*KVT;
        const unsigned* vs = vh2 + cur*KVT;
        const int*      km = kmb + cur*64;

        // ---- S = Q K^T ----
        float sf[8][4];
        #pragma unroll
        for (int n = 0; n < 8; n++)
            #pragma unroll
            for (int j = 0; j < 4; j++) sf[n][j] = 0.f;
        #pragma unroll
        for (int kc = 0; kc < 4; kc++) {
            #pragma unroll
            for (int n = 0; n < 8; n++) {
                unsigned b0 = ks[(n*8+g)*KV_S2 + 8*kc + t4];
                unsigned b1 = ks[(n*8+g)*KV_S2 + 8*kc + t4 + 4];
                mma_f16(sf[n], qa[kc][0], qa[kc][1], qa[kc][2], qa[kc][3], b0, b1);
            }
        }

        // ---- p = mask ? exp(s/181) : 0 ----
        #pragma unroll
        for (int n = 0; n < 8; n++) {
            const int km0 = km[n*8 + 2*t4];
            const int km1 = km[n*8 + 2*t4 + 1];
            float p0 = km0 ? ex2a(sf[n][0]*EXP_C) : 0.f;
            float p1 = km1 ? ex2a(sf[n][1]*EXP_C) : 0.f;
            float p2 = km0 ? ex2a(sf[n][2]*EXP_C) : 0.f;
            float p3 = km1 ? ex2a(sf[n][3]*EXP_C) : 0.f;
            rs0 += p0 + p1; rs1 += p2 + p3;
            sf[n][0] = p0; sf[n][1] = p1; sf[n][2] = p2; sf[n][3] = p3;
        }

        // ---- O += P V^T : P packs straight into A fragments ----
        #pragma unroll
        for (int kc = 0; kc < 4; kc++) {
            unsigned a0 = packh2(sf[2*kc  ][0], sf[2*kc  ][1]);
            unsigned a1 = packh2(sf[2*kc  ][2], sf[2*kc  ][3]);
            unsigned a2 = packh2(sf[2*kc+1][0], sf[2*kc+1][1]);
            unsigned a3 = packh2(sf[2*kc+1][2], sf[2*kc+1][3]);
            #pragma unroll
            for (int n = 0; n < 8; n++) {
                unsigned b0 = vs[(n*8+g)*KV_S2 + 8*kc + t4];
                unsigned b1 = vs[(n*8+g)*KV_S2 + 8*kc + t4 + 4];
                mma_f16(oacc[n], a0, a1, a2, a3, b0, b1);
            }
        }
    }

    // ---- row-sum reduction and transposed half epilogue ----
    rs0 += __shfl_xor_sync(0xffffffffu, rs0, 1);
    rs0 += __shfl_xor_sync(0xffffffffu, rs0, 2);
    rs1 += __shfl_xor_sync(0xffffffffu, rs1, 1);
    rs1 += __shfl_xor_sync(0xffffffffu, rs1, 2);

    const int qrow0 = t0 + w16 + g;
    const int qrow1 = qrow0 + 8;
    const float sel0 = (qmask[b*NT + qrow0] != 0) ? (1.0f / rs0) : 0.f;
    const float sel1 = (qmask[b*NT + qrow1] != 0) ? (1.0f / rs1) : 0.f;
    __half* o0 = aT + (size_t)(b*NT + qrow0)*NE + h*ND;
    __half* o1 = aT + (size_t)(b*NT + qrow1)*NE + h*ND;
    #pragma unroll
    for (int n = 0; n < 8; n++) {
        const int d0 = n*8 + 2*t4;
        *(unsigned*)(o0 + d0) = packh2(oacc[n][0]*sel0, oacc[n][1]*sel0);
        *(unsigned*)(o1 + d0) = packh2(oacc[n][2]*sel1, oacc[n][3]*sel1);
    }
}

// ---------------- launch ----------------
extern "C" void kernel_launch(void* const* d_in, const int* in_sizes, int n_in,
                              void* d_out, int out_size) {
    (void)in_sizes; (void)n_in; (void)out_size;
    const float* q   = (const float*)d_in[0];
    const float* k   = (const float*)d_in[1];
    const float* v   = (const float*)d_in[2];
    const int*   qm  = (const int*)d_in[3];
    const int*   km  = (const int*)d_in[4];
    const int*   vm  = (const int*)d_in[5];
    const float* Wq  = (const float*)d_in[6];
    const float* bq  = (const float*)d_in[7];
    const float* Wk  = (const float*)d_in[8];
    const float* bk  = (const float*)d_in[9];
    const float* Wv  = (const float*)d_in[10];
    const float* bv  = (const float*)d_in[11];
    const float* Wo  = (const float*)d_in[12];
    const float* bo  = (const float*)d_in[13];
    const float* gq  = (const float*)d_in[14];
    const float* bgq = (const float*)d_in[15];
    const float* gk  = (const float*)d_in[16];
    const float* bgk = (const float*)d_in[17];
    const float* gv  = (const float*)d_in[18];
    const float* bgv = (const float*)d_in[19];

    __half *wh, *xT, *qh, *kh, *vh, *aT;
    cudaGetSymbolAddress((void**)&wh, g_Wh);
    cudaGetSymbolAddress((void**)&xT, g_xT);
    cudaGetSymbolAddress((void**)&qh, g_qh);
    cudaGetSymbolAddress((void**)&kh, g_kh);
    cudaGetSymbolAddress((void**)&vh, g_vh);
    cudaGetSymbolAddress((void**)&aT, g_aT);

    cudaFuncSetAttribute((const void*)proj_h_kernel<true>,
                         cudaFuncAttributeMaxDynamicSharedMemorySize, PROJ_SMEM);
    cudaFuncSetAttribute((const void*)proj_h_kernel<false>,
                         cudaFuncAttributeMaxDynamicSharedMemorySize, PROJ_SMEM);

    std_weights_kernel<<<dim3(NE, 4), 128>>>(Wq, Wk, Wv, Wo);
    transpose_mask_kernel<<<dim3(NT/32, NE/32, 6), dim3(32, 8)>>>(q, k, v, qm, km, vm);

    const size_t XSL = (size_t)NB*NT*NE;
    ProjArgs A;
    A.s[0] = { xT + 0*XSL, wh + 0*NE*NE, bq, gq, bgq, (void*)qh, 1 };
    A.s[1] = { xT + 1*XSL, wh + 1*NE*NE, bk, gk, bgk, (void*)kh, 1 };
    A.s[2] = { xT + 2*XSL, wh + 2*NE*NE, bv, gv, bgv, (void*)vh, 2 };
    proj_h_kernel<true><<<dim3(NT/128, NH, 6), 256, PROJ_SMEM>>>(A);

    attn_mma_kernel<<<dim3(NT/128, NH, NB), 256>>>(qh, kh, vh, qm, km, aT);

    ProjArgs Ao;
    Ao.s[0] = { aT, wh + 3*NE*NE, bo, nullptr, nullptr, d_out, 0 };
    Ao.s[1] = Ao.s[0];
    Ao.s[2] = Ao.s[0];
    proj_h_kernel<false><<<dim3(NT/128, NH, 2), 256, PROJ_SMEM>>>(Ao);
}

// round 9
// speedup vs baseline: 5.6859x; 1.0139x over previous
#include <cuda_runtime.h>
#include <cuda_fp16.h>
#include <math.h>

#define NB 2
#define NE 512
#define NH 8
#define ND 64
#define NT 2048
#define EPSV 1e-5f
// exp(s/181) = ex2(s * log2(e)/181); folded into Q at projection time
#define EXP_C (1.44269504088896341f/181.0f)

// ---------------- scratch (device globals: allocation-free) ----------------
__device__ __half g_Wh[4*NE*NE];        // standardized weights, half, [mat][m][e]
__device__ __half g_xT[3*NB*NT*NE];     // masked transposed inputs [which][b][t][e]
__device__ __half g_qh[NB*NH*NT*ND];    // Q transposed (pre-scaled by EXP_C): [b][h][t][d]
__device__ __half g_kh[NB*NH*NT*ND];    // K transposed: [b][h][t][d]
__device__ __half g_vh[NB*NE*NT];       // V (key-masked): [b][e][t]
__device__ __half g_kmh[NB*NT];         // key_mask as half
__device__ __half g_aT[NB*NT*NE];       // attention out transposed [b][t][e]

__device__ __forceinline__ float ex2a(float x) {
    float y;
    asm("ex2.approx.f32 %0, %1;" : "=f"(y) : "f"(x));
    return y;
}
// pack two fp32 -> half2 (lo = first arg)
__device__ __forceinline__ unsigned packh2(float lo, float hi) {
    unsigned r;
    asm("cvt.rn.f16x2.f32 %0, %1, %2;" : "=r"(r) : "f"(hi), "f"(lo));
    return r;
}
__device__ __forceinline__ void mma_f16(float* d,
        unsigned a0, unsigned a1, unsigned a2, unsigned a3,
        unsigned b0, unsigned b1) {
    asm volatile("mma.sync.aligned.m16n8k16.row.col.f32.f16.f16.f32 "
        "{%0,%1,%2,%3}, {%4,%5,%6,%7}, {%8,%9}, {%0,%1,%2,%3};\n"
        : "+f"(d[0]), "+f"(d[1]), "+f"(d[2]), "+f"(d[3])
        : "r"(a0), "r"(a1), "r"(a2), "r"(a3), "r"(b0), "r"(b1));
}
__device__ __forceinline__ void ldsm4(unsigned& r0, unsigned& r1, unsigned& r2, unsigned& r3,
                                      unsigned a) {
    asm volatile("ldmatrix.sync.aligned.m8n8.x4.shared.b16 {%0,%1,%2,%3}, [%4];"
        : "=r"(r0), "=r"(r1), "=r"(r2), "=r"(r3) : "r"(a));
}
__device__ __forceinline__ void ldsm2(unsigned& r0, unsigned& r1, unsigned a) {
    asm volatile("ldmatrix.sync.aligned.m8n8.x2.shared.b16 {%0,%1}, [%2];"
        : "=r"(r0), "=r"(r1) : "r"(a));
}
__device__ __forceinline__ void cp16(void* dst, const void* src) {
    unsigned d = (unsigned)__cvta_generic_to_shared(dst);
    asm volatile("cp.async.ca.shared.global [%0], [%1], 16;" :: "r"(d), "l"(src));
}
__device__ __forceinline__ void cp_commit() { asm volatile("cp.async.commit_group;"); }
__device__ __forceinline__ void cp_wait0()  { asm volatile("cp.async.wait_group 0;"); }

// ---------------- 1) weight standardization (writes half) ----------------
__global__ void std_weights_kernel(const float* __restrict__ W0, const float* __restrict__ W1,
                                   const float* __restrict__ W2, const float* __restrict__ W3) {
    const float* Ws[4] = {W0, W1, W2, W3};
    const float* W = Ws[blockIdx.y];
    __half* out = g_Wh + blockIdx.y * NE * NE;
    const int row = blockIdx.x;
    const int tid = threadIdx.x;

    float w[4];
    #pragma unroll
    for (int j = 0; j < 4; j++) w[j] = W[row*NE + tid + 128*j];

    __shared__ float red[4];
    float s = w[0]+w[1]+w[2]+w[3];
    #pragma unroll
    for (int o = 16; o > 0; o >>= 1) s += __shfl_down_sync(0xffffffffu, s, o);
    if ((tid & 31) == 0) red[tid >> 5] = s;
    __syncthreads();
    const float mu = (red[0]+red[1]+red[2]+red[3]) * (1.0f/NE);
    __syncthreads();

    float s2 = 0.f;
    #pragma unroll
    for (int j = 0; j < 4; j++) { float d = w[j]-mu; s2 += d*d; }
    #pragma unroll
    for (int o = 16; o > 0; o >>= 1) s2 += __shfl_down_sync(0xffffffffu, s2, o);
    if ((tid & 31) == 0) red[tid >> 5] = s2;
    __syncthreads();
    const float var = (red[0]+red[1]+red[2]+red[3]) * (1.0f/NE);
    const float rstd = rsqrtf(var + EPSV);
    #pragma unroll
    for (int j = 0; j < 4; j++)
        out[row*NE + tid + 128*j] = __float2half_rn((w[j]-mu)*rstd);
}

// ---------------- 1b) masked transpose + mask-to-half ----------------
__global__ void transpose_mask_kernel(const float* __restrict__ x0, const float* __restrict__ x1,
                                      const float* __restrict__ x2,
                                      const int* __restrict__ m0, const int* __restrict__ m1,
                                      const int* __restrict__ m2) {
    const int which = blockIdx.z >> 1;
    const int b = blockIdx.z & 1;
    const float* X = (which == 0) ? x0 : (which == 1) ? x1 : x2;
    const int*   M = (which == 0) ? m0 : (which == 1) ? m1 : m2;
    __half* O = g_xT + ((size_t)which*NB + b)*NT*NE;

    __shared__ float tile[32][33];
    const int t0 = blockIdx.x*32, e0 = blockIdx.y*32;
    const int tx = threadIdx.x, ty = threadIdx.y;
    #pragma unroll
    for (int i = 0; i < 4; i++)
        tile[ty+8*i][tx] = X[(size_t)(b*NE + e0 + ty + 8*i)*NT + t0 + tx];
    __syncthreads();
    #pragma unroll
    for (int i = 0; i < 4; i++) {
        const int t = t0 + ty + 8*i;
        const float mk = (float)M[b*NT + t];
        O[(size_t)t*NE + e0 + tx] = __float2half_rn(tile[tx][ty+8*i]*mk);
    }
}

__global__ void mask_half_kernel(const int* __restrict__ km) {
    const int i = blockIdx.x*256 + threadIdx.x;
    g_kmh[i] = __float2half_rn((float)km[i]);
}

// ---------------- 2/4) projection GEMM: fp16 m16n8k16 + cp.async 2-stage ----------------
// mode 1: LN*oscale + transposed half out [b][h][t][64]  (Q: oscale=EXP_C; K: 1)
// mode 2: LN * key_mask + half out [b][e][t]             (V)
// mode 0: fp32 out [b][e][t] + bias                      (final output)
struct ProjSet {
    const __half* bT; const __half* wh; const float* bias;
    const float* lng; const float* lnb; void* out; int mode;
    float oscale; const int* xmask;
};
struct ProjArgs { ProjSet s[3]; };

#define WT_U 20
#define WCHU (64*WT_U)
#define XCHU (128*WT_U)
#define XT_S 136
#define PROJ_SMEM (64*XT_S*4)

template<bool DO_LN>
__global__ void __launch_bounds__(256) proj_h_kernel(ProjArgs A) {
    const int which = blockIdx.z >> 1;
    const int b = blockIdx.z & 1;
    const __half* __restrict__ Bt = A.s[which].bT + (size_t)b*NT*NE;
    const __half* __restrict__ Wh = A.s[which].wh;
    const float*  __restrict__ Bp = A.s[which].bias;
    const float*  __restrict__ Gp = A.s[which].lng;
    const float*  __restrict__ Lp = A.s[which].lnb;
    void*         __restrict__ Op = A.s[which].out;

    const int h  = blockIdx.y;
    const int t0 = blockIdx.x * 128;
    const int tid = threadIdx.x;
    const int lane = tid & 31;
    const int wid = tid >> 5;
    const int wm = wid & 1, wn = wid >> 1;
    const int g = lane >> 2, t4 = lane & 3;

    extern __shared__ float psm[];
    unsigned* wtb = (unsigned*)psm;
    unsigned* xtb = wtb + 2*WCHU;
    __shared__ float lng_s[ND];
    __shared__ float lnb_s[ND];

    if (DO_LN && tid < 64) {
        lng_s[tid] = Gp[tid];
        lnb_s[tid] = Lp[tid];
    }

    const __half* Wr = Wh + (size_t)(h*ND)*NE;

    auto prefetch = [&](int c, int s) {
        const int k0 = c*32;
        {
            int r = tid >> 2, c16 = tid & 3;
            cp16((char*)(wtb + s*WCHU + r*WT_U) + c16*16, Wr + (size_t)r*NE + k0 + c16*8);
        }
        #pragma unroll
        for (int l = 0; l < 2; l++) {
            int idx = tid + 256*l; int r = idx >> 2, c16 = idx & 3;
            cp16((char*)(xtb + s*XCHU + r*WT_U) + c16*16, Bt + (size_t)(t0 + r)*NE + k0 + c16*8);
        }
    };

    prefetch(0, 0);
    cp_commit();

    float acc[2][4][4];
    #pragma unroll
    for (int mt = 0; mt < 2; mt++)
        #pragma unroll
        for (int n = 0; n < 4; n++)
            #pragma unroll
            for (int j = 0; j < 4; j++) acc[mt][n][j] = 0.f;

    for (int c = 0; c < 16; c++) {
        const int cur = c & 1;
        cp_wait0();
        __syncthreads();
        if (c + 1 < 16) { prefetch(c+1, cur^1); cp_commit(); }

        const unsigned* wt = wtb + cur*WCHU;
        const unsigned* xt = xtb + cur*XCHU;
        #pragma unroll
        for (int sub = 0; sub < 2; sub++) {
            unsigned a[2][4];
            #pragma unroll
            for (int mt = 0; mt < 2; mt++) {
                const int r0 = wm*32 + mt*16;
                a[mt][0] = wt[(r0+g  )*WT_U + 8*sub + t4];
                a[mt][1] = wt[(r0+g+8)*WT_U + 8*sub + t4];
                a[mt][2] = wt[(r0+g  )*WT_U + 8*sub + t4 + 4];
                a[mt][3] = wt[(r0+g+8)*WT_U + 8*sub + t4 + 4];
            }
            #pragma unroll
            for (int n = 0; n < 4; n++) {
                const int col = wn*32 + n*8 + g;
                unsigned b0 = xt[col*WT_U + 8*sub + t4];
                unsigned b1 = xt[col*WT_U + 8*sub + t4 + 4];
                #pragma unroll
                for (int mt = 0; mt < 2; mt++)
                    mma_f16(acc[mt][n], a[mt][0], a[mt][1], a[mt][2], a[mt][3], b0, b1);
            }
        }
    }

    float bv[2][2];
    #pragma unroll
    for (int mt = 0; mt < 2; mt++) {
        bv[mt][0] = Bp[h*ND + wm*32 + mt*16 + g];
        bv[mt][1] = Bp[h*ND + wm*32 + mt*16 + g + 8];
    }

    if (!DO_LN) {
        float* o = (float*)Op + (size_t)(b*NE + h*ND)*NT + t0;
        #pragma unroll
        for (int mt = 0; mt < 2; mt++) {
            const int r0 = wm*32 + mt*16 + g;
            #pragma unroll
            for (int n = 0; n < 4; n++) {
                const int cc = wn*32 + n*8 + 2*t4;
                *(float2*)(o + (size_t)(r0  )*NT + cc) =
                    make_float2(acc[mt][n][0] + bv[mt][0], acc[mt][n][1] + bv[mt][0]);
                *(float2*)(o + (size_t)(r0+8)*NT + cc) =
                    make_float2(acc[mt][n][2] + bv[mt][1], acc[mt][n][3] + bv[mt][1]);
            }
        }
    } else {
        __syncthreads();
        #pragma unroll
        for (int mt = 0; mt < 2; mt++) {
            const int r0 = wm*32 + mt*16 + g;
            #pragma unroll
            for (int n = 0; n < 4; n++) {
                const int cc = wn*32 + n*8 + 2*t4;
                *(float2*)(psm + (r0  )*XT_S + cc) =
                    make_float2(acc[mt][n][0] + bv[mt][0], acc[mt][n][1] + bv[mt][0]);
                *(float2*)(psm + (r0+8)*XT_S + cc) =
                    make_float2(acc[mt][n][2] + bv[mt][1], acc[mt][n][3] + bv[mt][1]);
            }
        }
        __syncthreads();
        if (tid < 128) {
            const int cc = tid;
            float s = 0.f;
            #pragma unroll 16
            for (int d = 0; d < 64; d++) s += psm[d*XT_S + cc];
            const float mu = s * (1.0f/64.0f);
            float s2 = 0.f;
            #pragma unroll 16
            for (int d = 0; d < 64; d++) { float dd = psm[d*XT_S + cc] - mu; s2 += dd*dd; }
            const float rstd = rsqrtf(s2*(1.0f/64.0f) + EPSV);
            const int mode = A.s[which].mode;
            if (mode == 1) {
                const float osc = A.s[which].oscale;
                __half2* dst = (__half2*)((__half*)Op + ((size_t)((b*NH + h)*NT) + t0 + cc)*64);
                #pragma unroll 8
                for (int d2 = 0; d2 < 32; d2++) {
                    float x0 = ((psm[(2*d2  )*XT_S + cc] - mu)*rstd*lng_s[2*d2  ] + lnb_s[2*d2  ])*osc;
                    float x1 = ((psm[(2*d2+1)*XT_S + cc] - mu)*rstd*lng_s[2*d2+1] + lnb_s[2*d2+1])*osc;
                    dst[d2] = __floats2half2_rn(x0, x1);
                }
            } else {
                // V: multiply by key_mask so attention needs no score masking
                const float kmv = (float)A.s[which].xmask[b*NT + t0 + cc];
                __half* dst = (__half*)Op + (size_t)(b*NE + h*ND)*NT + t0 + cc;
                #pragma unroll 8
                for (int d = 0; d < 64; d++)
                    dst[(size_t)d*NT] =
                        __float2half_rn(((psm[d*XT_S + cc] - mu)*rstd*lng_s[d] + lnb_s[d])*kmv);
            }
        }
    }
}

// ---------------- 3) flash attention: fp16 mma + ldmatrix + rs-by-matmul ----------------
// grid (T/128, H, B), 256 thr = 8 warps; warp w owns q-rows [w*16, w*16+16).
// K tile: 64 rows x 72 halves (row=key, col=d). V tile: 72 rows x 72 halves
// (rows 0..63 = d, row 64 = key_mask, rows 65..71 = 0); stride 144B => LDSM conflict-free.
// Q pre-scaled by log2e/181 => p = ex2(sf) directly; V key-masked => no score mask;
// oacc n-tile 8 col 64 accumulates the softmax denominator.
#define KV_S2 36
#define KTILE (64*KV_S2)
#define VTILE (72*KV_S2)

__global__ void __launch_bounds__(256, 2) attn_mma_kernel(
        const __half* __restrict__ qh, const __half* __restrict__ kh, const __half* __restrict__ vh,
        const __half* __restrict__ kmh, const int* __restrict__ qmask,
        __half* __restrict__ aT) {
    __shared__ unsigned kh2[2*KTILE];
    __shared__ unsigned vh2[2*VTILE];

    const int t0 = blockIdx.x * 128;
    const int h = blockIdx.y, b = blockIdx.z;
    const int tid = threadIdx.x;
    const int lane = tid & 31;
    const int w = tid >> 5;
    const int g = lane >> 2;
    const int t4 = lane & 3;
    const int w16 = w * 16;
    const int base  = (b*NE + h*ND)*NT;
    const int baseq = ((b*NH + h)*NT);

    // zero V rows 65..71 (both stages) — never touched by cp.async afterwards
    for (int i = tid; i < 2*7*KV_S2; i += 256) {
        int s = i / (7*KV_S2), r = i - s*(7*KV_S2);
        vh2[s*VTILE + 65*KV_S2 + r] = 0;
    }

    // Q fragments straight from gmem (transposed [t][64], pre-scaled)
    const __half* q0 = qh + (size_t)(baseq + t0 + w16 + g)*64;
    const __half* q1 = q0 + 8*64;
    unsigned qa[4][4];
    #pragma unroll
    for (int kc = 0; kc < 4; kc++) {
        qa[kc][0] = *(const unsigned*)(q0 + 16*kc + 2*t4);
        qa[kc][1] = *(const unsigned*)(q1 + 16*kc + 2*t4);
        qa[kc][2] = *(const unsigned*)(q0 + 16*kc + 2*t4 + 8);
        qa[kc][3] = *(const unsigned*)(q1 + 16*kc + 2*t4 + 8);
    }

    auto prefetch = [&](int kt, int s) {
        const int tk0 = kt*64;
        #pragma unroll
        for (int l = 0; l < 2; l++) {
            int idx = tid + 256*l;
            int row = idx >> 3, c16 = idx & 7;
            cp16((char*)(kh2 + s*KTILE + row*KV_S2) + c16*16,
                 kh + (size_t)(baseq + tk0 + row)*64 + c16*8);
            cp16((char*)(vh2 + s*VTILE + row*KV_S2) + c16*16,
                 vh + (size_t)(base + row*NT) + tk0 + c16*8);
        }
        if (tid < 8)
            cp16((char*)(vh2 + s*VTILE + 64*KV_S2) + tid*16, kmh + b*NT + tk0 + tid*8);
    };

    prefetch(0, 0);
    cp_commit();

    const unsigned ks_sh = (unsigned)__cvta_generic_to_shared(kh2);
    const unsigned vs_sh = (unsigned)__cvta_generic_to_shared(vh2);
    const int mm = lane >> 3, rr = lane & 7;
    const unsigned rowoff  = (unsigned)((((mm>>1)*8 + rr)*144) + (mm&1)*16);
    const unsigned rowoff2 = (unsigned)(((64 + rr)*144) + (mm&1)*16);

    float oacc[9][4];
    #pragma unroll
    for (int n = 0; n < 9; n++)
        #pragma unroll
        for (int j = 0; j < 4; j++) oacc[n][j] = 0.f;

    for (int kt = 0; kt < NT/64; kt++) {
        const int cur = kt & 1;
        cp_wait0();
        __syncthreads();
        if (kt + 1 < NT/64) { prefetch(kt+1, cur^1); cp_commit(); }

        const unsigned ksb = ks_sh + cur*KTILE*4 + rowoff;
        const unsigned vsb = vs_sh + cur*VTILE*4;

        // ---- S = Q K^T (scaled) ----
        float sf[8][4];
        #pragma unroll
        for (int n = 0; n < 8; n++)
            #pragma unroll
            for (int j = 0; j < 4; j++) sf[n][j] = 0.f;
        #pragma unroll
        for (int kc = 0; kc < 4; kc++) {
            #pragma unroll
            for (int j = 0; j < 4; j++) {
                unsigned b0a, b1a, b0b, b1b;
                ldsm4(b0a, b1a, b0b, b1b, ksb + j*2304 + kc*32);
                mma_f16(sf[2*j  ], qa[kc][0], qa[kc][1], qa[kc][2], qa[kc][3], b0a, b1a);
                mma_f16(sf[2*j+1], qa[kc][0], qa[kc][1], qa[kc][2], qa[kc][3], b0b, b1b);
            }
        }

        // ---- p = ex2(sf) (unmasked; V carries the mask), pack to A fragments ----
        unsigned plo[8], phi[8];
        #pragma unroll
        for (int n = 0; n < 8; n++) {
            plo[n] = packh2(ex2a(sf[n][0]), ex2a(sf[n][1]));
            phi[n] = packh2(ex2a(sf[n][2]), ex2a(sf[n][3]));
        }

        // ---- O += P V^T (+ mask-row tile accumulates denominator) ----
        #pragma unroll
        for (int kc = 0; kc < 4; kc++) {
            unsigned a0 = plo[2*kc], a1 = phi[2*kc], a2 = plo[2*kc+1], a3 = phi[2*kc+1];
            #pragma unroll
            for (int j = 0; j < 4; j++) {
                unsigned b0a, b1a, b0b, b1b;
                ldsm4(b0a, b1a, b0b, b1b, vsb + rowoff + j*2304 + kc*32);
                mma_f16(oacc[2*j  ], a0, a1, a2, a3, b0a, b1a);
                mma_f16(oacc[2*j+1], a0, a1, a2, a3, b0b, b1b);
            }
            unsigned m0, m1;
            ldsm2(m0, m1, vsb + rowoff2 + kc*32);
            mma_f16(oacc[8], a0, a1, a2, a3, m0, m1);
        }
    }

    // ---- denominator from mask-tile col 64 (t4==0 slot), broadcast in quad ----
    const float rs0 = __shfl_sync(0xffffffffu, oacc[8][0], lane & ~3);
    const float rs1 = __shfl_sync(0xffffffffu, oacc[8][2], lane & ~3);

    const int qrow0 = t0 + w16 + g;
    const int qrow1 = qrow0 + 8;
    const float sel0 = (qmask[b*NT + qrow0] != 0) ? (1.0f / rs0) : 0.f;
    const float sel1 = (qmask[b*NT + qrow1] != 0) ? (1.0f / rs1) : 0.f;
    __half* o0 = aT + (size_t)(b*NT + qrow0)*NE + h*ND;
    __half* o1 = aT + (size_t)(b*NT + qrow1)*NE + h*ND;
    #pragma unroll
    for (int n = 0; n < 8; n++) {
        const int d0 = n*8 + 2*t4;
        *(unsigned*)(o0 + d0) = packh2(oacc[n][0]*sel0, oacc[n][1]*sel0);
        *(unsigned*)(o1 + d0) = packh2(oacc[n][2]*sel1, oacc[n][3]*sel1);
    }
}

// ---------------- launch ----------------
extern "C" void kernel_launch(void* const* d_in, const int* in_sizes, int n_in,
                              void* d_out, int out_size) {
    (void)in_sizes; (void)n_in; (void)out_size;
    const float* q   = (const float*)d_in[0];
    const float* k   = (const float*)d_in[1];
    const float* v   = (const float*)d_in[2];
    const int*   qm  = (const int*)d_in[3];
    const int*   km  = (const int*)d_in[4];
    const int*   vm  = (const int*)d_in[5];
    const float* Wq  = (const float*)d_in[6];
    const float* bq  = (const float*)d_in[7];
    const float* Wk  = (const float*)d_in[8];
    const float* bk  = (const float*)d_in[9];
    const float* Wv  = (const float*)d_in[10];
    const float* bv  = (const float*)d_in[11];
    const float* Wo  = (const float*)d_in[12];
    const float* bo  = (const float*)d_in[13];
    const float* gq  = (const float*)d_in[14];
    const float* bgq = (const float*)d_in[15];
    const float* gk  = (const float*)d_in[16];
    const float* bgk = (const float*)d_in[17];
    const float* gv  = (const float*)d_in[18];
    const float* bgv = (const float*)d_in[19];

    __half *wh, *xT, *qh, *kh, *vh, *kmh, *aT;
    cudaGetSymbolAddress((void**)&wh, g_Wh);
    cudaGetSymbolAddress((void**)&xT, g_xT);
    cudaGetSymbolAddress((void**)&qh, g_qh);
    cudaGetSymbolAddress((void**)&kh, g_kh);
    cudaGetSymbolAddress((void**)&vh, g_vh);
    cudaGetSymbolAddress((void**)&kmh, g_kmh);
    cudaGetSymbolAddress((void**)&aT, g_aT);

    cudaFuncSetAttribute((const void*)proj_h_kernel<true>,
                         cudaFuncAttributeMaxDynamicSharedMemorySize, PROJ_SMEM);
    cudaFuncSetAttribute((const void*)proj_h_kernel<false>,
                         cudaFuncAttributeMaxDynamicSharedMemorySize, PROJ_SMEM);

    std_weights_kernel<<<dim3(NE, 4), 128>>>(Wq, Wk, Wv, Wo);
    transpose_mask_kernel<<<dim3(NT/32, NE/32, 6), dim3(32, 8)>>>(q, k, v, qm, km, vm);
    mask_half_kernel<<<NB*NT/256, 256>>>(km);

    const size_t XSL = (size_t)NB*NT*NE;
    ProjArgs A;
    A.s[0] = { xT + 0*XSL, wh + 0*NE*NE, bq, gq, bgq, (void*)qh, 1, EXP_C, nullptr };
    A.s[1] = { xT + 1*XSL, wh + 1*NE*NE, bk, gk, bgk, (void*)kh, 1, 1.0f, nullptr };
    A.s[2] = { xT + 2*XSL, wh + 2*NE*NE, bv, gv, bgv, (void*)vh, 2, 1.0f, km };
    proj_h_kernel<true><<<dim3(NT/128, NH, 6), 256, PROJ_SMEM>>>(A);

    attn_mma_kernel<<<dim3(NT/128, NH, NB), 256>>>(qh, kh, vh, kmh, qm, aT);

    ProjArgs Ao;
    Ao.s[0] = { aT, wh + 3*NE*NE, bo, nullptr, nullptr, d_out, 0, 1.0f, nullptr };
    Ao.s[1] = Ao.s[0];
    Ao.s[2] = Ao.s[0];
    proj_h_kernel<false><<<dim3(NT/128, NH, 2), 256, PROJ_SMEM>>>(Ao);
}

// round 10
// speedup vs baseline: 6.3884x; 1.1235x over previous
#include <cuda_runtime.h>
#include <cuda_fp16.h>
#include <math.h>

#define NB 2
#define NE 512
#define NH 8
#define ND 64
#define NT 2048
#define EPSV 1e-5f
// exp(s/181) = ex2(s * log2(e)/181); folded into Q at projection time
#define EXP_C (1.44269504088896341f/181.0f)

// ---------------- scratch (device globals: allocation-free) ----------------
__device__ __half g_Wh[4*NE*NE];        // standardized weights, half, [mat][m][e]
__device__ __half g_xT[3*NB*NT*NE];     // masked transposed inputs [which][b][t][e]
__device__ __half g_qh[NB*NH*NT*ND];    // Q transposed (pre-scaled by EXP_C): [b][h][t][d]
__device__ __half g_kh[NB*NH*NT*ND];    // K transposed: [b][h][t][d]
__device__ __half g_vh[NB*NE*NT];       // V (key-masked): [b][e][t]
__device__ __half g_kmh[NB*NT];         // key_mask as half
__device__ __half g_aT[NB*NT*NE];       // attention out transposed [b][t][e]

__device__ __forceinline__ float ex2a(float x) {
    float y;
    asm("ex2.approx.f32 %0, %1;" : "=f"(y) : "f"(x));
    return y;
}
// pack two fp32 -> half2 (lo = first arg)
__device__ __forceinline__ unsigned packh2(float lo, float hi) {
    unsigned r;
    asm("cvt.rn.f16x2.f32 %0, %1, %2;" : "=r"(r) : "f"(hi), "f"(lo));
    return r;
}
__device__ __forceinline__ void mma_f16(float* d,
        unsigned a0, unsigned a1, unsigned a2, unsigned a3,
        unsigned b0, unsigned b1) {
    asm volatile("mma.sync.aligned.m16n8k16.row.col.f32.f16.f16.f32 "
        "{%0,%1,%2,%3}, {%4,%5,%6,%7}, {%8,%9}, {%0,%1,%2,%3};\n"
        : "+f"(d[0]), "+f"(d[1]), "+f"(d[2]), "+f"(d[3])
        : "r"(a0), "r"(a1), "r"(a2), "r"(a3), "r"(b0), "r"(b1));
}
__device__ __forceinline__ void ldsm4(unsigned& r0, unsigned& r1, unsigned& r2, unsigned& r3,
                                      unsigned a) {
    asm volatile("ldmatrix.sync.aligned.m8n8.x4.shared.b16 {%0,%1,%2,%3}, [%4];"
        : "=r"(r0), "=r"(r1), "=r"(r2), "=r"(r3) : "r"(a));
}
__device__ __forceinline__ void ldsm2(unsigned& r0, unsigned& r1, unsigned a) {
    asm volatile("ldmatrix.sync.aligned.m8n8.x2.shared.b16 {%0,%1}, [%2];"
        : "=r"(r0), "=r"(r1) : "r"(a));
}
__device__ __forceinline__ void cp16(void* dst, const void* src) {
    unsigned d = (unsigned)__cvta_generic_to_shared(dst);
    asm volatile("cp.async.ca.shared.global [%0], [%1], 16;" :: "r"(d), "l"(src));
}
__device__ __forceinline__ void cp_commit() { asm volatile("cp.async.commit_group;"); }
__device__ __forceinline__ void cp_wait0()  { asm volatile("cp.async.wait_group 0;"); }

// ---------------- 1) weight standardization (writes half) ----------------
__global__ void std_weights_kernel(const float* __restrict__ W0, const float* __restrict__ W1,
                                   const float* __restrict__ W2, const float* __restrict__ W3) {
    const float* Ws[4] = {W0, W1, W2, W3};
    const float* W = Ws[blockIdx.y];
    __half* out = g_Wh + blockIdx.y * NE * NE;
    const int row = blockIdx.x;
    const int tid = threadIdx.x;

    float w[4];
    #pragma unroll
    for (int j = 0; j < 4; j++) w[j] = W[row*NE + tid + 128*j];

    __shared__ float red[4];
    float s = w[0]+w[1]+w[2]+w[3];
    #pragma unroll
    for (int o = 16; o > 0; o >>= 1) s += __shfl_down_sync(0xffffffffu, s, o);
    if ((tid & 31) == 0) red[tid >> 5] = s;
    __syncthreads();
    const float mu = (red[0]+red[1]+red[2]+red[3]) * (1.0f/NE);
    __syncthreads();

    float s2 = 0.f;
    #pragma unroll
    for (int j = 0; j < 4; j++) { float d = w[j]-mu; s2 += d*d; }
    #pragma unroll
    for (int o = 16; o > 0; o >>= 1) s2 += __shfl_down_sync(0xffffffffu, s2, o);
    if ((tid & 31) == 0) red[tid >> 5] = s2;
    __syncthreads();
    const float var = (red[0]+red[1]+red[2]+red[3]) * (1.0f/NE);
    const float rstd = rsqrtf(var + EPSV);
    #pragma unroll
    for (int j = 0; j < 4; j++)
        out[row*NE + tid + 128*j] = __float2half_rn((w[j]-mu)*rstd);
}

// ---------------- 1b) masked transpose + mask-to-half ----------------
__global__ void transpose_mask_kernel(const float* __restrict__ x0, const float* __restrict__ x1,
                                      const float* __restrict__ x2,
                                      const int* __restrict__ m0, const int* __restrict__ m1,
                                      const int* __restrict__ m2) {
    const int which = blockIdx.z >> 1;
    const int b = blockIdx.z & 1;
    const float* X = (which == 0) ? x0 : (which == 1) ? x1 : x2;
    const int*   M = (which == 0) ? m0 : (which == 1) ? m1 : m2;
    __half* O = g_xT + ((size_t)which*NB + b)*NT*NE;

    __shared__ float tile[32][33];
    const int t0 = blockIdx.x*32, e0 = blockIdx.y*32;
    const int tx = threadIdx.x, ty = threadIdx.y;
    #pragma unroll
    for (int i = 0; i < 4; i++)
        tile[ty+8*i][tx] = X[(size_t)(b*NE + e0 + ty + 8*i)*NT + t0 + tx];
    __syncthreads();
    #pragma unroll
    for (int i = 0; i < 4; i++) {
        const int t = t0 + ty + 8*i;
        const float mk = (float)M[b*NT + t];
        O[(size_t)t*NE + e0 + tx] = __float2half_rn(tile[tx][ty+8*i]*mk);
    }
}

__global__ void mask_half_kernel(const int* __restrict__ km) {
    const int i = blockIdx.x*256 + threadIdx.x;
    g_kmh[i] = __float2half_rn((float)km[i]);
}

// ---------------- 2/4) projection GEMM: fp16 mma + ldmatrix + cp.async 2-stage ----------------
// mode 1: LN*oscale + transposed half out [b][h][t][64]  (Q: oscale=EXP_C; K: 1)
// mode 2: LN * key_mask + half out [b][e][t]             (V)
// mode 0: fp32 out [b][e][t] + bias                      (final output)
struct ProjSet {
    const __half* bT; const __half* wh; const float* bias;
    const float* lng; const float* lnb; void* out; int mode;
    float oscale; const int* xmask;
};
struct ProjArgs { ProjSet s[3]; };

#define WT_U 20
#define WCHU (64*WT_U)
#define XCHU (128*WT_U)
#define XT_S 136
#define PROJ_SMEM (64*XT_S*4)

template<bool DO_LN>
__global__ void __launch_bounds__(256) proj_h_kernel(ProjArgs A) {
    const int which = blockIdx.z >> 1;
    const int b = blockIdx.z & 1;
    const __half* __restrict__ Bt = A.s[which].bT + (size_t)b*NT*NE;
    const __half* __restrict__ Wh = A.s[which].wh;
    const float*  __restrict__ Bp = A.s[which].bias;
    const float*  __restrict__ Gp = A.s[which].lng;
    const float*  __restrict__ Lp = A.s[which].lnb;
    void*         __restrict__ Op = A.s[which].out;

    const int h  = blockIdx.y;
    const int t0 = blockIdx.x * 128;
    const int tid = threadIdx.x;
    const int lane = tid & 31;
    const int wid = tid >> 5;
    const int wm = wid & 1, wn = wid >> 1;
    const int g = lane >> 2, t4 = lane & 3;

    extern __shared__ float psm[];
    unsigned* wtb = (unsigned*)psm;
    unsigned* xtb = wtb + 2*WCHU;
    __shared__ float lng_s[ND];
    __shared__ float lnb_s[ND];
    __shared__ float red_s[256];

    if (DO_LN && tid < 64) {
        lng_s[tid] = Gp[tid];
        lnb_s[tid] = Lp[tid];
    }

    const __half* Wr = Wh + (size_t)(h*ND)*NE;

    auto prefetch = [&](int c, int s) {
        const int k0 = c*32;
        {
            int r = tid >> 2, c16 = tid & 3;
            cp16((char*)(wtb + s*WCHU + r*WT_U) + c16*16, Wr + (size_t)r*NE + k0 + c16*8);
        }
        #pragma unroll
        for (int l = 0; l < 2; l++) {
            int idx = tid + 256*l; int r = idx >> 2, c16 = idx & 3;
            cp16((char*)(xtb + s*XCHU + r*WT_U) + c16*16, Bt + (size_t)(t0 + r)*NE + k0 + c16*8);
        }
    };

    prefetch(0, 0);
    cp_commit();

    // ldmatrix lane->address maps (80B row stride: conflict-free)
    const unsigned w_sh = (unsigned)__cvta_generic_to_shared(wtb);
    const unsigned x_sh = (unsigned)__cvta_generic_to_shared(xtb);
    const unsigned aoff = (unsigned)(((((lane>>3)&1)*8) + (lane&7))*80 + ((lane>>4)&1)*16);
    const unsigned boff = (unsigned)(((((lane>>4)&1)*8) + (lane&7))*80 + ((lane>>3)&1)*16);

    float acc[2][4][4];
    #pragma unroll
    for (int mt = 0; mt < 2; mt++)
        #pragma unroll
        for (int n = 0; n < 4; n++)
            #pragma unroll
            for (int j = 0; j < 4; j++) acc[mt][n][j] = 0.f;

    for (int c = 0; c < 16; c++) {
        const int cur = c & 1;
        cp_wait0();
        __syncthreads();
        if (c + 1 < 16) { prefetch(c+1, cur^1); cp_commit(); }

        const unsigned wb = w_sh + cur*(WCHU*4);
        const unsigned xb = x_sh + cur*(XCHU*4);
        #pragma unroll
        for (int sub = 0; sub < 2; sub++) {
            unsigned a[2][4];
            #pragma unroll
            for (int mt = 0; mt < 2; mt++)
                ldsm4(a[mt][0], a[mt][1], a[mt][2], a[mt][3],
                      wb + (wm*32 + mt*16)*80 + sub*32 + aoff);
            #pragma unroll
            for (int ng = 0; ng < 2; ng++) {
                unsigned b0a, b1a, b0b, b1b;
                ldsm4(b0a, b1a, b0b, b1b, xb + (wn*32 + ng*16)*80 + sub*32 + boff);
                #pragma unroll
                for (int mt = 0; mt < 2; mt++) {
                    mma_f16(acc[mt][ng*2  ], a[mt][0], a[mt][1], a[mt][2], a[mt][3], b0a, b1a);
                    mma_f16(acc[mt][ng*2+1], a[mt][0], a[mt][1], a[mt][2], a[mt][3], b0b, b1b);
                }
            }
        }
    }

    float bv[2][2];
    #pragma unroll
    for (int mt = 0; mt < 2; mt++) {
        bv[mt][0] = Bp[h*ND + wm*32 + mt*16 + g];
        bv[mt][1] = Bp[h*ND + wm*32 + mt*16 + g + 8];
    }

    if (!DO_LN) {
        float* o = (float*)Op + (size_t)(b*NE + h*ND)*NT + t0;
        #pragma unroll
        for (int mt = 0; mt < 2; mt++) {
            const int r0 = wm*32 + mt*16 + g;
            #pragma unroll
            for (int n = 0; n < 4; n++) {
                const int cc = wn*32 + n*8 + 2*t4;
                *(float2*)(o + (size_t)(r0  )*NT + cc) =
                    make_float2(acc[mt][n][0] + bv[mt][0], acc[mt][n][1] + bv[mt][0]);
                *(float2*)(o + (size_t)(r0+8)*NT + cc) =
                    make_float2(acc[mt][n][2] + bv[mt][1], acc[mt][n][3] + bv[mt][1]);
            }
        }
    } else {
        __syncthreads();   // done with pipeline buffers; reuse psm as [64][136] fp32 tile
        #pragma unroll
        for (int mt = 0; mt < 2; mt++) {
            const int r0 = wm*32 + mt*16 + g;
            #pragma unroll
            for (int n = 0; n < 4; n++) {
                const int cc = wn*32 + n*8 + 2*t4;
                *(float2*)(psm + (r0  )*XT_S + cc) =
                    make_float2(acc[mt][n][0] + bv[mt][0], acc[mt][n][1] + bv[mt][0]);
                *(float2*)(psm + (r0+8)*XT_S + cc) =
                    make_float2(acc[mt][n][2] + bv[mt][1], acc[mt][n][3] + bv[mt][1]);
            }
        }
        __syncthreads();
        // parallel LN: 256 threads, thread owns 32 rows of column cc
        const int cc = tid & 127, hf = tid >> 7;
        const int d0 = hf*32;
        float s = 0.f;
        #pragma unroll 8
        for (int d = 0; d < 32; d++) s += psm[(d0+d)*XT_S + cc];
        red_s[tid] = s;
        __syncthreads();
        const float mu = (red_s[cc] + red_s[128+cc]) * (1.0f/64.0f);
        __syncthreads();
        float s2 = 0.f;
        #pragma unroll 8
        for (int d = 0; d < 32; d++) { float dd = psm[(d0+d)*XT_S + cc] - mu; s2 += dd*dd; }
        red_s[tid] = s2;
        __syncthreads();
        const float rstd = rsqrtf((red_s[cc] + red_s[128+cc])*(1.0f/64.0f) + EPSV);
        const int mode = A.s[which].mode;
        if (mode == 1) {
            const float osc = A.s[which].oscale;
            __half2* dst = (__half2*)((__half*)Op + ((size_t)((b*NH + h)*NT) + t0 + cc)*64);
            #pragma unroll 8
            for (int d2 = hf*16; d2 < hf*16 + 16; d2++) {
                float x0 = ((psm[(2*d2  )*XT_S + cc] - mu)*rstd*lng_s[2*d2  ] + lnb_s[2*d2  ])*osc;
                float x1 = ((psm[(2*d2+1)*XT_S + cc] - mu)*rstd*lng_s[2*d2+1] + lnb_s[2*d2+1])*osc;
                dst[d2] = __floats2half2_rn(x0, x1);
            }
        } else {
            // V: multiply by key_mask so attention needs no score masking
            const float kmv = (float)A.s[which].xmask[b*NT + t0 + cc];
            __half* dst = (__half*)Op + (size_t)(b*NE + h*ND)*NT + t0 + cc;
            #pragma unroll 8
            for (int d = d0; d < d0 + 32; d++)
                dst[(size_t)d*NT] =
                    __float2half_rn(((psm[d*XT_S + cc] - mu)*rstd*lng_s[d] + lnb_s[d])*kmv);
        }
    }
}

// ---------------- 3) flash attention: fp16 mma + ldmatrix + rs-by-matmul ----------------
// grid (T/128, H, B), 256 thr = 8 warps; warp w owns q-rows [w*16, w*16+16).
// K tile: 64 rows x 72 halves (row=key, col=d). V tile: 72 rows x 72 halves
// (rows 0..63 = d, row 64 = key_mask, rows 65..71 = 0); stride 144B => LDSM conflict-free.
// Q pre-scaled by log2e/181 => p = ex2(sf) directly; V key-masked => no score mask;
// oacc n-tile 8 col 64 accumulates the softmax denominator.
#define KV_S2 36
#define KTILE (64*KV_S2)
#define VTILE (72*KV_S2)

__global__ void __launch_bounds__(256, 2) attn_mma_kernel(
        const __half* __restrict__ qh, const __half* __restrict__ kh, const __half* __restrict__ vh,
        const __half* __restrict__ kmh, const int* __restrict__ qmask,
        __half* __restrict__ aT) {
    __shared__ unsigned kh2[2*KTILE];
    __shared__ unsigned vh2[2*VTILE];

    const int t0 = blockIdx.x * 128;
    const int h = blockIdx.y, b = blockIdx.z;
    const int tid = threadIdx.x;
    const int lane = tid & 31;
    const int w = tid >> 5;
    const int g = lane >> 2;
    const int t4 = lane & 3;
    const int w16 = w * 16;
    const int base  = (b*NE + h*ND)*NT;
    const int baseq = ((b*NH + h)*NT);

    // zero V rows 65..71 (both stages) — never touched by cp.async afterwards
    for (int i = tid; i < 2*7*KV_S2; i += 256) {
        int s = i / (7*KV_S2), r = i - s*(7*KV_S2);
        vh2[s*VTILE + 65*KV_S2 + r] = 0;
    }

    // Q fragments straight from gmem (transposed [t][64], pre-scaled)
    const __half* q0 = qh + (size_t)(baseq + t0 + w16 + g)*64;
    const __half* q1 = q0 + 8*64;
    unsigned qa[4][4];
    #pragma unroll
    for (int kc = 0; kc < 4; kc++) {
        qa[kc][0] = *(const unsigned*)(q0 + 16*kc + 2*t4);
        qa[kc][1] = *(const unsigned*)(q1 + 16*kc + 2*t4);
        qa[kc][2] = *(const unsigned*)(q0 + 16*kc + 2*t4 + 8);
        qa[kc][3] = *(const unsigned*)(q1 + 16*kc + 2*t4 + 8);
    }

    auto prefetch = [&](int kt, int s) {
        const int tk0 = kt*64;
        #pragma unroll
        for (int l = 0; l < 2; l++) {
            int idx = tid + 256*l;
            int row = idx >> 3, c16 = idx & 7;
            cp16((char*)(kh2 + s*KTILE + row*KV_S2) + c16*16,
                 kh + (size_t)(baseq + tk0 + row)*64 + c16*8);
            cp16((char*)(vh2 + s*VTILE + row*KV_S2) + c16*16,
                 vh + (size_t)(base + row*NT) + tk0 + c16*8);
        }
        if (tid < 8)
            cp16((char*)(vh2 + s*VTILE + 64*KV_S2) + tid*16, kmh + b*NT + tk0 + tid*8);
    };

    prefetch(0, 0);
    cp_commit();

    const unsigned ks_sh = (unsigned)__cvta_generic_to_shared(kh2);
    const unsigned vs_sh = (unsigned)__cvta_generic_to_shared(vh2);
    const int mm = lane >> 3, rr = lane & 7;
    const unsigned rowoff  = (unsigned)((((mm>>1)*8 + rr)*144) + (mm&1)*16);
    const unsigned rowoff2 = (unsigned)(((64 + rr)*144) + (mm&1)*16);

    float oacc[9][4];
    #pragma unroll
    for (int n = 0; n < 9; n++)
        #pragma unroll
        for (int j = 0; j < 4; j++) oacc[n][j] = 0.f;

    for (int kt = 0; kt < NT/64; kt++) {
        const int cur = kt & 1;
        cp_wait0();
        __syncthreads();
        if (kt + 1 < NT/64) { prefetch(kt+1, cur^1); cp_commit(); }

        const unsigned ksb = ks_sh + cur*KTILE*4 + rowoff;
        const unsigned vsb = vs_sh + cur*VTILE*4;

        // ---- S = Q K^T (scaled) ----
        float sf[8][4];
        #pragma unroll
        for (int n = 0; n < 8; n++)
            #pragma unroll
            for (int j = 0; j < 4; j++) sf[n][j] = 0.f;
        #pragma unroll
        for (int kc = 0; kc < 4; kc++) {
            #pragma unroll
            for (int j = 0; j < 4; j++) {
                unsigned b0a, b1a, b0b, b1b;
                ldsm4(b0a, b1a, b0b, b1b, ksb + j*2304 + kc*32);
                mma_f16(sf[2*j  ], qa[kc][0], qa[kc][1], qa[kc][2], qa[kc][3], b0a, b1a);
                mma_f16(sf[2*j+1], qa[kc][0], qa[kc][1], qa[kc][2], qa[kc][3], b0b, b1b);
            }
        }

        // ---- p = ex2(sf) (unmasked; V carries the mask), pack to A fragments ----
        unsigned plo[8], phi[8];
        #pragma unroll
        for (int n = 0; n < 8; n++) {
            plo[n] = packh2(ex2a(sf[n][0]), ex2a(sf[n][1]));
            phi[n] = packh2(ex2a(sf[n][2]), ex2a(sf[n][3]));
        }

        // ---- O += P V^T (+ mask-row tile accumulates denominator) ----
        #pragma unroll
        for (int kc = 0; kc < 4; kc++) {
            unsigned a0 = plo[2*kc], a1 = phi[2*kc], a2 = plo[2*kc+1], a3 = phi[2*kc+1];
            #pragma unroll
            for (int j = 0; j < 4; j++) {
                unsigned b0a, b1a, b0b, b1b;
                ldsm4(b0a, b1a, b0b, b1b, vsb + rowoff + j*2304 + kc*32);
                mma_f16(oacc[2*j  ], a0, a1, a2, a3, b0a, b1a);
                mma_f16(oacc[2*j+1], a0, a1, a2, a3, b0b, b1b);
            }
            unsigned m0, m1;
            ldsm2(m0, m1, vsb + rowoff2 + kc*32);
            mma_f16(oacc[8], a0, a1, a2, a3, m0, m1);
        }
    }

    // ---- denominator from mask-tile col 64 (t4==0 slot), broadcast in quad ----
    const float rs0 = __shfl_sync(0xffffffffu, oacc[8][0], lane & ~3);
    const float rs1 = __shfl_sync(0xffffffffu, oacc[8][2], lane & ~3);

    const int qrow0 = t0 + w16 + g;
    const int qrow1 = qrow0 + 8;
    const float sel0 = (qmask[b*NT + qrow0] != 0) ? (1.0f / rs0) : 0.f;
    const float sel1 = (qmask[b*NT + qrow1] != 0) ? (1.0f / rs1) : 0.f;
    __half* o0 = aT + (size_t)(b*NT + qrow0)*NE + h*ND;
    __half* o1 = aT + (size_t)(b*NT + qrow1)*NE + h*ND;
    #pragma unroll
    for (int n = 0; n < 8; n++) {
        const int d0 = n*8 + 2*t4;
        *(unsigned*)(o0 + d0) = packh2(oacc[n][0]*sel0, oacc[n][1]*sel0);
        *(unsigned*)(o1 + d0) = packh2(oacc[n][2]*sel1, oacc[n][3]*sel1);
    }
}

// ---------------- launch ----------------
extern "C" void kernel_launch(void* const* d_in, const int* in_sizes, int n_in,
                              void* d_out, int out_size) {
    (void)in_sizes; (void)n_in; (void)out_size;
    const float* q   = (const float*)d_in[0];
    const float* k   = (const float*)d_in[1];
    const float* v   = (const float*)d_in[2];
    const int*   qm  = (const int*)d_in[3];
    const int*   km  = (const int*)d_in[4];
    const int*   vm  = (const int*)d_in[5];
    const float* Wq  = (const float*)d_in[6];
    const float* bq  = (const float*)d_in[7];
    const float* Wk  = (const float*)d_in[8];
    const float* bk  = (const float*)d_in[9];
    const float* Wv  = (const float*)d_in[10];
    const float* bv  = (const float*)d_in[11];
    const float* Wo  = (const float*)d_in[12];
    const float* bo  = (const float*)d_in[13];
    const float* gq  = (const float*)d_in[14];
    const float* bgq = (const float*)d_in[15];
    const float* gk  = (const float*)d_in[16];
    const float* bgk = (const float*)d_in[17];
    const float* gv  = (const float*)d_in[18];
    const float* bgv = (const float*)d_in[19];

    __half *wh, *xT, *qh, *kh, *vh, *kmh, *aT;
    cudaGetSymbolAddress((void**)&wh, g_Wh);
    cudaGetSymbolAddress((void**)&xT, g_xT);
    cudaGetSymbolAddress((void**)&qh, g_qh);
    cudaGetSymbolAddress((void**)&kh, g_kh);
    cudaGetSymbolAddress((void**)&vh, g_vh);
    cudaGetSymbolAddress((void**)&kmh, g_kmh);
    cudaGetSymbolAddress((void**)&aT, g_aT);

    cudaFuncSetAttribute((const void*)proj_h_kernel<true>,
                         cudaFuncAttributeMaxDynamicSharedMemorySize, PROJ_SMEM);
    cudaFuncSetAttribute((const void*)proj_h_kernel<false>,
                         cudaFuncAttributeMaxDynamicSharedMemorySize, PROJ_SMEM);

    std_weights_kernel<<<dim3(NE, 4), 128>>>(Wq, Wk, Wv, Wo);
    transpose_mask_kernel<<<dim3(NT/32, NE/32, 6), dim3(32, 8)>>>(q, k, v, qm, km, vm);
    mask_half_kernel<<<NB*NT/256, 256>>>(km);

    const size_t XSL = (size_t)NB*NT*NE;
    ProjArgs A;
    A.s[0] = { xT + 0*XSL, wh + 0*NE*NE, bq, gq, bgq, (void*)qh, 1, EXP_C, nullptr };
    A.s[1] = { xT + 1*XSL, wh + 1*NE*NE, bk, gk, bgk, (void*)kh, 1, 1.0f, nullptr };
    A.s[2] = { xT + 2*XSL, wh + 2*NE*NE, bv, gv, bgv, (void*)vh, 2, 1.0f, km };
    proj_h_kernel<true><<<dim3(NT/128, NH, 6), 256, PROJ_SMEM>>>(A);

    attn_mma_kernel<<<dim3(NT/128, NH, NB), 256>>>(qh, kh, vh, kmh, qm, aT);

    ProjArgs Ao;
    Ao.s[0] = { aT, wh + 3*NE*NE, bo, nullptr, nullptr, d_out, 0, 1.0f, nullptr };
    Ao.s[1] = Ao.s[0];
    Ao.s[2] = Ao.s[0];
    proj_h_kernel<false><<<dim3(NT/128, NH, 2), 256, PROJ_SMEM>>>(Ao);
}

// round 11
// speedup vs baseline: 6.8433x; 1.0712x over previous
#include <cuda_runtime.h>
#include <cuda_fp16.h>
#include <math.h>

#define NB 2
#define NE 512
#define NH 8
#define ND 64
#define NT 2048
#define EPSV 1e-5f
// exp(s/181) = ex2(s * log2(e)/181); folded into Q at projection time
#define EXP_C (1.44269504088896341f/181.0f)

// ---------------- scratch (device globals: allocation-free) ----------------
__device__ __half g_Wh[4*NE*NE];        // standardized weights, half, [mat][m][e]
__device__ __half g_xT[3*NB*NT*NE];     // masked transposed inputs [which][b][t][e]
__device__ __half g_qh[NB*NH*NT*ND];    // Q transposed (pre-scaled by EXP_C): [b][h][t][d]
__device__ __half g_kh[NB*NH*NT*ND];    // K transposed: [b][h][t][d]
__device__ __half g_vh[NB*NE*NT];       // V (key-masked): [b][e][t]
__device__ __half g_kmh[NB*NT];         // key_mask as half
__device__ __half g_aT[NB*NT*NE];       // attention out transposed [b][t][e]

__device__ __forceinline__ float ex2a(float x) {
    float y;
    asm("ex2.approx.f32 %0, %1;" : "=f"(y) : "f"(x));
    return y;
}
// pack two fp32 -> half2 (lo = first arg)
__device__ __forceinline__ unsigned packh2(float lo, float hi) {
    unsigned r;
    asm("cvt.rn.f16x2.f32 %0, %1, %2;" : "=r"(r) : "f"(hi), "f"(lo));
    return r;
}
__device__ __forceinline__ void mma_f16(float* d,
        unsigned a0, unsigned a1, unsigned a2, unsigned a3,
        unsigned b0, unsigned b1) {
    asm volatile("mma.sync.aligned.m16n8k16.row.col.f32.f16.f16.f32 "
        "{%0,%1,%2,%3}, {%4,%5,%6,%7}, {%8,%9}, {%0,%1,%2,%3};\n"
        : "+f"(d[0]), "+f"(d[1]), "+f"(d[2]), "+f"(d[3])
        : "r"(a0), "r"(a1), "r"(a2), "r"(a3), "r"(b0), "r"(b1));
}
__device__ __forceinline__ void ldsm4(unsigned& r0, unsigned& r1, unsigned& r2, unsigned& r3,
                                      unsigned a) {
    asm volatile("ldmatrix.sync.aligned.m8n8.x4.shared.b16 {%0,%1,%2,%3}, [%4];"
        : "=r"(r0), "=r"(r1), "=r"(r2), "=r"(r3) : "r"(a));
}
__device__ __forceinline__ void ldsm2(unsigned& r0, unsigned& r1, unsigned a) {
    asm volatile("ldmatrix.sync.aligned.m8n8.x2.shared.b16 {%0,%1}, [%2];"
        : "=r"(r0), "=r"(r1) : "r"(a));
}
__device__ __forceinline__ void cp16(void* dst, const void* src) {
    unsigned d = (unsigned)__cvta_generic_to_shared(dst);
    asm volatile("cp.async.ca.shared.global [%0], [%1], 16;" :: "r"(d), "l"(src));
}
__device__ __forceinline__ void cp_commit() { asm volatile("cp.async.commit_group;"); }
__device__ __forceinline__ void cp_wait0()  { asm volatile("cp.async.wait_group 0;"); }

// ---------------- 1) weight standardization (writes half) ----------------
__global__ void std_weights_kernel(const float* __restrict__ W0, const float* __restrict__ W1,
                                   const float* __restrict__ W2, const float* __restrict__ W3) {
    const float* Ws[4] = {W0, W1, W2, W3};
    const float* W = Ws[blockIdx.y];
    __half* out = g_Wh + blockIdx.y * NE * NE;
    const int row = blockIdx.x;
    const int tid = threadIdx.x;

    float w[4];
    #pragma unroll
    for (int j = 0; j < 4; j++) w[j] = W[row*NE + tid + 128*j];

    __shared__ float red[4];
    float s = w[0]+w[1]+w[2]+w[3];
    #pragma unroll
    for (int o = 16; o > 0; o >>= 1) s += __shfl_down_sync(0xffffffffu, s, o);
    if ((tid & 31) == 0) red[tid >> 5] = s;
    __syncthreads();
    const float mu = (red[0]+red[1]+red[2]+red[3]) * (1.0f/NE);
    __syncthreads();

    float s2 = 0.f;
    #pragma unroll
    for (int j = 0; j < 4; j++) { float d = w[j]-mu; s2 += d*d; }
    #pragma unroll
    for (int o = 16; o > 0; o >>= 1) s2 += __shfl_down_sync(0xffffffffu, s2, o);
    if ((tid & 31) == 0) red[tid >> 5] = s2;
    __syncthreads();
    const float var = (red[0]+red[1]+red[2]+red[3]) * (1.0f/NE);
    const float rstd = rsqrtf(var + EPSV);
    #pragma unroll
    for (int j = 0; j < 4; j++)
        out[row*NE + tid + 128*j] = __float2half_rn((w[j]-mu)*rstd);
}

// ---------------- 1b) masked transpose + mask-to-half ----------------
__global__ void transpose_mask_kernel(const float* __restrict__ x0, const float* __restrict__ x1,
                                      const float* __restrict__ x2,
                                      const int* __restrict__ m0, const int* __restrict__ m1,
                                      const int* __restrict__ m2) {
    const int which = blockIdx.z >> 1;
    const int b = blockIdx.z & 1;
    const float* X = (which == 0) ? x0 : (which == 1) ? x1 : x2;
    const int*   M = (which == 0) ? m0 : (which == 1) ? m1 : m2;
    __half* O = g_xT + ((size_t)which*NB + b)*NT*NE;

    __shared__ float tile[32][33];
    const int t0 = blockIdx.x*32, e0 = blockIdx.y*32;
    const int tx = threadIdx.x, ty = threadIdx.y;
    #pragma unroll
    for (int i = 0; i < 4; i++)
        tile[ty+8*i][tx] = X[(size_t)(b*NE + e0 + ty + 8*i)*NT + t0 + tx];
    __syncthreads();
    #pragma unroll
    for (int i = 0; i < 4; i++) {
        const int t = t0 + ty + 8*i;
        const float mk = (float)M[b*NT + t];
        O[(size_t)t*NE + e0 + tx] = __float2half_rn(tile[tx][ty+8*i]*mk);
    }
}

__global__ void mask_half_kernel(const int* __restrict__ km) {
    const int i = blockIdx.x*256 + threadIdx.x;
    g_kmh[i] = __float2half_rn((float)km[i]);
}

// ---------------- 2/4) projection GEMM: fp16 mma + ldmatrix, BK=64, 2-stage ----------------
// mode 1: LN*oscale + transposed half out [b][h][t][64]  (Q: oscale=EXP_C; K: 1)
// mode 2: LN * key_mask + half out [b][e][t]             (V)
// mode 0: fp32 out [b][e][t] + bias                      (final output)
struct ProjSet {
    const __half* bT; const __half* wh; const float* bias;
    const float* lng; const float* lnb; void* out; int mode;
    float oscale; const int* xmask;
};
struct ProjArgs { ProjSet s[3]; };

// BK=64 halves: tile rows hold 64 halves (128B) padded to 144B (36 u32) — LDSM conflict-free
#define PR_S 36
#define WST (64*PR_S)            // 2304 u32 per W stage
#define XST (128*PR_S)           // 4608 u32 per x stage
#define XT_S 136
#define PROJ_SMEM ((2*WST + 2*XST)*4)   // 55296 B (also covers LN tile 64*136*4)

template<bool DO_LN>
__global__ void __launch_bounds__(256) proj_h_kernel(ProjArgs A) {
    const int which = blockIdx.z >> 1;
    const int b = blockIdx.z & 1;
    const __half* __restrict__ Bt = A.s[which].bT + (size_t)b*NT*NE;
    const __half* __restrict__ Wh = A.s[which].wh;
    const float*  __restrict__ Bp = A.s[which].bias;
    const float*  __restrict__ Gp = A.s[which].lng;
    const float*  __restrict__ Lp = A.s[which].lnb;
    void*         __restrict__ Op = A.s[which].out;

    const int h  = blockIdx.y;
    const int t0 = blockIdx.x * 128;
    const int tid = threadIdx.x;
    const int lane = tid & 31;
    const int wid = tid >> 5;
    const int wm = wid & 1, wn = wid >> 1;
    const int g = lane >> 2, t4 = lane & 3;

    extern __shared__ float psm[];
    unsigned* wtb = (unsigned*)psm;        // [2][WST]
    unsigned* xtb = wtb + 2*WST;           // [2][XST]
    __shared__ float lng_s[ND];
    __shared__ float lnb_s[ND];
    __shared__ float red_s[256];

    if (DO_LN && tid < 64) {
        lng_s[tid] = Gp[tid];
        lnb_s[tid] = Lp[tid];
    }

    const __half* Wr = Wh + (size_t)(h*ND)*NE;

    auto prefetch = [&](int c, int s) {
        const int k0 = c*64;
        #pragma unroll
        for (int l = 0; l < 2; l++) {   // W: 64 rows x 128B = 512 cp16
            int idx = tid + 256*l; int r = idx >> 3, c16 = idx & 7;
            cp16((char*)(wtb + s*WST + r*PR_S) + c16*16, Wr + (size_t)r*NE + k0 + c16*8);
        }
        #pragma unroll
        for (int l = 0; l < 4; l++) {   // x: 128 rows x 128B = 1024 cp16
            int idx = tid + 256*l; int r = idx >> 3, c16 = idx & 7;
            cp16((char*)(xtb + s*XST + r*PR_S) + c16*16, Bt + (size_t)(t0 + r)*NE + k0 + c16*8);
        }
    };

    prefetch(0, 0);
    cp_commit();

    // ldmatrix lane->address maps (144B row stride: conflict-free)
    const unsigned w_sh = (unsigned)__cvta_generic_to_shared(wtb);
    const unsigned x_sh = (unsigned)__cvta_generic_to_shared(xtb);
    const unsigned aoff = (unsigned)(((((lane>>3)&1)*8) + (lane&7))*144 + ((lane>>4)&1)*16);
    const unsigned boff = (unsigned)(((((lane>>4)&1)*8) + (lane&7))*144 + ((lane>>3)&1)*16);

    float acc[2][4][4];
    #pragma unroll
    for (int mt = 0; mt < 2; mt++)
        #pragma unroll
        for (int n = 0; n < 4; n++)
            #pragma unroll
            for (int j = 0; j < 4; j++) acc[mt][n][j] = 0.f;

    for (int c = 0; c < 8; c++) {
        const int cur = c & 1;
        cp_wait0();
        __syncthreads();
        if (c + 1 < 8) { prefetch(c+1, cur^1); cp_commit(); }

        const unsigned wb = w_sh + cur*(WST*4);
        const unsigned xb = x_sh + cur*(XST*4);
        #pragma unroll
        for (int sub = 0; sub < 4; sub++) {
            unsigned a[2][4];
            #pragma unroll
            for (int mt = 0; mt < 2; mt++)
                ldsm4(a[mt][0], a[mt][1], a[mt][2], a[mt][3],
                      wb + (wm*32 + mt*16)*144 + sub*32 + aoff);
            #pragma unroll
            for (int ng = 0; ng < 2; ng++) {
                unsigned b0a, b1a, b0b, b1b;
                ldsm4(b0a, b1a, b0b, b1b, xb + (wn*32 + ng*16)*144 + sub*32 + boff);
                #pragma unroll
                for (int mt = 0; mt < 2; mt++) {
                    mma_f16(acc[mt][ng*2  ], a[mt][0], a[mt][1], a[mt][2], a[mt][3], b0a, b1a);
                    mma_f16(acc[mt][ng*2+1], a[mt][0], a[mt][1], a[mt][2], a[mt][3], b0b, b1b);
                }
            }
        }
    }

    float bv[2][2];
    #pragma unroll
    for (int mt = 0; mt < 2; mt++) {
        bv[mt][0] = Bp[h*ND + wm*32 + mt*16 + g];
        bv[mt][1] = Bp[h*ND + wm*32 + mt*16 + g + 8];
    }

    if (!DO_LN) {
        float* o = (float*)Op + (size_t)(b*NE + h*ND)*NT + t0;
        #pragma unroll
        for (int mt = 0; mt < 2; mt++) {
            const int r0 = wm*32 + mt*16 + g;
            #pragma unroll
            for (int n = 0; n < 4; n++) {
                const int cc = wn*32 + n*8 + 2*t4;
                *(float2*)(o + (size_t)(r0  )*NT + cc) =
                    make_float2(acc[mt][n][0] + bv[mt][0], acc[mt][n][1] + bv[mt][0]);
                *(float2*)(o + (size_t)(r0+8)*NT + cc) =
                    make_float2(acc[mt][n][2] + bv[mt][1], acc[mt][n][3] + bv[mt][1]);
            }
        }
    } else {
        __syncthreads();   // done with pipeline buffers; reuse psm as [64][136] fp32 tile
        #pragma unroll
        for (int mt = 0; mt < 2; mt++) {
            const int r0 = wm*32 + mt*16 + g;
            #pragma unroll
            for (int n = 0; n < 4; n++) {
                const int cc = wn*32 + n*8 + 2*t4;
                *(float2*)(psm + (r0  )*XT_S + cc) =
                    make_float2(acc[mt][n][0] + bv[mt][0], acc[mt][n][1] + bv[mt][0]);
                *(float2*)(psm + (r0+8)*XT_S + cc) =
                    make_float2(acc[mt][n][2] + bv[mt][1], acc[mt][n][3] + bv[mt][1]);
            }
        }
        __syncthreads();
        // parallel LN: 256 threads, thread owns 32 rows of column cc
        const int cc = tid & 127, hf = tid >> 7;
        const int d0 = hf*32;
        float s = 0.f;
        #pragma unroll 8
        for (int d = 0; d < 32; d++) s += psm[(d0+d)*XT_S + cc];
        red_s[tid] = s;
        __syncthreads();
        const float mu = (red_s[cc] + red_s[128+cc]) * (1.0f/64.0f);
        __syncthreads();
        float s2 = 0.f;
        #pragma unroll 8
        for (int d = 0; d < 32; d++) { float dd = psm[(d0+d)*XT_S + cc] - mu; s2 += dd*dd; }
        red_s[tid] = s2;
        __syncthreads();
        const float rstd = rsqrtf((red_s[cc] + red_s[128+cc])*(1.0f/64.0f) + EPSV);
        const int mode = A.s[which].mode;
        if (mode == 1) {
            const float osc = A.s[which].oscale;
            __half2* dst = (__half2*)((__half*)Op + ((size_t)((b*NH + h)*NT) + t0 + cc)*64);
            #pragma unroll 8
            for (int d2 = hf*16; d2 < hf*16 + 16; d2++) {
                float x0 = ((psm[(2*d2  )*XT_S + cc] - mu)*rstd*lng_s[2*d2  ] + lnb_s[2*d2  ])*osc;
                float x1 = ((psm[(2*d2+1)*XT_S + cc] - mu)*rstd*lng_s[2*d2+1] + lnb_s[2*d2+1])*osc;
                dst[d2] = __floats2half2_rn(x0, x1);
            }
        } else {
            // V: multiply by key_mask so attention needs no score masking
            const float kmv = (float)A.s[which].xmask[b*NT + t0 + cc];
            __half* dst = (__half*)Op + (size_t)(b*NE + h*ND)*NT + t0 + cc;
            #pragma unroll 8
            for (int d = d0; d < d0 + 32; d++)
                dst[(size_t)d*NT] =
                    __float2half_rn(((psm[d*XT_S + cc] - mu)*rstd*lng_s[d] + lnb_s[d])*kmv);
        }
    }
}

// ---------------- 3) flash attention: fp16 mma + ldmatrix + rs-by-matmul ----------------
// grid (T/128, H, B), 256 thr = 8 warps; warp w owns q-rows [w*16, w*16+16).
// K tile: 64 rows x 72 halves (row=key, col=d). V tile: 72 rows x 72 halves
// (rows 0..63 = d, row 64 = key_mask, rows 65..71 = 0); stride 144B => LDSM conflict-free.
// Q pre-scaled by log2e/181 => p = ex2(sf) directly; V key-masked => no score mask;
// oacc n-tile 8 col 64 accumulates the softmax denominator.
#define KV_S2 36
#define KTILE (64*KV_S2)
#define VTILE (72*KV_S2)

__global__ void __launch_bounds__(256, 2) attn_mma_kernel(
        const __half* __restrict__ qh, const __half* __restrict__ kh, const __half* __restrict__ vh,
        const __half* __restrict__ kmh, const int* __restrict__ qmask,
        __half* __restrict__ aT) {
    __shared__ unsigned kh2[2*KTILE];
    __shared__ unsigned vh2[2*VTILE];

    const int t0 = blockIdx.x * 128;
    const int h = blockIdx.y, b = blockIdx.z;
    const int tid = threadIdx.x;
    const int lane = tid & 31;
    const int w = tid >> 5;
    const int g = lane >> 2;
    const int t4 = lane & 3;
    const int w16 = w * 16;
    const int base  = (b*NE + h*ND)*NT;
    const int baseq = ((b*NH + h)*NT);

    // zero V rows 65..71 (both stages) — never touched by cp.async afterwards
    for (int i = tid; i < 2*7*KV_S2; i += 256) {
        int s = i / (7*KV_S2), r = i - s*(7*KV_S2);
        vh2[s*VTILE + 65*KV_S2 + r] = 0;
    }

    // Q fragments straight from gmem (transposed [t][64], pre-scaled)
    const __half* q0 = qh + (size_t)(baseq + t0 + w16 + g)*64;
    const __half* q1 = q0 + 8*64;
    unsigned qa[4][4];
    #pragma unroll
    for (int kc = 0; kc < 4; kc++) {
        qa[kc][0] = *(const unsigned*)(q0 + 16*kc + 2*t4);
        qa[kc][1] = *(const unsigned*)(q1 + 16*kc + 2*t4);
        qa[kc][2] = *(const unsigned*)(q0 + 16*kc + 2*t4 + 8);
        qa[kc][3] = *(const unsigned*)(q1 + 16*kc + 2*t4 + 8);
    }

    auto prefetch = [&](int kt, int s) {
        const int tk0 = kt*64;
        #pragma unroll
        for (int l = 0; l < 2; l++) {
            int idx = tid + 256*l;
            int row = idx >> 3, c16 = idx & 7;
            cp16((char*)(kh2 + s*KTILE + row*KV_S2) + c16*16,
                 kh + (size_t)(baseq + tk0 + row)*64 + c16*8);
            cp16((char*)(vh2 + s*VTILE + row*KV_S2) + c16*16,
                 vh + (size_t)(base + row*NT) + tk0 + c16*8);
        }
        if (tid < 8)
            cp16((char*)(vh2 + s*VTILE + 64*KV_S2) + tid*16, kmh + b*NT + tk0 + tid*8);
    };

    prefetch(0, 0);
    cp_commit();

    const unsigned ks_sh = (unsigned)__cvta_generic_to_shared(kh2);
    const unsigned vs_sh = (unsigned)__cvta_generic_to_shared(vh2);
    const int mm = lane >> 3, rr = lane & 7;
    const unsigned rowoff  = (unsigned)((((mm>>1)*8 + rr)*144) + (mm&1)*16);
    const unsigned rowoff2 = (unsigned)(((64 + rr)*144) + (mm&1)*16);

    float oacc[9][4];
    #pragma unroll
    for (int n = 0; n < 9; n++)
        #pragma unroll
        for (int j = 0; j < 4; j++) oacc[n][j] = 0.f;

    for (int kt = 0; kt < NT/64; kt++) {
        const int cur = kt & 1;
        cp_wait0();
        __syncthreads();
        if (kt + 1 < NT/64) { prefetch(kt+1, cur^1); cp_commit(); }

        const unsigned ksb = ks_sh + cur*KTILE*4 + rowoff;
        const unsigned vsb = vs_sh + cur*VTILE*4;

        // ---- S = Q K^T (scaled) ----
        float sf[8][4];
        #pragma unroll
        for (int n = 0; n < 8; n++)
            #pragma unroll
            for (int j = 0; j < 4; j++) sf[n][j] = 0.f;
        #pragma unroll
        for (int kc = 0; kc < 4; kc++) {
            #pragma unroll
            for (int j = 0; j < 4; j++) {
                unsigned b0a, b1a, b0b, b1b;
                ldsm4(b0a, b1a, b0b, b1b, ksb + j*2304 + kc*32);
                mma_f16(sf[2*j  ], qa[kc][0], qa[kc][1], qa[kc][2], qa[kc][3], b0a, b1a);
                mma_f16(sf[2*j+1], qa[kc][0], qa[kc][1], qa[kc][2], qa[kc][3], b0b, b1b);
            }
        }

        // ---- p = ex2(sf) (unmasked; V carries the mask), pack to A fragments ----
        unsigned plo[8], phi[8];
        #pragma unroll
        for (int n = 0; n < 8; n++) {
            plo[n] = packh2(ex2a(sf[n][0]), ex2a(sf[n][1]));
            phi[n] = packh2(ex2a(sf[n][2]), ex2a(sf[n][3]));
        }

        // ---- O += P V^T (+ mask-row tile accumulates denominator) ----
        #pragma unroll
        for (int kc = 0; kc < 4; kc++) {
            unsigned a0 = plo[2*kc], a1 = phi[2*kc], a2 = plo[2*kc+1], a3 = phi[2*kc+1];
            #pragma unroll
            for (int j = 0; j < 4; j++) {
                unsigned b0a, b1a, b0b, b1b;
                ldsm4(b0a, b1a, b0b, b1b, vsb + rowoff + j*2304 + kc*32);
                mma_f16(oacc[2*j  ], a0, a1, a2, a3, b0a, b1a);
                mma_f16(oacc[2*j+1], a0, a1, a2, a3, b0b, b1b);
            }
            unsigned m0, m1;
            ldsm2(m0, m1, vsb + rowoff2 + kc*32);
            mma_f16(oacc[8], a0, a1, a2, a3, m0, m1);
        }
    }

    // ---- denominator from mask-tile col 64 (t4==0 slot), broadcast in quad ----
    const float rs0 = __shfl_sync(0xffffffffu, oacc[8][0], lane & ~3);
    const float rs1 = __shfl_sync(0xffffffffu, oacc[8][2], lane & ~3);

    const int qrow0 = t0 + w16 + g;
    const int qrow1 = qrow0 + 8;
    const float sel0 = (qmask[b*NT + qrow0] != 0) ? (1.0f / rs0) : 0.f;
    const float sel1 = (qmask[b*NT + qrow1] != 0) ? (1.0f / rs1) : 0.f;
    __half* o0 = aT + (size_t)(b*NT + qrow0)*NE + h*ND;
    __half* o1 = aT + (size_t)(b*NT + qrow1)*NE + h*ND;
    #pragma unroll
    for (int n = 0; n < 8; n++) {
        const int d0 = n*8 + 2*t4;
        *(unsigned*)(o0 + d0) = packh2(oacc[n][0]*sel0, oacc[n][1]*sel0);
        *(unsigned*)(o1 + d0) = packh2(oacc[n][2]*sel1, oacc[n][3]*sel1);
    }
}

// ---------------- launch ----------------
extern "C" void kernel_launch(void* const* d_in, const int* in_sizes, int n_in,
                              void* d_out, int out_size) {
    (void)in_sizes; (void)n_in; (void)out_size;
    const float* q   = (const float*)d_in[0];
    const float* k   = (const float*)d_in[1];
    const float* v   = (const float*)d_in[2];
    const int*   qm  = (const int*)d_in[3];
    const int*   km  = (const int*)d_in[4];
    const int*   vm  = (const int*)d_in[5];
    const float* Wq  = (const float*)d_in[6];
    const float* bq  = (const float*)d_in[7];
    const float* Wk  = (const float*)d_in[8];
    const float* bk  = (const float*)d_in[9];
    const float* Wv  = (const float*)d_in[10];
    const float* bv  = (const float*)d_in[11];
    const float* Wo  = (const float*)d_in[12];
    const float* bo  = (const float*)d_in[13];
    const float* gq  = (const float*)d_in[14];
    const float* bgq = (const float*)d_in[15];
    const float* gk  = (const float*)d_in[16];
    const float* bgk = (const float*)d_in[17];
    const float* gv  = (const float*)d_in[18];
    const float* bgv = (const float*)d_in[19];

    __half *wh, *xT, *qh, *kh, *vh, *kmh, *aT;
    cudaGetSymbolAddress((void**)&wh, g_Wh);
    cudaGetSymbolAddress((void**)&xT, g_xT);
    cudaGetSymbolAddress((void**)&qh, g_qh);
    cudaGetSymbolAddress((void**)&kh, g_kh);
    cudaGetSymbolAddress((void**)&vh, g_vh);
    cudaGetSymbolAddress((void**)&kmh, g_kmh);
    cudaGetSymbolAddress((void**)&aT, g_aT);

    cudaFuncSetAttribute((const void*)proj_h_kernel<true>,
                         cudaFuncAttributeMaxDynamicSharedMemorySize, PROJ_SMEM);
    cudaFuncSetAttribute((const void*)proj_h_kernel<false>,
                         cudaFuncAttributeMaxDynamicSharedMemorySize, PROJ_SMEM);

    std_weights_kernel<<<dim3(NE, 4), 128>>>(Wq, Wk, Wv, Wo);
    transpose_mask_kernel<<<dim3(NT/32, NE/32, 6), dim3(32, 8)>>>(q, k, v, qm, km, vm);
    mask_half_kernel<<<NB*NT/256, 256>>>(km);

    const size_t XSL = (size_t)NB*NT*NE;
    ProjArgs A;
    A.s[0] = { xT + 0*XSL, wh + 0*NE*NE, bq, gq, bgq, (void*)qh, 1, EXP_C, nullptr };
    A.s[1] = { xT + 1*XSL, wh + 1*NE*NE, bk, gk, bgk, (void*)kh, 1, 1.0f, nullptr };
    A.s[2] = { xT + 2*XSL, wh + 2*NE*NE, bv, gv, bgv, (void*)vh, 2, 1.0f, km };
    proj_h_kernel<true><<<dim3(NT/128, NH, 6), 256, PROJ_SMEM>>>(A);

    attn_mma_kernel<<<dim3(NT/128, NH, NB), 256>>>(qh, kh, vh, kmh, qm, aT);

    ProjArgs Ao;
    Ao.s[0] = { aT, wh + 3*NE*NE, bo, nullptr, nullptr, d_out, 0, 1.0f, nullptr };
    Ao.s[1] = Ao.s[0];
    Ao.s[2] = Ao.s[0];
    proj_h_kernel<false><<<dim3(NT/128, NH, 2), 256, PROJ_SMEM>>>(Ao);
}